// round 6
// baseline (speedup 1.0000x reference)
#include <cuda_runtime.h>
#include <math.h>

#define BATCH 2
#define SEQ   2048
#define DIM   1024
#define FFN   4096
#define HEADS 8
#define HD    128
#define HV    128
#define VD    1024
#define NLAYERS 2
#define BL    (BATCH*SEQ)          // 4096
#define EPSV  1e-5f

// ---------------- scratch (static device globals; no allocations) ----------
__device__ float g_X  [BL*DIM];
__device__ float g_Xn [BL*DIM];
__device__ float g_Q  [BL*DIM];
__device__ float g_K  [BL*DIM];
__device__ float g_V  [BL*DIM];
__device__ float g_G  [BL*DIM];
__device__ float g_Y  [BL*DIM];
__device__ float g_Yg [BL*DIM];
__device__ float g_Att[BL*DIM];
__device__ float g_Hf [BL*FFN];
__device__ float g_Wqp[DIM*DIM];
__device__ float g_Wkp[DIM*DIM];
__device__ float g_Wvp[DIM*DIM];

// ---------------- small helpers -------------------------------------------
__device__ __forceinline__ float gelu_f(float x) {
    return 0.5f * x * (1.0f + erff(x * 0.70710678118654752f));
}

// ---------------- copy X -> scratch ---------------------------------------
__global__ void copy_k(const float* __restrict__ src, float* __restrict__ dst, int n4) {
    int i = blockIdx.x * blockDim.x + threadIdx.x;
    if (i < n4) ((float4*)dst)[i] = ((const float4*)src)[i];
}

// ---------------- pack head-major weights to [d, h*e] ----------------------
__global__ void pack_qkv_k(const float* __restrict__ Wq, const float* __restrict__ Wk,
                           const float* __restrict__ Wv,
                           float* __restrict__ Pq, float* __restrict__ Pk, float* __restrict__ Pv) {
    int idx = blockIdx.x * blockDim.x + threadIdx.x;       // over DIM*DIM
    if (idx >= DIM * DIM) return;
    int d = idx >> 10;
    int h = (idx >> 7) & 7;
    int e = idx & 127;
    int src = (h * DIM + d) * HD + e;                      // W[h][d][e]
    Pq[idx] = Wq[src];
    Pk[idx] = Wk[src];
    Pv[idx] = Wv[src];
}

// ---------------- layernorm over 1024 (one block per row) -----------------
__global__ void __launch_bounds__(256) layernorm_k(const float* __restrict__ in,
        float* __restrict__ out, const float* __restrict__ w, const float* __restrict__ bb) {
    int row = blockIdx.x, tid = threadIdx.x;
    const float4 xv = *(const float4*)(in + (size_t)row * DIM + tid * 4);
    float s  = xv.x + xv.y + xv.z + xv.w;
    float ss = xv.x*xv.x + xv.y*xv.y + xv.z*xv.z + xv.w*xv.w;
    #pragma unroll
    for (int o = 16; o; o >>= 1) {
        s  += __shfl_xor_sync(0xffffffffu, s,  o);
        ss += __shfl_xor_sync(0xffffffffu, ss, o);
    }
    __shared__ float sw[8], ssw[8], stat[2];
    int wid = tid >> 5, lane = tid & 31;
    if (!lane) { sw[wid] = s; ssw[wid] = ss; }
    __syncthreads();
    if (tid == 0) {
        float S = 0.f, SS = 0.f;
        #pragma unroll
        for (int i = 0; i < 8; i++) { S += sw[i]; SS += ssw[i]; }
        float mean = S * (1.f / DIM);
        float var  = SS * (1.f / DIM) - mean * mean;
        stat[0] = mean;
        stat[1] = rsqrtf(var + EPSV);
    }
    __syncthreads();
    float mean = stat[0], rstd = stat[1];
    const float4 wv = *(const float4*)(w  + tid * 4);
    const float4 bv = *(const float4*)(bb + tid * 4);
    float4 o;
    o.x = (xv.x - mean) * rstd * wv.x + bv.x;
    o.y = (xv.y - mean) * rstd * wv.y + bv.y;
    o.z = (xv.z - mean) * rstd * wv.z + bv.z;
    o.w = (xv.w - mean) * rstd * wv.w + bv.w;
    *(float4*)(out + (size_t)row * DIM + tid * 4) = o;
}

// ---------------- SGEMM: C[M,N] = A[M,K] @ B[K,N]  (+ epilogue) ------------
// EPI: 0 none | 1 +R | 2 +bias,gelu | 3 +bias,+R
template<int EPI>
__global__ void __launch_bounds__(256) sgemm_k(const float* __restrict__ A,
        const float* __restrict__ Bw, float* __restrict__ C,
        const float* __restrict__ bias, const float* __restrict__ R,
        int M, int N, int K) {
    __shared__ float As[8][128];
    __shared__ float Bs[8][128];
    const int tid = threadIdx.x;
    const int tx = tid & 15, ty = tid >> 4;
    const int row0 = blockIdx.y * 128, col0 = blockIdx.x * 128;
    const int ar = tid >> 1, ac = (tid & 1) * 4;     // A tile load coords
    const int br = tid >> 5, bc = (tid & 31) * 4;    // B tile load coords

    float acc[8][8];
    #pragma unroll
    for (int i = 0; i < 8; i++)
        #pragma unroll
        for (int j = 0; j < 8; j++) acc[i][j] = 0.f;

    for (int k0 = 0; k0 < K; k0 += 8) {
        float4 av = *(const float4*)&A[(size_t)(row0 + ar) * K + k0 + ac];
        float4 bv = *(const float4*)&Bw[(size_t)(k0 + br) * N + col0 + bc];
        As[ac + 0][ar] = av.x;
        As[ac + 1][ar] = av.y;
        As[ac + 2][ar] = av.z;
        As[ac + 3][ar] = av.w;
        *(float4*)&Bs[br][bc] = bv;
        __syncthreads();
        #pragma unroll
        for (int kk = 0; kk < 8; kk++) {
            float4 a0 = *(const float4*)&As[kk][ty * 8];
            float4 a1 = *(const float4*)&As[kk][ty * 8 + 4];
            float4 b0 = *(const float4*)&Bs[kk][tx * 8];
            float4 b1 = *(const float4*)&Bs[kk][tx * 8 + 4];
            float af[8] = {a0.x, a0.y, a0.z, a0.w, a1.x, a1.y, a1.z, a1.w};
            float bf[8] = {b0.x, b0.y, b0.z, b0.w, b1.x, b1.y, b1.z, b1.w};
            #pragma unroll
            for (int i = 0; i < 8; i++)
                #pragma unroll
                for (int j = 0; j < 8; j++)
                    acc[i][j] += af[i] * bf[j];
        }
        __syncthreads();
    }

    const int rbase = row0 + ty * 8, cbase = col0 + tx * 8;
    float bvv[8];
    if (EPI == 2 || EPI == 3) {
        #pragma unroll
        for (int j = 0; j < 8; j++) bvv[j] = bias[cbase + j];
    }
    #pragma unroll
    for (int i = 0; i < 8; i++) {
        size_t roff = (size_t)(rbase + i) * N + cbase;
        float v[8];
        #pragma unroll
        for (int j = 0; j < 8; j++) {
            float x = acc[i][j];
            if (EPI == 2 || EPI == 3) x += bvv[j];
            if (EPI == 2) x = gelu_f(x);
            if (EPI == 1 || EPI == 3) x += R[roff + j];
            v[j] = x;
        }
        *(float4*)&C[roff]     = make_float4(v[0], v[1], v[2], v[3]);
        *(float4*)&C[roff + 4] = make_float4(v[4], v[5], v[6], v[7]);
    }
}

// ---------------- xPos rotary (in-place on Q and K) ------------------------
__global__ void xpos_k(float* __restrict__ Q, float* __restrict__ K) {
    int idx = blockIdx.x * blockDim.x + threadIdx.x;  // over B*L*H*64 pairs
    if (idx >= BATCH * SEQ * HEADS * 64) return;
    int p = idx & 63;
    int h = (idx >> 6) & 7;
    int l = (idx >> 9) & (SEQ - 1);
    int b = idx >> (9 + 11);
    size_t base = ((size_t)(b * SEQ + l)) * DIM + h * HD + 2 * p;
    float pos = (float)l;
    float bs  = (2.f * p + 0.4f * HD) / (1.4f * HD);
    float sc  = powf(bs, pos * (1.f / 512.f));
    float invf = expf(-(float)p * (logf(10000.f) / 64.f));
    float ang = pos * invf;
    float sn, cs;
    sincosf(ang, &sn, &cs);
    float q0 = Q[base], q1 = Q[base + 1];
    Q[base]     = q0 * cs * sc - q1 * sn * sc;
    Q[base + 1] = q1 * cs * sc + q0 * sn * sc;
    float isc = 1.f / sc;
    float k0 = K[base], k1 = K[base + 1];
    K[base]     = k0 * cs * isc - k1 * sn * isc;
    K[base + 1] = k1 * cs * isc + k0 * sn * isc;
}

// ---------------- fused retention attention --------------------------------
// Y[b,h,l,v] = sum_m (Q_l . K_m) * gamma_h^(l-m) [l>=m] * V[m,v]
#define ATTN_SMEM ((3*64*132 + 64*68)*4)

__global__ void __launch_bounds__(256) attn_k(const float* __restrict__ Q,
        const float* __restrict__ K, const float* __restrict__ V, float* __restrict__ Y) {
    extern __shared__ float sm[];
    float* Qs = sm;                 // [64][132]
    float* Ks = sm + 64 * 132;      // [64][132]
    float* Vs = sm + 2 * 64 * 132;  // [64][132]
    float* Ss = sm + 3 * 64 * 132;  // [64][68]
    const int tid = threadIdx.x;
    const int q0  = blockIdx.x * 64;
    const int bh  = blockIdx.y;
    const int b = bh >> 3, h = bh & 7;
    const float gamma = 1.f - expf(-3.4657359028f + (float)h * -0.3960840962f);
    const float lg = logf(gamma);

    for (int i = tid; i < 64 * 32; i += 256) {
        int r = i >> 5, c = (i & 31) << 2;
        *(float4*)&Qs[r * 132 + c] =
            *(const float4*)&Q[((size_t)(b * SEQ + q0 + r)) * DIM + h * HD + c];
    }

    float acc[8][4];
    #pragma unroll
    for (int i = 0; i < 8; i++) { acc[i][0]=acc[i][1]=acc[i][2]=acc[i][3]=0.f; }
    const int yr = (tid >> 5) << 3;
    const int yc = (tid & 31) << 2;
    const int si = (tid >> 4) << 2;
    const int sj = (tid & 15) << 2;

    const int nmt = (q0 >> 6) + 1;
    for (int mt = 0; mt < nmt; mt++) {
        const int m0 = mt << 6;
        __syncthreads();
        for (int i = tid; i < 64 * 32; i += 256) {
            int r = i >> 5, c = (i & 31) << 2;
            size_t src = ((size_t)(b * SEQ + m0 + r)) * DIM + h * HD + c;
            *(float4*)&Ks[r * 132 + c] = *(const float4*)&K[src];
            *(float4*)&Vs[r * 132 + c] = *(const float4*)&V[src];
        }
        __syncthreads();
        float s[4][4];
        #pragma unroll
        for (int i = 0; i < 4; i++)
            #pragma unroll
            for (int j = 0; j < 4; j++) s[i][j] = 0.f;
        #pragma unroll 4
        for (int e = 0; e < 128; e += 4) {
            float4 qv[4], kv[4];
            #pragma unroll
            for (int i = 0; i < 4; i++) qv[i] = *(const float4*)&Qs[(si + i) * 132 + e];
            #pragma unroll
            for (int j = 0; j < 4; j++) kv[j] = *(const float4*)&Ks[(sj + j) * 132 + e];
            #pragma unroll
            for (int i = 0; i < 4; i++)
                #pragma unroll
                for (int j = 0; j < 4; j++)
                    s[i][j] += qv[i].x * kv[j].x + qv[i].y * kv[j].y
                             + qv[i].z * kv[j].z + qv[i].w * kv[j].w;
        }
        #pragma unroll
        for (int i = 0; i < 4; i++)
            #pragma unroll
            for (int j = 0; j < 4; j++) {
                int li = q0 + si + i, mj = m0 + sj + j;
                float d = (li >= mj) ? __expf(lg * (float)(li - mj)) : 0.f;
                Ss[(si + i) * 68 + sj + j] = s[i][j] * d;
            }
        __syncthreads();
        #pragma unroll 4
        for (int j = 0; j < 64; j++) {
            float4 vv = *(const float4*)&Vs[j * 132 + yc];
            #pragma unroll
            for (int i = 0; i < 8; i++) {
                float sv = Ss[(yr + i) * 68 + j];
                acc[i][0] += sv * vv.x;
                acc[i][1] += sv * vv.y;
                acc[i][2] += sv * vv.z;
                acc[i][3] += sv * vv.w;
            }
        }
    }
    #pragma unroll
    for (int i = 0; i < 8; i++) {
        *(float4*)&Y[((size_t)((b * 8 + h) * SEQ) + q0 + yr + i) * HV + yc] =
            make_float4(acc[i][0], acc[i][1], acc[i][2], acc[i][3]);
    }
}

// ---------------- per-head groupnorm + SiLU gate, rearrange to [b,l,h*v] ---
__global__ void __launch_bounds__(256) gn_gate_k(const float* __restrict__ Y,
        const float* __restrict__ G, const float* __restrict__ gnw,
        const float* __restrict__ gnb, float* __restrict__ out) {
    int gwarp = (blockIdx.x * blockDim.x + threadIdx.x) >> 5;   // row over B*H*L
    int lane = threadIdx.x & 31;
    if (gwarp >= BATCH * HEADS * SEQ) return;
    int b = gwarp / (HEADS * SEQ);
    int h = (gwarp / SEQ) & 7;
    int l = gwarp & (SEQ - 1);
    const float* y = Y + (size_t)gwarp * HV;
    float v0 = y[lane], v1 = y[lane + 32], v2 = y[lane + 64], v3 = y[lane + 96];
    float s  = v0 + v1 + v2 + v3;
    float ss = v0*v0 + v1*v1 + v2*v2 + v3*v3;
    #pragma unroll
    for (int o = 16; o; o >>= 1) {
        s  += __shfl_xor_sync(0xffffffffu, s,  o);
        ss += __shfl_xor_sync(0xffffffffu, ss, o);
    }
    float mean = s * (1.f / HV);
    float var  = ss * (1.f / HV) - mean * mean;
    float rstd = rsqrtf(var + EPSV);
    size_t ob = ((size_t)(b * SEQ + l)) * VD + h * HV;
    float vv[4] = {v0, v1, v2, v3};
    #pragma unroll
    for (int i = 0; i < 4; i++) {
        int c = lane + i * 32;
        float g = G[ob + c];
        float gate = g / (1.f + expf(-g));
        out[ob + c] = ((vv[i] - mean) * rstd * gnw[h * HV + c] + gnb[h * HV + c]) * gate;
    }
}

// ---------------- host launcher --------------------------------------------
extern "C" void kernel_launch(void* const* d_in, const int* in_sizes, int n_in,
                              void* d_out, int out_size) {
    const float* X    = (const float*)d_in[0];
    const float* Wq   = (const float*)d_in[1];
    const float* Wk   = (const float*)d_in[2];
    const float* Wv   = (const float*)d_in[3];
    const float* W_G  = (const float*)d_in[4];
    const float* W_O  = (const float*)d_in[5];
    const float* gnw  = (const float*)d_in[6];
    const float* gnb  = (const float*)d_in[7];
    const float* ln1w = (const float*)d_in[8];
    const float* ln1b = (const float*)d_in[9];
    const float* ln2w = (const float*)d_in[10];
    const float* ln2b = (const float*)d_in[11];
    const float* fw1  = (const float*)d_in[12];
    const float* fb1  = (const float*)d_in[13];
    const float* fw2  = (const float*)d_in[14];
    const float* fb2  = (const float*)d_in[15];
    float* out = (float*)d_out;

    void* p;
    cudaGetSymbolAddress(&p, g_X);   float* pX   = (float*)p;
    cudaGetSymbolAddress(&p, g_Xn);  float* pXn  = (float*)p;
    cudaGetSymbolAddress(&p, g_Q);   float* pQ   = (float*)p;
    cudaGetSymbolAddress(&p, g_K);   float* pK   = (float*)p;
    cudaGetSymbolAddress(&p, g_V);   float* pV   = (float*)p;
    cudaGetSymbolAddress(&p, g_G);   float* pG   = (float*)p;
    cudaGetSymbolAddress(&p, g_Y);   float* pY   = (float*)p;
    cudaGetSymbolAddress(&p, g_Yg);  float* pYg  = (float*)p;
    cudaGetSymbolAddress(&p, g_Att); float* pAtt = (float*)p;
    cudaGetSymbolAddress(&p, g_Hf);  float* pH   = (float*)p;
    cudaGetSymbolAddress(&p, g_Wqp); float* pWq  = (float*)p;
    cudaGetSymbolAddress(&p, g_Wkp); float* pWk  = (float*)p;
    cudaGetSymbolAddress(&p, g_Wvp); float* pWv  = (float*)p;

    cudaFuncSetAttribute(attn_k, cudaFuncAttributeMaxDynamicSharedMemorySize, ATTN_SMEM);

    copy_k<<<(BL * DIM / 4 + 255) / 256, 256>>>(X, pX, BL * DIM / 4);

    dim3 g8(DIM / 128, BL / 128);
    dim3 gf1(FFN / 128, BL / 128);

    for (int i = 0; i < NLAYERS; i++) {
        size_t wofs = (size_t)i * HEADS * DIM * HD;
        pack_qkv_k<<<(DIM * DIM + 255) / 256, 256>>>(Wq + wofs, Wk + wofs, Wv + wofs,
                                                     pWq, pWk, pWv);
        layernorm_k<<<BL, 256>>>(pX, pXn, ln1w + i * DIM, ln1b + i * DIM);

        sgemm_k<0><<<g8, 256>>>(pXn, pWq, pQ, nullptr, nullptr, BL, DIM, DIM);
        sgemm_k<0><<<g8, 256>>>(pXn, pWk, pK, nullptr, nullptr, BL, DIM, DIM);
        sgemm_k<0><<<g8, 256>>>(pXn, pWv, pV, nullptr, nullptr, BL, DIM, DIM);
        sgemm_k<0><<<g8, 256>>>(pXn, W_G + (size_t)i * DIM * VD, pG, nullptr, nullptr,
                                BL, DIM, DIM);

        xpos_k<<<(BATCH * SEQ * HEADS * 64 + 255) / 256, 256>>>(pQ, pK);

        attn_k<<<dim3(SEQ / 64, BATCH * HEADS), 256, ATTN_SMEM>>>(pQ, pK, pV, pY);

        gn_gate_k<<<(BATCH * HEADS * SEQ) / 8, 256>>>(pY, pG, gnw + i * VD, gnb + i * VD, pYg);

        sgemm_k<1><<<g8, 256>>>(pYg, W_O + (size_t)i * VD * DIM, pAtt, nullptr, pX,
                                BL, DIM, DIM);

        layernorm_k<<<BL, 256>>>(pAtt, pXn, ln2w + i * DIM, ln2b + i * DIM);

        sgemm_k<2><<<gf1, 256>>>(pXn, fw1 + (size_t)i * DIM * FFN, pH,
                                 fb1 + i * FFN, nullptr, BL, FFN, DIM);

        float* dst = (i == NLAYERS - 1) ? out : pX;
        sgemm_k<3><<<g8, 256>>>(pH, fw2 + (size_t)i * FFN * DIM, dst,
                                fb2 + i * DIM, pAtt, BL, DIM, FFN);
    }
}

// round 7
// speedup vs baseline: 2.8330x; 2.8330x over previous
#include <cuda_runtime.h>
#include <math.h>

#define BATCH 2
#define SEQ   2048
#define DIM   1024
#define FFN   4096
#define HEADS 8
#define HD    128
#define HV    128
#define VD    1024
#define NLAYERS 2
#define BL    (BATCH*SEQ)          // 4096
#define EPSV  1e-5f

// ---------------- scratch (static device globals; no allocations) ----------
__device__ float g_X  [BL*DIM];
__device__ float g_Xn [BL*DIM];
__device__ float g_Q  [BL*DIM];
__device__ float g_K  [BL*DIM];
__device__ float g_V  [BL*DIM];
__device__ float g_G  [BL*DIM];
__device__ float g_Y  [BL*DIM];
__device__ float g_Yg [BL*DIM];
__device__ float g_Att[BL*DIM];
__device__ float g_Hf [BL*FFN];
__device__ float g_Wqp[DIM*DIM];
__device__ float g_Wkp[DIM*DIM];
__device__ float g_Wvp[DIM*DIM];

// ---------------- small helpers -------------------------------------------
__device__ __forceinline__ float gelu_f(float x) {
    return 0.5f * x * (1.0f + erff(x * 0.70710678118654752f));
}

__device__ __forceinline__ unsigned f2tf32(float x) {
    unsigned r;
    asm("cvt.rna.tf32.f32 %0, %1;" : "=r"(r) : "f"(x));
    return r;
}

// cvt 8 floats -> tf32 bit patterns and store to smem
__device__ __forceinline__ void stcvt8(float* dst, float4 a, float4 b) {
    dst[0] = __uint_as_float(f2tf32(a.x));
    dst[1] = __uint_as_float(f2tf32(a.y));
    dst[2] = __uint_as_float(f2tf32(a.z));
    dst[3] = __uint_as_float(f2tf32(a.w));
    dst[4] = __uint_as_float(f2tf32(b.x));
    dst[5] = __uint_as_float(f2tf32(b.y));
    dst[6] = __uint_as_float(f2tf32(b.z));
    dst[7] = __uint_as_float(f2tf32(b.w));
}

// ---------------- copy X -> scratch ---------------------------------------
__global__ void copy_k(const float* __restrict__ src, float* __restrict__ dst, int n4) {
    int i = blockIdx.x * blockDim.x + threadIdx.x;
    if (i < n4) ((float4*)dst)[i] = ((const float4*)src)[i];
}

// ---------------- pack head-major weights to [d, h*e] ----------------------
__global__ void pack_qkv_k(const float* __restrict__ Wq, const float* __restrict__ Wk,
                           const float* __restrict__ Wv,
                           float* __restrict__ Pq, float* __restrict__ Pk, float* __restrict__ Pv) {
    int idx = blockIdx.x * blockDim.x + threadIdx.x;       // over DIM*DIM
    if (idx >= DIM * DIM) return;
    int d = idx >> 10;
    int h = (idx >> 7) & 7;
    int e = idx & 127;
    int src = (h * DIM + d) * HD + e;                      // W[h][d][e]
    Pq[idx] = Wq[src];
    Pk[idx] = Wk[src];
    Pv[idx] = Wv[src];
}

// ---------------- layernorm over 1024 (one block per row) -----------------
__global__ void __launch_bounds__(256) layernorm_k(const float* __restrict__ in,
        float* __restrict__ out, const float* __restrict__ w, const float* __restrict__ bb) {
    int row = blockIdx.x, tid = threadIdx.x;
    const float4 xv = *(const float4*)(in + (size_t)row * DIM + tid * 4);
    float s  = xv.x + xv.y + xv.z + xv.w;
    float ss = xv.x*xv.x + xv.y*xv.y + xv.z*xv.z + xv.w*xv.w;
    #pragma unroll
    for (int o = 16; o; o >>= 1) {
        s  += __shfl_xor_sync(0xffffffffu, s,  o);
        ss += __shfl_xor_sync(0xffffffffu, ss, o);
    }
    __shared__ float sw[8], ssw[8], stat[2];
    int wid = tid >> 5, lane = tid & 31;
    if (!lane) { sw[wid] = s; ssw[wid] = ss; }
    __syncthreads();
    if (tid == 0) {
        float S = 0.f, SS = 0.f;
        #pragma unroll
        for (int i = 0; i < 8; i++) { S += sw[i]; SS += ssw[i]; }
        float mean = S * (1.f / DIM);
        float var  = SS * (1.f / DIM) - mean * mean;
        stat[0] = mean;
        stat[1] = rsqrtf(var + EPSV);
    }
    __syncthreads();
    float mean = stat[0], rstd = stat[1];
    const float4 wv = *(const float4*)(w  + tid * 4);
    const float4 bv = *(const float4*)(bb + tid * 4);
    float4 o;
    o.x = (xv.x - mean) * rstd * wv.x + bv.x;
    o.y = (xv.y - mean) * rstd * wv.y + bv.y;
    o.z = (xv.z - mean) * rstd * wv.z + bv.z;
    o.w = (xv.w - mean) * rstd * wv.w + bv.w;
    *(float4*)(out + (size_t)row * DIM + tid * 4) = o;
}

// ---------------- TF32 tensor-core GEMM -----------------------------------
// C[M,N] = A[M,K] @ B[K,N], A/B row-major fp32, tf32 mma, fp32 accumulate.
// EPI: 0 none | 1 +R | 2 +bias,gelu | 3 +bias,+R
// CTA tile 128x128, K-step 16, 8 warps (2x4), warp tile 64x32 (4x4 m16n8k8).
#define LDA 20
#define LDB 136

template<int EPI>
__global__ void __launch_bounds__(256) tgemm_k(const float* __restrict__ A,
        const float* __restrict__ Bw, float* __restrict__ C,
        const float* __restrict__ bias, const float* __restrict__ R,
        int M, int N, int K) {
    __shared__ float As[2][128 * LDA];
    __shared__ float Bs[2][16 * LDB];

    const int tid  = threadIdx.x;
    const int lane = tid & 31;
    const int warp = tid >> 5;
    const int wm = warp >> 2, wn = warp & 3;
    const int row0 = blockIdx.y * 128, col0 = blockIdx.x * 128;

    // load assignments: A 128x16 (each thread one row-half), B 16x128
    const int aRow = tid >> 1,  aCol = (tid & 1) * 8;
    const int bRow = tid >> 4,  bCol = (tid & 15) * 8;

    float acc[4][4][4];
    #pragma unroll
    for (int i = 0; i < 4; i++)
        #pragma unroll
        for (int j = 0; j < 4; j++)
            #pragma unroll
            for (int q = 0; q < 4; q++) acc[i][j][q] = 0.f;

    const float* Aptr = A  + (size_t)(row0 + aRow) * K + aCol;
    const float* Bptr = Bw + (size_t)bRow * N + col0 + bCol;

    // prologue: stage 0 -> buf 0
    {
        float4 pA0 = *(const float4*)(Aptr);
        float4 pA1 = *(const float4*)(Aptr + 4);
        float4 pB0 = *(const float4*)(Bptr);
        float4 pB1 = *(const float4*)(Bptr + 4);
        stcvt8(&As[0][aRow * LDA + aCol], pA0, pA1);
        stcvt8(&Bs[0][bRow * LDB + bCol], pB0, pB1);
    }
    __syncthreads();

    const int nk = K >> 4;
    for (int s = 0; s < nk; s++) {
        const int buf = s & 1;
        float4 pA0, pA1, pB0, pB1;
        const bool more = (s + 1) < nk;
        if (more) {
            const float* ap = Aptr + (s + 1) * 16;
            pA0 = *(const float4*)ap;
            pA1 = *(const float4*)(ap + 4);
            const float* bp = Bptr + (size_t)(s + 1) * 16 * N;
            pB0 = *(const float4*)bp;
            pB1 = *(const float4*)(bp + 4);
        }

        #pragma unroll
        for (int kk = 0; kk < 16; kk += 8) {
            unsigned bf[4][2];
            #pragma unroll
            for (int nj = 0; nj < 4; nj++) {
                int n  = wn * 32 + nj * 8 + (lane >> 2);
                int kb = kk + (lane & 3);
                bf[nj][0] = __float_as_uint(Bs[buf][kb * LDB + n]);
                bf[nj][1] = __float_as_uint(Bs[buf][(kb + 4) * LDB + n]);
            }
            #pragma unroll
            for (int mi = 0; mi < 4; mi++) {
                int r = wm * 64 + mi * 16 + (lane >> 2);
                int c = kk + (lane & 3);
                unsigned a0 = __float_as_uint(As[buf][r * LDA + c]);
                unsigned a1 = __float_as_uint(As[buf][(r + 8) * LDA + c]);
                unsigned a2 = __float_as_uint(As[buf][r * LDA + c + 4]);
                unsigned a3 = __float_as_uint(As[buf][(r + 8) * LDA + c + 4]);
                #pragma unroll
                for (int nj = 0; nj < 4; nj++) {
                    asm volatile(
                        "mma.sync.aligned.m16n8k8.row.col.f32.tf32.tf32.f32 "
                        "{%0,%1,%2,%3}, {%4,%5,%6,%7}, {%8,%9}, {%0,%1,%2,%3};"
                        : "+f"(acc[mi][nj][0]), "+f"(acc[mi][nj][1]),
                          "+f"(acc[mi][nj][2]), "+f"(acc[mi][nj][3])
                        : "r"(a0), "r"(a1), "r"(a2), "r"(a3),
                          "r"(bf[nj][0]), "r"(bf[nj][1]));
                }
            }
        }

        if (more) {
            const int nb = buf ^ 1;
            stcvt8(&As[nb][aRow * LDA + aCol], pA0, pA1);
            stcvt8(&Bs[nb][bRow * LDB + bCol], pB0, pB1);
        }
        __syncthreads();
    }

    // epilogue
    #pragma unroll
    for (int mi = 0; mi < 4; mi++) {
        const int r = row0 + wm * 64 + mi * 16 + (lane >> 2);
        #pragma unroll
        for (int nj = 0; nj < 4; nj++) {
            const int cidx = col0 + wn * 32 + nj * 8 + 2 * (lane & 3);
            float v0 = acc[mi][nj][0], v1 = acc[mi][nj][1];
            float v2 = acc[mi][nj][2], v3 = acc[mi][nj][3];
            if (EPI == 2 || EPI == 3) {
                float b0 = bias[cidx], b1 = bias[cidx + 1];
                v0 += b0; v1 += b1; v2 += b0; v3 += b1;
            }
            if (EPI == 2) {
                v0 = gelu_f(v0); v1 = gelu_f(v1);
                v2 = gelu_f(v2); v3 = gelu_f(v3);
            }
            const size_t o0 = (size_t)r * N + cidx;
            const size_t o1 = (size_t)(r + 8) * N + cidx;
            if (EPI == 1 || EPI == 3) {
                const float2 r0 = *(const float2*)&R[o0];
                const float2 r1 = *(const float2*)&R[o1];
                v0 += r0.x; v1 += r0.y; v2 += r1.x; v3 += r1.y;
            }
            *(float2*)&C[o0] = make_float2(v0, v1);
            *(float2*)&C[o1] = make_float2(v2, v3);
        }
    }
}

// ---------------- xPos rotary (in-place on Q and K) ------------------------
__global__ void xpos_k(float* __restrict__ Q, float* __restrict__ K) {
    int idx = blockIdx.x * blockDim.x + threadIdx.x;  // over B*L*H*64 pairs
    if (idx >= BATCH * SEQ * HEADS * 64) return;
    int p = idx & 63;
    int h = (idx >> 6) & 7;
    int l = (idx >> 9) & (SEQ - 1);
    int b = idx >> (9 + 11);
    size_t base = ((size_t)(b * SEQ + l)) * DIM + h * HD + 2 * p;
    float pos = (float)l;
    float bs  = (2.f * p + 0.4f * HD) / (1.4f * HD);
    float sc  = powf(bs, pos * (1.f / 512.f));
    float invf = expf(-(float)p * (logf(10000.f) / 64.f));
    float ang = pos * invf;
    float sn, cs;
    sincosf(ang, &sn, &cs);
    float q0 = Q[base], q1 = Q[base + 1];
    Q[base]     = q0 * cs * sc - q1 * sn * sc;
    Q[base + 1] = q1 * cs * sc + q0 * sn * sc;
    float isc = 1.f / sc;
    float k0 = K[base], k1 = K[base + 1];
    K[base]     = k0 * cs * isc - k1 * sn * isc;
    K[base + 1] = k1 * cs * isc + k0 * sn * isc;
}

// ---------------- fused retention attention --------------------------------
// Y[b,h,l,v] = sum_m (Q_l . K_m) * gamma_h^(l-m) [l>=m] * V[m,v]
#define ATTN_SMEM ((3*64*132 + 64*68)*4)

__global__ void __launch_bounds__(256) attn_k(const float* __restrict__ Q,
        const float* __restrict__ K, const float* __restrict__ V, float* __restrict__ Y) {
    extern __shared__ float sm[];
    float* Qs = sm;                 // [64][132]
    float* Ks = sm + 64 * 132;      // [64][132]
    float* Vs = sm + 2 * 64 * 132;  // [64][132]
    float* Ss = sm + 3 * 64 * 132;  // [64][68]
    const int tid = threadIdx.x;
    const int q0  = blockIdx.x * 64;
    const int bh  = blockIdx.y;
    const int b = bh >> 3, h = bh & 7;
    const float gamma = 1.f - expf(-3.4657359028f + (float)h * -0.3960840962f);
    const float lg = logf(gamma);

    for (int i = tid; i < 64 * 32; i += 256) {
        int r = i >> 5, c = (i & 31) << 2;
        *(float4*)&Qs[r * 132 + c] =
            *(const float4*)&Q[((size_t)(b * SEQ + q0 + r)) * DIM + h * HD + c];
    }

    float acc[8][4];
    #pragma unroll
    for (int i = 0; i < 8; i++) { acc[i][0]=acc[i][1]=acc[i][2]=acc[i][3]=0.f; }
    const int yr = (tid >> 5) << 3;
    const int yc = (tid & 31) << 2;
    const int si = (tid >> 4) << 2;
    const int sj = (tid & 15) << 2;

    const int nmt = (q0 >> 6) + 1;
    for (int mt = 0; mt < nmt; mt++) {
        const int m0 = mt << 6;
        __syncthreads();
        for (int i = tid; i < 64 * 32; i += 256) {
            int r = i >> 5, c = (i & 31) << 2;
            size_t src = ((size_t)(b * SEQ + m0 + r)) * DIM + h * HD + c;
            *(float4*)&Ks[r * 132 + c] = *(const float4*)&K[src];
            *(float4*)&Vs[r * 132 + c] = *(const float4*)&V[src];
        }
        __syncthreads();
        float s[4][4];
        #pragma unroll
        for (int i = 0; i < 4; i++)
            #pragma unroll
            for (int j = 0; j < 4; j++) s[i][j] = 0.f;
        #pragma unroll 4
        for (int e = 0; e < 128; e += 4) {
            float4 qv[4], kv[4];
            #pragma unroll
            for (int i = 0; i < 4; i++) qv[i] = *(const float4*)&Qs[(si + i) * 132 + e];
            #pragma unroll
            for (int j = 0; j < 4; j++) kv[j] = *(const float4*)&Ks[(sj + j) * 132 + e];
            #pragma unroll
            for (int i = 0; i < 4; i++)
                #pragma unroll
                for (int j = 0; j < 4; j++)
                    s[i][j] += qv[i].x * kv[j].x + qv[i].y * kv[j].y
                             + qv[i].z * kv[j].z + qv[i].w * kv[j].w;
        }
        #pragma unroll
        for (int i = 0; i < 4; i++)
            #pragma unroll
            for (int j = 0; j < 4; j++) {
                int li = q0 + si + i, mj = m0 + sj + j;
                float d = (li >= mj) ? __expf(lg * (float)(li - mj)) : 0.f;
                Ss[(si + i) * 68 + sj + j] = s[i][j] * d;
            }
        __syncthreads();
        #pragma unroll 4
        for (int j = 0; j < 64; j++) {
            float4 vv = *(const float4*)&Vs[j * 132 + yc];
            #pragma unroll
            for (int i = 0; i < 8; i++) {
                float sv = Ss[(yr + i) * 68 + j];
                acc[i][0] += sv * vv.x;
                acc[i][1] += sv * vv.y;
                acc[i][2] += sv * vv.z;
                acc[i][3] += sv * vv.w;
            }
        }
    }
    #pragma unroll
    for (int i = 0; i < 8; i++) {
        *(float4*)&Y[((size_t)((b * 8 + h) * SEQ) + q0 + yr + i) * HV + yc] =
            make_float4(acc[i][0], acc[i][1], acc[i][2], acc[i][3]);
    }
}

// ---------------- per-head groupnorm + SiLU gate, rearrange to [b,l,h*v] ---
__global__ void __launch_bounds__(256) gn_gate_k(const float* __restrict__ Y,
        const float* __restrict__ G, const float* __restrict__ gnw,
        const float* __restrict__ gnb, float* __restrict__ out) {
    int gwarp = (blockIdx.x * blockDim.x + threadIdx.x) >> 5;   // row over B*H*L
    int lane = threadIdx.x & 31;
    if (gwarp >= BATCH * HEADS * SEQ) return;
    int b = gwarp / (HEADS * SEQ);
    int h = (gwarp / SEQ) & 7;
    int l = gwarp & (SEQ - 1);
    const float* y = Y + (size_t)gwarp * HV;
    float v0 = y[lane], v1 = y[lane + 32], v2 = y[lane + 64], v3 = y[lane + 96];
    float s  = v0 + v1 + v2 + v3;
    float ss = v0*v0 + v1*v1 + v2*v2 + v3*v3;
    #pragma unroll
    for (int o = 16; o; o >>= 1) {
        s  += __shfl_xor_sync(0xffffffffu, s,  o);
        ss += __shfl_xor_sync(0xffffffffu, ss, o);
    }
    float mean = s * (1.f / HV);
    float var  = ss * (1.f / HV) - mean * mean;
    float rstd = rsqrtf(var + EPSV);
    size_t ob = ((size_t)(b * SEQ + l)) * VD + h * HV;
    float vv[4] = {v0, v1, v2, v3};
    #pragma unroll
    for (int i = 0; i < 4; i++) {
        int c = lane + i * 32;
        float g = G[ob + c];
        float gate = g / (1.f + expf(-g));
        out[ob + c] = ((vv[i] - mean) * rstd * gnw[h * HV + c] + gnb[h * HV + c]) * gate;
    }
}

// ---------------- host launcher --------------------------------------------
extern "C" void kernel_launch(void* const* d_in, const int* in_sizes, int n_in,
                              void* d_out, int out_size) {
    const float* X    = (const float*)d_in[0];
    const float* Wq   = (const float*)d_in[1];
    const float* Wk   = (const float*)d_in[2];
    const float* Wv   = (const float*)d_in[3];
    const float* W_G  = (const float*)d_in[4];
    const float* W_O  = (const float*)d_in[5];
    const float* gnw  = (const float*)d_in[6];
    const float* gnb  = (const float*)d_in[7];
    const float* ln1w = (const float*)d_in[8];
    const float* ln1b = (const float*)d_in[9];
    const float* ln2w = (const float*)d_in[10];
    const float* ln2b = (const float*)d_in[11];
    const float* fw1  = (const float*)d_in[12];
    const float* fb1  = (const float*)d_in[13];
    const float* fw2  = (const float*)d_in[14];
    const float* fb2  = (const float*)d_in[15];
    float* out = (float*)d_out;

    void* p;
    cudaGetSymbolAddress(&p, g_X);   float* pX   = (float*)p;
    cudaGetSymbolAddress(&p, g_Xn);  float* pXn  = (float*)p;
    cudaGetSymbolAddress(&p, g_Q);   float* pQ   = (float*)p;
    cudaGetSymbolAddress(&p, g_K);   float* pK   = (float*)p;
    cudaGetSymbolAddress(&p, g_V);   float* pV   = (float*)p;
    cudaGetSymbolAddress(&p, g_G);   float* pG   = (float*)p;
    cudaGetSymbolAddress(&p, g_Y);   float* pY   = (float*)p;
    cudaGetSymbolAddress(&p, g_Yg);  float* pYg  = (float*)p;
    cudaGetSymbolAddress(&p, g_Att); float* pAtt = (float*)p;
    cudaGetSymbolAddress(&p, g_Hf);  float* pH   = (float*)p;
    cudaGetSymbolAddress(&p, g_Wqp); float* pWq  = (float*)p;
    cudaGetSymbolAddress(&p, g_Wkp); float* pWk  = (float*)p;
    cudaGetSymbolAddress(&p, g_Wvp); float* pWv  = (float*)p;

    cudaFuncSetAttribute(attn_k, cudaFuncAttributeMaxDynamicSharedMemorySize, ATTN_SMEM);

    copy_k<<<(BL * DIM / 4 + 255) / 256, 256>>>(X, pX, BL * DIM / 4);

    dim3 g8(DIM / 128, BL / 128);
    dim3 gf1(FFN / 128, BL / 128);

    for (int i = 0; i < NLAYERS; i++) {
        size_t wofs = (size_t)i * HEADS * DIM * HD;
        pack_qkv_k<<<(DIM * DIM + 255) / 256, 256>>>(Wq + wofs, Wk + wofs, Wv + wofs,
                                                     pWq, pWk, pWv);
        layernorm_k<<<BL, 256>>>(pX, pXn, ln1w + i * DIM, ln1b + i * DIM);

        tgemm_k<0><<<g8, 256>>>(pXn, pWq, pQ, nullptr, nullptr, BL, DIM, DIM);
        tgemm_k<0><<<g8, 256>>>(pXn, pWk, pK, nullptr, nullptr, BL, DIM, DIM);
        tgemm_k<0><<<g8, 256>>>(pXn, pWv, pV, nullptr, nullptr, BL, DIM, DIM);
        tgemm_k<0><<<g8, 256>>>(pXn, W_G + (size_t)i * DIM * VD, pG, nullptr, nullptr,
                                BL, DIM, DIM);

        xpos_k<<<(BATCH * SEQ * HEADS * 64 + 255) / 256, 256>>>(pQ, pK);

        attn_k<<<dim3(SEQ / 64, BATCH * HEADS), 256, ATTN_SMEM>>>(pQ, pK, pV, pY);

        gn_gate_k<<<(BATCH * HEADS * SEQ) / 8, 256>>>(pY, pG, gnw + i * VD, gnb + i * VD, pYg);

        tgemm_k<1><<<g8, 256>>>(pYg, W_O + (size_t)i * VD * DIM, pAtt, nullptr, pX,
                                BL, DIM, DIM);

        layernorm_k<<<BL, 256>>>(pAtt, pXn, ln2w + i * DIM, ln2b + i * DIM);

        tgemm_k<2><<<gf1, 256>>>(pXn, fw1 + (size_t)i * DIM * FFN, pH,
                                 fb1 + i * FFN, nullptr, BL, FFN, DIM);

        float* dst = (i == NLAYERS - 1) ? out : pX;
        tgemm_k<3><<<g8, 256>>>(pH, fw2 + (size_t)i * FFN * DIM, dst,
                                fb2 + i * DIM, pAtt, BL, DIM, FFN);
    }
}

// round 8
// speedup vs baseline: 4.2222x; 1.4904x over previous
#include <cuda_runtime.h>
#include <math.h>

#define BATCH 2
#define SEQ   2048
#define DIM   1024
#define FFN   4096
#define HEADS 8
#define HD    128
#define HV    128
#define VD    1024
#define NLAYERS 2
#define BL    (BATCH*SEQ)          // 4096
#define EPSV  1e-5f

// ---------------- scratch (static device globals; no allocations) ----------
__device__ float g_X  [BL*DIM];
__device__ float g_Xn [BL*DIM];
__device__ float g_Q  [BL*DIM];
__device__ float g_K  [BL*DIM];
__device__ float g_V  [BL*DIM];
__device__ float g_G  [BL*DIM];
__device__ float g_Y  [BL*DIM];
__device__ float g_Yg [BL*DIM];
__device__ float g_Att[BL*DIM];
__device__ float g_Hf [BL*FFN];
__device__ float g_Wqp[DIM*DIM];
__device__ float g_Wkp[DIM*DIM];
__device__ float g_Wvp[DIM*DIM];

// ---------------- small helpers -------------------------------------------
__device__ __forceinline__ float gelu_f(float x) {
    return 0.5f * x * (1.0f + erff(x * 0.70710678118654752f));
}

__device__ __forceinline__ unsigned f2tf32(float x) {
    unsigned r;
    asm("cvt.rna.tf32.f32 %0, %1;" : "=r"(r) : "f"(x));
    return r;
}

// cvt 8 floats -> tf32 bit patterns and store to smem
__device__ __forceinline__ void stcvt8(float* dst, float4 a, float4 b) {
    dst[0] = __uint_as_float(f2tf32(a.x));
    dst[1] = __uint_as_float(f2tf32(a.y));
    dst[2] = __uint_as_float(f2tf32(a.z));
    dst[3] = __uint_as_float(f2tf32(a.w));
    dst[4] = __uint_as_float(f2tf32(b.x));
    dst[5] = __uint_as_float(f2tf32(b.y));
    dst[6] = __uint_as_float(f2tf32(b.z));
    dst[7] = __uint_as_float(f2tf32(b.w));
}

__device__ __forceinline__ void stcvt4(float* dst, float4 a) {
    dst[0] = __uint_as_float(f2tf32(a.x));
    dst[1] = __uint_as_float(f2tf32(a.y));
    dst[2] = __uint_as_float(f2tf32(a.z));
    dst[3] = __uint_as_float(f2tf32(a.w));
}

__device__ __forceinline__ void mma_tf32(float* c, unsigned a0, unsigned a1,
                                         unsigned a2, unsigned a3,
                                         unsigned b0, unsigned b1) {
    asm volatile(
        "mma.sync.aligned.m16n8k8.row.col.f32.tf32.tf32.f32 "
        "{%0,%1,%2,%3}, {%4,%5,%6,%7}, {%8,%9}, {%0,%1,%2,%3};"
        : "+f"(c[0]), "+f"(c[1]), "+f"(c[2]), "+f"(c[3])
        : "r"(a0), "r"(a1), "r"(a2), "r"(a3), "r"(b0), "r"(b1));
}

// ---------------- copy X -> scratch ---------------------------------------
__global__ void copy_k(const float* __restrict__ src, float* __restrict__ dst, int n4) {
    int i = blockIdx.x * blockDim.x + threadIdx.x;
    if (i < n4) ((float4*)dst)[i] = ((const float4*)src)[i];
}

// ---------------- pack head-major weights to [d, h*e] ----------------------
__global__ void pack_qkv_k(const float* __restrict__ Wq, const float* __restrict__ Wk,
                           const float* __restrict__ Wv,
                           float* __restrict__ Pq, float* __restrict__ Pk, float* __restrict__ Pv) {
    int idx = blockIdx.x * blockDim.x + threadIdx.x;       // over DIM*DIM
    if (idx >= DIM * DIM) return;
    int d = idx >> 10;
    int h = (idx >> 7) & 7;
    int e = idx & 127;
    int src = (h * DIM + d) * HD + e;                      // W[h][d][e]
    Pq[idx] = Wq[src];
    Pk[idx] = Wk[src];
    Pv[idx] = Wv[src];
}

// ---------------- layernorm over 1024 (one block per row) -----------------
__global__ void __launch_bounds__(256) layernorm_k(const float* __restrict__ in,
        float* __restrict__ out, const float* __restrict__ w, const float* __restrict__ bb) {
    int row = blockIdx.x, tid = threadIdx.x;
    const float4 xv = *(const float4*)(in + (size_t)row * DIM + tid * 4);
    float s  = xv.x + xv.y + xv.z + xv.w;
    float ss = xv.x*xv.x + xv.y*xv.y + xv.z*xv.z + xv.w*xv.w;
    #pragma unroll
    for (int o = 16; o; o >>= 1) {
        s  += __shfl_xor_sync(0xffffffffu, s,  o);
        ss += __shfl_xor_sync(0xffffffffu, ss, o);
    }
    __shared__ float sw[8], ssw[8], stat[2];
    int wid = tid >> 5, lane = tid & 31;
    if (!lane) { sw[wid] = s; ssw[wid] = ss; }
    __syncthreads();
    if (tid == 0) {
        float S = 0.f, SS = 0.f;
        #pragma unroll
        for (int i = 0; i < 8; i++) { S += sw[i]; SS += ssw[i]; }
        float mean = S * (1.f / DIM);
        float var  = SS * (1.f / DIM) - mean * mean;
        stat[0] = mean;
        stat[1] = rsqrtf(var + EPSV);
    }
    __syncthreads();
    float mean = stat[0], rstd = stat[1];
    const float4 wv = *(const float4*)(w  + tid * 4);
    const float4 bv = *(const float4*)(bb + tid * 4);
    float4 o;
    o.x = (xv.x - mean) * rstd * wv.x + bv.x;
    o.y = (xv.y - mean) * rstd * wv.y + bv.y;
    o.z = (xv.z - mean) * rstd * wv.z + bv.z;
    o.w = (xv.w - mean) * rstd * wv.w + bv.w;
    *(float4*)(out + (size_t)row * DIM + tid * 4) = o;
}

// ---------------- TF32 tensor-core GEMM -----------------------------------
// C[M,N] = A[M,K] @ B[K,N], A/B row-major fp32, tf32 mma, fp32 accumulate.
// EPI: 0 none | 1 +R | 2 +bias,gelu | 3 +bias,+R
#define LDA 20
#define LDB 136

template<int EPI>
__global__ void __launch_bounds__(256) tgemm_k(const float* __restrict__ A,
        const float* __restrict__ Bw, float* __restrict__ C,
        const float* __restrict__ bias, const float* __restrict__ R,
        int M, int N, int K) {
    __shared__ float As[2][128 * LDA];
    __shared__ float Bs[2][16 * LDB];

    const int tid  = threadIdx.x;
    const int lane = tid & 31;
    const int warp = tid >> 5;
    const int wm = warp >> 2, wn = warp & 3;
    const int row0 = blockIdx.y * 128, col0 = blockIdx.x * 128;

    const int aRow = tid >> 1,  aCol = (tid & 1) * 8;
    const int bRow = tid >> 4,  bCol = (tid & 15) * 8;

    float acc[4][4][4];
    #pragma unroll
    for (int i = 0; i < 4; i++)
        #pragma unroll
        for (int j = 0; j < 4; j++)
            #pragma unroll
            for (int q = 0; q < 4; q++) acc[i][j][q] = 0.f;

    const float* Aptr = A  + (size_t)(row0 + aRow) * K + aCol;
    const float* Bptr = Bw + (size_t)bRow * N + col0 + bCol;

    {
        float4 pA0 = *(const float4*)(Aptr);
        float4 pA1 = *(const float4*)(Aptr + 4);
        float4 pB0 = *(const float4*)(Bptr);
        float4 pB1 = *(const float4*)(Bptr + 4);
        stcvt8(&As[0][aRow * LDA + aCol], pA0, pA1);
        stcvt8(&Bs[0][bRow * LDB + bCol], pB0, pB1);
    }
    __syncthreads();

    const int nk = K >> 4;
    for (int s = 0; s < nk; s++) {
        const int buf = s & 1;
        float4 pA0, pA1, pB0, pB1;
        const bool more = (s + 1) < nk;
        if (more) {
            const float* ap = Aptr + (s + 1) * 16;
            pA0 = *(const float4*)ap;
            pA1 = *(const float4*)(ap + 4);
            const float* bp = Bptr + (size_t)(s + 1) * 16 * N;
            pB0 = *(const float4*)bp;
            pB1 = *(const float4*)(bp + 4);
        }

        #pragma unroll
        for (int kk = 0; kk < 16; kk += 8) {
            unsigned bf[4][2];
            #pragma unroll
            for (int nj = 0; nj < 4; nj++) {
                int n  = wn * 32 + nj * 8 + (lane >> 2);
                int kb = kk + (lane & 3);
                bf[nj][0] = __float_as_uint(Bs[buf][kb * LDB + n]);
                bf[nj][1] = __float_as_uint(Bs[buf][(kb + 4) * LDB + n]);
            }
            #pragma unroll
            for (int mi = 0; mi < 4; mi++) {
                int r = wm * 64 + mi * 16 + (lane >> 2);
                int c = kk + (lane & 3);
                unsigned a0 = __float_as_uint(As[buf][r * LDA + c]);
                unsigned a1 = __float_as_uint(As[buf][(r + 8) * LDA + c]);
                unsigned a2 = __float_as_uint(As[buf][r * LDA + c + 4]);
                unsigned a3 = __float_as_uint(As[buf][(r + 8) * LDA + c + 4]);
                #pragma unroll
                for (int nj = 0; nj < 4; nj++)
                    mma_tf32(acc[mi][nj], a0, a1, a2, a3, bf[nj][0], bf[nj][1]);
            }
        }

        if (more) {
            const int nb = buf ^ 1;
            stcvt8(&As[nb][aRow * LDA + aCol], pA0, pA1);
            stcvt8(&Bs[nb][bRow * LDB + bCol], pB0, pB1);
        }
        __syncthreads();
    }

    #pragma unroll
    for (int mi = 0; mi < 4; mi++) {
        const int r = row0 + wm * 64 + mi * 16 + (lane >> 2);
        #pragma unroll
        for (int nj = 0; nj < 4; nj++) {
            const int cidx = col0 + wn * 32 + nj * 8 + 2 * (lane & 3);
            float v0 = acc[mi][nj][0], v1 = acc[mi][nj][1];
            float v2 = acc[mi][nj][2], v3 = acc[mi][nj][3];
            if (EPI == 2 || EPI == 3) {
                float b0 = bias[cidx], b1 = bias[cidx + 1];
                v0 += b0; v1 += b1; v2 += b0; v3 += b1;
            }
            if (EPI == 2) {
                v0 = gelu_f(v0); v1 = gelu_f(v1);
                v2 = gelu_f(v2); v3 = gelu_f(v3);
            }
            const size_t o0 = (size_t)r * N + cidx;
            const size_t o1 = (size_t)(r + 8) * N + cidx;
            if (EPI == 1 || EPI == 3) {
                const float2 r0 = *(const float2*)&R[o0];
                const float2 r1 = *(const float2*)&R[o1];
                v0 += r0.x; v1 += r0.y; v2 += r1.x; v3 += r1.y;
            }
            *(float2*)&C[o0] = make_float2(v0, v1);
            *(float2*)&C[o1] = make_float2(v2, v3);
        }
    }
}

// ---------------- xPos rotary (in-place on Q and K) ------------------------
__global__ void xpos_k(float* __restrict__ Q, float* __restrict__ K) {
    int idx = blockIdx.x * blockDim.x + threadIdx.x;  // over B*L*H*64 pairs
    if (idx >= BATCH * SEQ * HEADS * 64) return;
    int p = idx & 63;
    int h = (idx >> 6) & 7;
    int l = (idx >> 9) & (SEQ - 1);
    int b = idx >> (9 + 11);
    size_t base = ((size_t)(b * SEQ + l)) * DIM + h * HD + 2 * p;
    float pos = (float)l;
    float bs  = (2.f * p + 0.4f * HD) / (1.4f * HD);
    float sc  = powf(bs, pos * (1.f / 512.f));
    float invf = expf(-(float)p * (logf(10000.f) / 64.f));
    float ang = pos * invf;
    float sn, cs;
    sincosf(ang, &sn, &cs);
    float q0 = Q[base], q1 = Q[base + 1];
    Q[base]     = q0 * cs * sc - q1 * sn * sc;
    Q[base + 1] = q1 * cs * sc + q0 * sn * sc;
    float isc = 1.f / sc;
    float k0 = K[base], k1 = K[base + 1];
    K[base]     = k0 * cs * isc - k1 * sn * isc;
    K[base + 1] = k1 * cs * isc + k0 * sn * isc;
}

// ---------------- fused retention attention (tf32 tensor-core) -------------
// Y[b,h,l,v] = sum_m (Q_l . K_m) * gamma_h^(l-m) [l>=m] * V[m,v]
// 8 warps: wm = warp>>1 (16 q-rows each), wn = warp&1.
// S phase: warp tile 16x32 over S[64][64]; SV phase: warp tile 16x64 over Y[64][128].
#define AT_LDQ 132
#define AT_LDV 68
#define AT_LDS 68
#define ATTN_SMEM ((64*AT_LDQ*2 + 128*AT_LDV + 64*AT_LDS)*4)

__global__ void __launch_bounds__(256) attn_k(const float* __restrict__ Q,
        const float* __restrict__ K, const float* __restrict__ V, float* __restrict__ Y) {
    extern __shared__ float sm[];
    float* Qs = sm;                        // [64][132] tf32
    float* Ks = Qs + 64 * AT_LDQ;          // [64][132] tf32
    float* Vt = Ks + 64 * AT_LDQ;          // [128][68] tf32 (transposed: [v][m])
    float* Ss = Vt + 128 * AT_LDV;         // [64][68]  tf32
    const int tid  = threadIdx.x;
    const int lane = tid & 31;
    const int warp = tid >> 5;
    const int wm = warp >> 1;              // 0..3
    const int wn = warp & 1;               // 0..1
    const int q0 = blockIdx.x * 64;
    const int bh = blockIdx.y;
    const int b = bh >> 3, h = bh & 7;
    const float gamma = 1.f - expf(-3.4657359028f + (float)h * -0.3960840962f);
    const float lg = logf(gamma);

    // load Q tile (cvt to tf32)
    for (int i = tid; i < 64 * 32; i += 256) {
        int r = i >> 5, c = (i & 31) << 2;
        float4 v = *(const float4*)&Q[((size_t)(b * SEQ + q0 + r)) * DIM + h * HD + c];
        stcvt4(&Qs[r * AT_LDQ + c], v);
    }

    float acc2[8][4];
    #pragma unroll
    for (int j = 0; j < 8; j++) { acc2[j][0]=acc2[j][1]=acc2[j][2]=acc2[j][3]=0.f; }

    const int qr = (lane >> 2);
    const int qc = (lane & 3);

    const int nmt = (q0 >> 6) + 1;
    for (int mt = 0; mt < nmt; mt++) {
        const int m0 = mt << 6;
        __syncthreads();   // all readers of Ks/Vt/Ss from previous tile done
        // load K tile (cvt)
        for (int i = tid; i < 64 * 32; i += 256) {
            int r = i >> 5, c = (i & 31) << 2;
            float4 v = *(const float4*)&K[((size_t)(b * SEQ + m0 + r)) * DIM + h * HD + c];
            stcvt4(&Ks[r * AT_LDQ + c], v);
        }
        // load V tile transposed: Vt[v][m] (each warp handles 8 m-rows)
        {
            const int mo = lane & 7;
            const int v0 = (lane >> 3) << 2;       // 0,4,8,12
            const int mrow = warp * 8 + mo;
            const float* vsrc = &V[((size_t)(b * SEQ + m0 + mrow)) * DIM + h * HD];
            #pragma unroll
            for (int vb = 0; vb < 128; vb += 16) {
                float4 vv = *(const float4*)&vsrc[vb + v0];
                Vt[(vb + v0 + 0) * AT_LDV + mrow] = __uint_as_float(f2tf32(vv.x));
                Vt[(vb + v0 + 1) * AT_LDV + mrow] = __uint_as_float(f2tf32(vv.y));
                Vt[(vb + v0 + 2) * AT_LDV + mrow] = __uint_as_float(f2tf32(vv.z));
                Vt[(vb + v0 + 3) * AT_LDV + mrow] = __uint_as_float(f2tf32(vv.w));
            }
        }
        __syncthreads();

        // ---- S = Q K^T : warp tile 16x32, k=128 ----
        float sacc[4][4];
        #pragma unroll
        for (int nj = 0; nj < 4; nj++) { sacc[nj][0]=sacc[nj][1]=sacc[nj][2]=sacc[nj][3]=0.f; }
        #pragma unroll
        for (int k0 = 0; k0 < 128; k0 += 8) {
            const int r = wm * 16 + qr;
            const int c = k0 + qc;
            unsigned a0 = __float_as_uint(Qs[r * AT_LDQ + c]);
            unsigned a1 = __float_as_uint(Qs[(r + 8) * AT_LDQ + c]);
            unsigned a2 = __float_as_uint(Qs[r * AT_LDQ + c + 4]);
            unsigned a3 = __float_as_uint(Qs[(r + 8) * AT_LDQ + c + 4]);
            #pragma unroll
            for (int nj = 0; nj < 4; nj++) {
                const int n = wn * 32 + nj * 8 + qr;
                unsigned b0 = __float_as_uint(Ks[n * AT_LDQ + c]);
                unsigned b1 = __float_as_uint(Ks[n * AT_LDQ + c + 4]);
                mma_tf32(sacc[nj], a0, a1, a2, a3, b0, b1);
            }
        }
        // decay + causal mask on fragments, cvt -> Ss
        {
            const int lr = wm * 16 + qr;
            const int li  = q0 + lr;
            const int li8 = li + 8;
            #pragma unroll
            for (int nj = 0; nj < 4; nj++) {
                const int lc = wn * 32 + nj * 8 + 2 * qc;
                const int mj = m0 + lc;
                float d00 = (li  >= mj    ) ? __expf(lg * (float)(li  - mj    )) : 0.f;
                float d01 = (li  >= mj + 1) ? __expf(lg * (float)(li  - mj - 1)) : 0.f;
                float d10 = (li8 >= mj    ) ? __expf(lg * (float)(li8 - mj    )) : 0.f;
                float d11 = (li8 >= mj + 1) ? __expf(lg * (float)(li8 - mj - 1)) : 0.f;
                Ss[lr * AT_LDS + lc]           = __uint_as_float(f2tf32(sacc[nj][0] * d00));
                Ss[lr * AT_LDS + lc + 1]       = __uint_as_float(f2tf32(sacc[nj][1] * d01));
                Ss[(lr + 8) * AT_LDS + lc]     = __uint_as_float(f2tf32(sacc[nj][2] * d10));
                Ss[(lr + 8) * AT_LDS + lc + 1] = __uint_as_float(f2tf32(sacc[nj][3] * d11));
            }
        }
        __syncthreads();

        // ---- Y += S @ V : warp tile 16x64, k=64 ----
        #pragma unroll
        for (int k0 = 0; k0 < 64; k0 += 8) {
            const int r = wm * 16 + qr;
            const int c = k0 + qc;
            unsigned a0 = __float_as_uint(Ss[r * AT_LDS + c]);
            unsigned a1 = __float_as_uint(Ss[(r + 8) * AT_LDS + c]);
            unsigned a2 = __float_as_uint(Ss[r * AT_LDS + c + 4]);
            unsigned a3 = __float_as_uint(Ss[(r + 8) * AT_LDS + c + 4]);
            #pragma unroll
            for (int nj = 0; nj < 8; nj++) {
                const int n = wn * 64 + nj * 8 + qr;
                unsigned b0 = __float_as_uint(Vt[n * AT_LDV + c]);
                unsigned b1 = __float_as_uint(Vt[n * AT_LDV + c + 4]);
                mma_tf32(acc2[nj], a0, a1, a2, a3, b0, b1);
            }
        }
    }

    // epilogue: Y layout [(b*8+h)*SEQ + l][v]
    {
        const int lr = wm * 16 + qr;
        const size_t rowbase = (size_t)((b * 8 + h) * SEQ) + q0 + lr;
        #pragma unroll
        for (int nj = 0; nj < 8; nj++) {
            const int c = wn * 64 + nj * 8 + 2 * qc;
            *(float2*)&Y[rowbase * HV + c]       = make_float2(acc2[nj][0], acc2[nj][1]);
            *(float2*)&Y[(rowbase + 8) * HV + c] = make_float2(acc2[nj][2], acc2[nj][3]);
        }
    }
}

// ---------------- per-head groupnorm + SiLU gate, rearrange to [b,l,h*v] ---
__global__ void __launch_bounds__(256) gn_gate_k(const float* __restrict__ Y,
        const float* __restrict__ G, const float* __restrict__ gnw,
        const float* __restrict__ gnb, float* __restrict__ out) {
    int gwarp = (blockIdx.x * blockDim.x + threadIdx.x) >> 5;   // row over B*H*L
    int lane = threadIdx.x & 31;
    if (gwarp >= BATCH * HEADS * SEQ) return;
    int b = gwarp / (HEADS * SEQ);
    int h = (gwarp / SEQ) & 7;
    int l = gwarp & (SEQ - 1);
    const float* y = Y + (size_t)gwarp * HV;
    float v0 = y[lane], v1 = y[lane + 32], v2 = y[lane + 64], v3 = y[lane + 96];
    float s  = v0 + v1 + v2 + v3;
    float ss = v0*v0 + v1*v1 + v2*v2 + v3*v3;
    #pragma unroll
    for (int o = 16; o; o >>= 1) {
        s  += __shfl_xor_sync(0xffffffffu, s,  o);
        ss += __shfl_xor_sync(0xffffffffu, ss, o);
    }
    float mean = s * (1.f / HV);
    float var  = ss * (1.f / HV) - mean * mean;
    float rstd = rsqrtf(var + EPSV);
    size_t ob = ((size_t)(b * SEQ + l)) * VD + h * HV;
    float vv[4] = {v0, v1, v2, v3};
    #pragma unroll
    for (int i = 0; i < 4; i++) {
        int c = lane + i * 32;
        float g = G[ob + c];
        float gate = g / (1.f + expf(-g));
        out[ob + c] = ((vv[i] - mean) * rstd * gnw[h * HV + c] + gnb[h * HV + c]) * gate;
    }
}

// ---------------- host launcher --------------------------------------------
extern "C" void kernel_launch(void* const* d_in, const int* in_sizes, int n_in,
                              void* d_out, int out_size) {
    const float* X    = (const float*)d_in[0];
    const float* Wq   = (const float*)d_in[1];
    const float* Wk   = (const float*)d_in[2];
    const float* Wv   = (const float*)d_in[3];
    const float* W_G  = (const float*)d_in[4];
    const float* W_O  = (const float*)d_in[5];
    const float* gnw  = (const float*)d_in[6];
    const float* gnb  = (const float*)d_in[7];
    const float* ln1w = (const float*)d_in[8];
    const float* ln1b = (const float*)d_in[9];
    const float* ln2w = (const float*)d_in[10];
    const float* ln2b = (const float*)d_in[11];
    const float* fw1  = (const float*)d_in[12];
    const float* fb1  = (const float*)d_in[13];
    const float* fw2  = (const float*)d_in[14];
    const float* fb2  = (const float*)d_in[15];
    float* out = (float*)d_out;

    void* p;
    cudaGetSymbolAddress(&p, g_X);   float* pX   = (float*)p;
    cudaGetSymbolAddress(&p, g_Xn);  float* pXn  = (float*)p;
    cudaGetSymbolAddress(&p, g_Q);   float* pQ   = (float*)p;
    cudaGetSymbolAddress(&p, g_K);   float* pK   = (float*)p;
    cudaGetSymbolAddress(&p, g_V);   float* pV   = (float*)p;
    cudaGetSymbolAddress(&p, g_G);   float* pG   = (float*)p;
    cudaGetSymbolAddress(&p, g_Y);   float* pY   = (float*)p;
    cudaGetSymbolAddress(&p, g_Yg);  float* pYg  = (float*)p;
    cudaGetSymbolAddress(&p, g_Att); float* pAtt = (float*)p;
    cudaGetSymbolAddress(&p, g_Hf);  float* pH   = (float*)p;
    cudaGetSymbolAddress(&p, g_Wqp); float* pWq  = (float*)p;
    cudaGetSymbolAddress(&p, g_Wkp); float* pWk  = (float*)p;
    cudaGetSymbolAddress(&p, g_Wvp); float* pWv  = (float*)p;

    cudaFuncSetAttribute(attn_k, cudaFuncAttributeMaxDynamicSharedMemorySize, ATTN_SMEM);

    copy_k<<<(BL * DIM / 4 + 255) / 256, 256>>>(X, pX, BL * DIM / 4);

    dim3 g8(DIM / 128, BL / 128);
    dim3 gf1(FFN / 128, BL / 128);

    for (int i = 0; i < NLAYERS; i++) {
        size_t wofs = (size_t)i * HEADS * DIM * HD;
        pack_qkv_k<<<(DIM * DIM + 255) / 256, 256>>>(Wq + wofs, Wk + wofs, Wv + wofs,
                                                     pWq, pWk, pWv);
        layernorm_k<<<BL, 256>>>(pX, pXn, ln1w + i * DIM, ln1b + i * DIM);

        tgemm_k<0><<<g8, 256>>>(pXn, pWq, pQ, nullptr, nullptr, BL, DIM, DIM);
        tgemm_k<0><<<g8, 256>>>(pXn, pWk, pK, nullptr, nullptr, BL, DIM, DIM);
        tgemm_k<0><<<g8, 256>>>(pXn, pWv, pV, nullptr, nullptr, BL, DIM, DIM);
        tgemm_k<0><<<g8, 256>>>(pXn, W_G + (size_t)i * DIM * VD, pG, nullptr, nullptr,
                                BL, DIM, DIM);

        xpos_k<<<(BATCH * SEQ * HEADS * 64 + 255) / 256, 256>>>(pQ, pK);

        attn_k<<<dim3(SEQ / 64, BATCH * HEADS), 256, ATTN_SMEM>>>(pQ, pK, pV, pY);

        gn_gate_k<<<(BATCH * HEADS * SEQ) / 8, 256>>>(pY, pG, gnw + i * VD, gnb + i * VD, pYg);

        tgemm_k<1><<<g8, 256>>>(pYg, W_O + (size_t)i * VD * DIM, pAtt, nullptr, pX,
                                BL, DIM, DIM);

        layernorm_k<<<BL, 256>>>(pAtt, pXn, ln2w + i * DIM, ln2b + i * DIM);

        tgemm_k<2><<<gf1, 256>>>(pXn, fw1 + (size_t)i * DIM * FFN, pH,
                                 fb1 + i * FFN, nullptr, BL, FFN, DIM);

        float* dst = (i == NLAYERS - 1) ? out : pX;
        tgemm_k<3><<<g8, 256>>>(pH, fw2 + (size_t)i * FFN * DIM, dst,
                                fb2 + i * DIM, pAtt, BL, DIM, FFN);
    }
}

// round 10
// speedup vs baseline: 4.7755x; 1.1310x over previous
#include <cuda_runtime.h>
#include <math.h>

#define BATCH 2
#define SEQ   2048
#define DIM   1024
#define FFN   4096
#define HEADS 8
#define HD    128
#define HV    128
#define VD    1024
#define NLAYERS 2
#define BL    (BATCH*SEQ)          // 4096
#define EPSV  1e-5f
#define PSTR  (4*DIM)              // packed QKVG row stride

// ---------------- scratch (static device globals; no allocations) ----------
__device__ float g_X   [BL*DIM];
__device__ float g_Xn  [BL*DIM];
__device__ float g_Y   [BL*DIM];
__device__ float g_Yg  [BL*DIM];
__device__ float g_Att [BL*DIM];
__device__ float g_Hf  [BL*FFN];
__device__ float g_Wbig[DIM*PSTR];
__device__ float g_QKVG[(size_t)BL*PSTR];

// ---------------- small helpers -------------------------------------------
__device__ __forceinline__ float gelu_f(float x) {
    return 0.5f * x * (1.0f + erff(x * 0.70710678118654752f));
}

__device__ __forceinline__ unsigned f2tf32(float x) {
    unsigned r;
    asm("cvt.rna.tf32.f32 %0, %1;" : "=r"(r) : "f"(x));
    return r;
}

__device__ __forceinline__ void stcvt4(float* dst, float4 a) {
    dst[0] = __uint_as_float(f2tf32(a.x));
    dst[1] = __uint_as_float(f2tf32(a.y));
    dst[2] = __uint_as_float(f2tf32(a.z));
    dst[3] = __uint_as_float(f2tf32(a.w));
}

__device__ __forceinline__ void mma_tf32(float* c, unsigned a0, unsigned a1,
                                         unsigned a2, unsigned a3,
                                         unsigned b0, unsigned b1) {
    asm volatile(
        "mma.sync.aligned.m16n8k8.row.col.f32.tf32.tf32.f32 "
        "{%0,%1,%2,%3}, {%4,%5,%6,%7}, {%8,%9}, {%0,%1,%2,%3};"
        : "+f"(c[0]), "+f"(c[1]), "+f"(c[2]), "+f"(c[3])
        : "r"(a0), "r"(a1), "r"(a2), "r"(a3), "r"(b0), "r"(b1));
}

__device__ __forceinline__ void cpa16(void* smem, const void* g) {
    unsigned s = (unsigned)__cvta_generic_to_shared(smem);
    asm volatile("cp.async.cg.shared.global [%0], [%1], 16;" :: "r"(s), "l"(g));
}
__device__ __forceinline__ void cp_commit() {
    asm volatile("cp.async.commit_group;");
}
template<int N> __device__ __forceinline__ void cp_wait() {
    asm volatile("cp.async.wait_group %0;" :: "n"(N));
}

// ---------------- copy X -> scratch ---------------------------------------
__global__ void copy_k(const float* __restrict__ src, float* __restrict__ dst, int n4) {
    int i = blockIdx.x * blockDim.x + threadIdx.x;
    if (i < n4) ((float4*)dst)[i] = ((const float4*)src)[i];
}

// ---------------- pack Wq|Wk|Wv|WG -> [d][4096] ----------------------------
__global__ void pack_qkvg_k(const float* __restrict__ Wq, const float* __restrict__ Wk,
                            const float* __restrict__ Wv, const float* __restrict__ WG,
                            float* __restrict__ P) {
    int idx = blockIdx.x * blockDim.x + threadIdx.x;       // over DIM*DIM (d, j)
    if (idx >= DIM * DIM) return;
    int d = idx >> 10;
    int j = idx & 1023;
    int h = j >> 7, e = j & 127;
    int src = (h * DIM + d) * HD + e;                      // W[h][d][e]
    float* row = P + (size_t)d * PSTR;
    row[j]          = Wq[src];
    row[1024 + j]   = Wk[src];
    row[2048 + j]   = Wv[src];
    row[3072 + j]   = WG[d * VD + j];
}

// ---------------- layernorm over 1024 (one block per row) -----------------
__global__ void __launch_bounds__(256) layernorm_k(const float* __restrict__ in,
        float* __restrict__ out, const float* __restrict__ w, const float* __restrict__ bb) {
    int row = blockIdx.x, tid = threadIdx.x;
    const float4 xv = *(const float4*)(in + (size_t)row * DIM + tid * 4);
    float s  = xv.x + xv.y + xv.z + xv.w;
    float ss = xv.x*xv.x + xv.y*xv.y + xv.z*xv.z + xv.w*xv.w;
    #pragma unroll
    for (int o = 16; o; o >>= 1) {
        s  += __shfl_xor_sync(0xffffffffu, s,  o);
        ss += __shfl_xor_sync(0xffffffffu, ss, o);
    }
    __shared__ float sw[8], ssw[8], stat[2];
    int wid = tid >> 5, lane = tid & 31;
    if (!lane) { sw[wid] = s; ssw[wid] = ss; }
    __syncthreads();
    if (tid == 0) {
        float S = 0.f, SS = 0.f;
        #pragma unroll
        for (int i = 0; i < 8; i++) { S += sw[i]; SS += ssw[i]; }
        float mean = S * (1.f / DIM);
        float var  = SS * (1.f / DIM) - mean * mean;
        stat[0] = mean;
        stat[1] = rsqrtf(var + EPSV);
    }
    __syncthreads();
    float mean = stat[0], rstd = stat[1];
    const float4 wv = *(const float4*)(w  + tid * 4);
    const float4 bv = *(const float4*)(bb + tid * 4);
    float4 o;
    o.x = (xv.x - mean) * rstd * wv.x + bv.x;
    o.y = (xv.y - mean) * rstd * wv.y + bv.y;
    o.z = (xv.z - mean) * rstd * wv.z + bv.z;
    o.w = (xv.w - mean) * rstd * wv.w + bv.w;
    *(float4*)(out + (size_t)row * DIM + tid * 4) = o;
}

// ---------------- TF32 tensor-core GEMM, cp.async 3-stage ------------------
// C[M,N] = A[M,K] @ B[K,N]; 4 warps, warp tile 64x64, CTA 128x128, k-step 16.
// EPI: 0 none | 1 +R | 2 +bias,gelu | 3 +bias,+R
#define LDA 20
#define LDB 132
#define GSTAGE 3
#define SMEM_GEMM (GSTAGE*(128*LDA + 16*LDB)*4)

template<int EPI>
__global__ void __launch_bounds__(128) tgemm_k(const float* __restrict__ A,
        const float* __restrict__ Bw, float* __restrict__ C,
        const float* __restrict__ bias, const float* __restrict__ R,
        int M, int N, int K) {
    extern __shared__ float smg[];
    float* AsBase = smg;                         // [GSTAGE][128*LDA]
    float* BsBase = smg + GSTAGE * 128 * LDA;    // [GSTAGE][16*LDB]

    const int tid  = threadIdx.x;
    const int lane = tid & 31;
    const int warp = tid >> 5;
    const int wm = warp >> 1, wn = warp & 1;
    const int row0 = blockIdx.y * 128, col0 = blockIdx.x * 128;
    const int qr = lane >> 2, qc = lane & 3;

    const int aRow = tid >> 2,  aCol = (tid & 3) * 4;
    const int bRow = tid >> 5,  bCol = (tid & 31) * 4;

    float acc[4][8][4];
    #pragma unroll
    for (int i = 0; i < 4; i++)
        #pragma unroll
        for (int j = 0; j < 8; j++)
            #pragma unroll
            for (int q = 0; q < 4; q++) acc[i][j][q] = 0.f;

    auto load_stage = [&](int st, int k0) {
        float* as = AsBase + st * 128 * LDA;
        #pragma unroll
        for (int i = 0; i < 4; i++) {
            int r = aRow + 32 * i;
            cpa16(&as[r * LDA + aCol], &A[(size_t)(row0 + r) * K + k0 + aCol]);
        }
        float* bs = BsBase + st * 16 * LDB;
        #pragma unroll
        for (int i = 0; i < 4; i++) {
            int k = bRow + 4 * i;
            cpa16(&bs[k * LDB + bCol], &Bw[(size_t)(k0 + k) * N + col0 + bCol]);
        }
        cp_commit();
    };

    load_stage(0, 0);
    load_stage(1, 16);

    const int nk = K >> 4;
    for (int s = 0; s < nk; s++) {
        // Tail fix: at s == nk-1 no newer group exists, so wait_group 1 would
        // NOT guarantee stage s landed -> must drain fully (wait_group 0).
        if (s + 1 < nk) cp_wait<1>(); else cp_wait<0>();
        __syncthreads();
        const float* as = AsBase + (s % 3) * 128 * LDA;
        const float* bs = BsBase + (s % 3) * 16 * LDB;
        #pragma unroll
        for (int kk = 0; kk < 16; kk += 8) {
            unsigned av[4][4], bv[8][2];
            #pragma unroll
            for (int mi = 0; mi < 4; mi++) {
                int r = wm * 64 + mi * 16 + qr;
                int c = kk + qc;
                av[mi][0] = f2tf32(as[r * LDA + c]);
                av[mi][1] = f2tf32(as[(r + 8) * LDA + c]);
                av[mi][2] = f2tf32(as[r * LDA + c + 4]);
                av[mi][3] = f2tf32(as[(r + 8) * LDA + c + 4]);
            }
            #pragma unroll
            for (int nj = 0; nj < 8; nj++) {
                int n  = wn * 64 + nj * 8 + qr;
                int kb = kk + qc;
                bv[nj][0] = f2tf32(bs[kb * LDB + n]);
                bv[nj][1] = f2tf32(bs[(kb + 4) * LDB + n]);
            }
            #pragma unroll
            for (int mi = 0; mi < 4; mi++)
                #pragma unroll
                for (int nj = 0; nj < 8; nj++)
                    mma_tf32(acc[mi][nj], av[mi][0], av[mi][1], av[mi][2], av[mi][3],
                             bv[nj][0], bv[nj][1]);
        }
        __syncthreads();
        if (s + 2 < nk) load_stage((s + 2) % 3, (s + 2) * 16);
    }

    // epilogue
    #pragma unroll
    for (int mi = 0; mi < 4; mi++) {
        const int r = row0 + wm * 64 + mi * 16 + qr;
        #pragma unroll
        for (int nj = 0; nj < 8; nj++) {
            const int cidx = col0 + wn * 64 + nj * 8 + 2 * qc;
            float v0 = acc[mi][nj][0], v1 = acc[mi][nj][1];
            float v2 = acc[mi][nj][2], v3 = acc[mi][nj][3];
            if (EPI == 2 || EPI == 3) {
                float b0 = bias[cidx], b1 = bias[cidx + 1];
                v0 += b0; v1 += b1; v2 += b0; v3 += b1;
            }
            if (EPI == 2) {
                v0 = gelu_f(v0); v1 = gelu_f(v1);
                v2 = gelu_f(v2); v3 = gelu_f(v3);
            }
            const size_t o0 = (size_t)r * N + cidx;
            const size_t o1 = (size_t)(r + 8) * N + cidx;
            if (EPI == 1 || EPI == 3) {
                const float2 r0 = *(const float2*)&R[o0];
                const float2 r1 = *(const float2*)&R[o1];
                v0 += r0.x; v1 += r0.y; v2 += r1.x; v3 += r1.y;
            }
            *(float2*)&C[o0] = make_float2(v0, v1);
            *(float2*)&C[o1] = make_float2(v2, v3);
        }
    }
}

// ---------------- xPos rotary (in-place on packed QKVG) --------------------
__global__ void xpos_k(float* __restrict__ QKVG) {
    int idx = blockIdx.x * blockDim.x + threadIdx.x;  // over B*L*H*64 pairs
    if (idx >= BATCH * SEQ * HEADS * 64) return;
    int p = idx & 63;
    int h = (idx >> 6) & 7;
    int l = (idx >> 9) & (SEQ - 1);
    int b = idx >> (9 + 11);
    size_t base = ((size_t)(b * SEQ + l)) * PSTR + h * HD + 2 * p;
    float pos = (float)l;
    float bs  = (2.f * p + 0.4f * HD) / (1.4f * HD);
    float sc  = powf(bs, pos * (1.f / 512.f));
    float invf = expf(-(float)p * (logf(10000.f) / 64.f));
    float ang = pos * invf;
    float sn, cs;
    sincosf(ang, &sn, &cs);
    float* Q = QKVG;
    float* K = QKVG + 1024;
    float q0 = Q[base], q1 = Q[base + 1];
    Q[base]     = q0 * cs * sc - q1 * sn * sc;
    Q[base + 1] = q1 * cs * sc + q0 * sn * sc;
    float isc = 1.f / sc;
    float k0 = K[base], k1 = K[base + 1];
    K[base]     = k0 * cs * isc - k1 * sn * isc;
    K[base + 1] = k1 * cs * isc + k0 * sn * isc;
}

// ---------------- fused retention attention (tf32 tensor-core) -------------
// Reads Q/K/V from packed QKVG (row stride PSTR, col offsets 0/1024/2048).
#define AT_LDQ 132
#define AT_LDV 68
#define AT_LDS 68
#define ATTN_SMEM ((64*AT_LDQ*2 + 128*AT_LDV + 64*AT_LDS)*4)

__global__ void __launch_bounds__(256) attn_k(const float* __restrict__ QKVG,
                                              float* __restrict__ Y) {
    extern __shared__ float sm[];
    float* Qs = sm;                        // [64][132] tf32
    float* Ks = Qs + 64 * AT_LDQ;          // [64][132] tf32
    float* Vt = Ks + 64 * AT_LDQ;          // [128][68] tf32 (transposed: [v][m])
    float* Ss = Vt + 128 * AT_LDV;         // [64][68]  tf32
    const int tid  = threadIdx.x;
    const int lane = tid & 31;
    const int warp = tid >> 5;
    const int wm = warp >> 1;              // 0..3
    const int wn = warp & 1;               // 0..1
    const int q0 = blockIdx.x * 64;
    const int bh = blockIdx.y;
    const int b = bh >> 3, h = bh & 7;
    const float gamma = 1.f - expf(-3.4657359028f + (float)h * -0.3960840962f);
    const float lg = logf(gamma);

    const float* Qg = QKVG;
    const float* Kg = QKVG + 1024;
    const float* Vg = QKVG + 2048;

    // load Q tile (cvt to tf32)
    for (int i = tid; i < 64 * 32; i += 256) {
        int r = i >> 5, c = (i & 31) << 2;
        float4 v = *(const float4*)&Qg[((size_t)(b * SEQ + q0 + r)) * PSTR + h * HD + c];
        stcvt4(&Qs[r * AT_LDQ + c], v);
    }

    float acc2[8][4];
    #pragma unroll
    for (int j = 0; j < 8; j++) { acc2[j][0]=acc2[j][1]=acc2[j][2]=acc2[j][3]=0.f; }

    const int qr = (lane >> 2);
    const int qc = (lane & 3);

    const int nmt = (q0 >> 6) + 1;
    for (int mt = 0; mt < nmt; mt++) {
        const int m0 = mt << 6;
        __syncthreads();
        for (int i = tid; i < 64 * 32; i += 256) {
            int r = i >> 5, c = (i & 31) << 2;
            float4 v = *(const float4*)&Kg[((size_t)(b * SEQ + m0 + r)) * PSTR + h * HD + c];
            stcvt4(&Ks[r * AT_LDQ + c], v);
        }
        {
            const int mo = lane & 7;
            const int v0 = (lane >> 3) << 2;
            const int mrow = warp * 8 + mo;
            const float* vsrc = &Vg[((size_t)(b * SEQ + m0 + mrow)) * PSTR + h * HD];
            #pragma unroll
            for (int vb = 0; vb < 128; vb += 16) {
                float4 vv = *(const float4*)&vsrc[vb + v0];
                Vt[(vb + v0 + 0) * AT_LDV + mrow] = __uint_as_float(f2tf32(vv.x));
                Vt[(vb + v0 + 1) * AT_LDV + mrow] = __uint_as_float(f2tf32(vv.y));
                Vt[(vb + v0 + 2) * AT_LDV + mrow] = __uint_as_float(f2tf32(vv.z));
                Vt[(vb + v0 + 3) * AT_LDV + mrow] = __uint_as_float(f2tf32(vv.w));
            }
        }
        __syncthreads();

        // ---- S = Q K^T : warp tile 16x32, k=128 ----
        float sacc[4][4];
        #pragma unroll
        for (int nj = 0; nj < 4; nj++) { sacc[nj][0]=sacc[nj][1]=sacc[nj][2]=sacc[nj][3]=0.f; }
        #pragma unroll
        for (int k0 = 0; k0 < 128; k0 += 8) {
            const int r = wm * 16 + qr;
            const int c = k0 + qc;
            unsigned a0 = __float_as_uint(Qs[r * AT_LDQ + c]);
            unsigned a1 = __float_as_uint(Qs[(r + 8) * AT_LDQ + c]);
            unsigned a2 = __float_as_uint(Qs[r * AT_LDQ + c + 4]);
            unsigned a3 = __float_as_uint(Qs[(r + 8) * AT_LDQ + c + 4]);
            #pragma unroll
            for (int nj = 0; nj < 4; nj++) {
                const int n = wn * 32 + nj * 8 + qr;
                unsigned b0 = __float_as_uint(Ks[n * AT_LDQ + c]);
                unsigned b1 = __float_as_uint(Ks[n * AT_LDQ + c + 4]);
                mma_tf32(sacc[nj], a0, a1, a2, a3, b0, b1);
            }
        }
        {
            const int lr = wm * 16 + qr;
            const int li  = q0 + lr;
            const int li8 = li + 8;
            #pragma unroll
            for (int nj = 0; nj < 4; nj++) {
                const int lc = wn * 32 + nj * 8 + 2 * qc;
                const int mj = m0 + lc;
                float d00 = (li  >= mj    ) ? __expf(lg * (float)(li  - mj    )) : 0.f;
                float d01 = (li  >= mj + 1) ? __expf(lg * (float)(li  - mj - 1)) : 0.f;
                float d10 = (li8 >= mj    ) ? __expf(lg * (float)(li8 - mj    )) : 0.f;
                float d11 = (li8 >= mj + 1) ? __expf(lg * (float)(li8 - mj - 1)) : 0.f;
                Ss[lr * AT_LDS + lc]           = __uint_as_float(f2tf32(sacc[nj][0] * d00));
                Ss[lr * AT_LDS + lc + 1]       = __uint_as_float(f2tf32(sacc[nj][1] * d01));
                Ss[(lr + 8) * AT_LDS + lc]     = __uint_as_float(f2tf32(sacc[nj][2] * d10));
                Ss[(lr + 8) * AT_LDS + lc + 1] = __uint_as_float(f2tf32(sacc[nj][3] * d11));
            }
        }
        __syncthreads();

        // ---- Y += S @ V : warp tile 16x64, k=64 ----
        #pragma unroll
        for (int k0 = 0; k0 < 64; k0 += 8) {
            const int r = wm * 16 + qr;
            const int c = k0 + qc;
            unsigned a0 = __float_as_uint(Ss[r * AT_LDS + c]);
            unsigned a1 = __float_as_uint(Ss[(r + 8) * AT_LDS + c]);
            unsigned a2 = __float_as_uint(Ss[r * AT_LDS + c + 4]);
            unsigned a3 = __float_as_uint(Ss[(r + 8) * AT_LDS + c + 4]);
            #pragma unroll
            for (int nj = 0; nj < 8; nj++) {
                const int n = wn * 64 + nj * 8 + qr;
                unsigned b0 = __float_as_uint(Vt[n * AT_LDV + c]);
                unsigned b1 = __float_as_uint(Vt[n * AT_LDV + c + 4]);
                mma_tf32(acc2[nj], a0, a1, a2, a3, b0, b1);
            }
        }
    }

    {
        const int lr = wm * 16 + qr;
        const size_t rowbase = (size_t)((b * 8 + h) * SEQ) + q0 + lr;
        #pragma unroll
        for (int nj = 0; nj < 8; nj++) {
            const int c = wn * 64 + nj * 8 + 2 * qc;
            *(float2*)&Y[rowbase * HV + c]       = make_float2(acc2[nj][0], acc2[nj][1]);
            *(float2*)&Y[(rowbase + 8) * HV + c] = make_float2(acc2[nj][2], acc2[nj][3]);
        }
    }
}

// ---------------- per-head groupnorm + SiLU gate ---------------------------
__global__ void __launch_bounds__(256) gn_gate_k(const float* __restrict__ Y,
        const float* __restrict__ QKVG, const float* __restrict__ gnw,
        const float* __restrict__ gnb, float* __restrict__ out) {
    int gwarp = (blockIdx.x * blockDim.x + threadIdx.x) >> 5;   // row over B*H*L
    int lane = threadIdx.x & 31;
    if (gwarp >= BATCH * HEADS * SEQ) return;
    int b = gwarp / (HEADS * SEQ);
    int h = (gwarp / SEQ) & 7;
    int l = gwarp & (SEQ - 1);
    const float* y = Y + (size_t)gwarp * HV;
    float v0 = y[lane], v1 = y[lane + 32], v2 = y[lane + 64], v3 = y[lane + 96];
    float s  = v0 + v1 + v2 + v3;
    float ss = v0*v0 + v1*v1 + v2*v2 + v3*v3;
    #pragma unroll
    for (int o = 16; o; o >>= 1) {
        s  += __shfl_xor_sync(0xffffffffu, s,  o);
        ss += __shfl_xor_sync(0xffffffffu, ss, o);
    }
    float mean = s * (1.f / HV);
    float var  = ss * (1.f / HV) - mean * mean;
    float rstd = rsqrtf(var + EPSV);
    size_t row = (size_t)(b * SEQ + l);
    const float* Gp = QKVG + row * PSTR + 3072 + h * HV;
    size_t ob = row * VD + h * HV;
    float vv[4] = {v0, v1, v2, v3};
    #pragma unroll
    for (int i = 0; i < 4; i++) {
        int c = lane + i * 32;
        float g = Gp[c];
        float gate = g / (1.f + expf(-g));
        out[ob + c] = ((vv[i] - mean) * rstd * gnw[h * HV + c] + gnb[h * HV + c]) * gate;
    }
}

// ---------------- host launcher --------------------------------------------
extern "C" void kernel_launch(void* const* d_in, const int* in_sizes, int n_in,
                              void* d_out, int out_size) {
    const float* X    = (const float*)d_in[0];
    const float* Wq   = (const float*)d_in[1];
    const float* Wk   = (const float*)d_in[2];
    const float* Wv   = (const float*)d_in[3];
    const float* W_G  = (const float*)d_in[4];
    const float* W_O  = (const float*)d_in[5];
    const float* gnw  = (const float*)d_in[6];
    const float* gnb  = (const float*)d_in[7];
    const float* ln1w = (const float*)d_in[8];
    const float* ln1b = (const float*)d_in[9];
    const float* ln2w = (const float*)d_in[10];
    const float* ln2b = (const float*)d_in[11];
    const float* fw1  = (const float*)d_in[12];
    const float* fb1  = (const float*)d_in[13];
    const float* fw2  = (const float*)d_in[14];
    const float* fb2  = (const float*)d_in[15];
    float* out = (float*)d_out;

    void* p;
    cudaGetSymbolAddress(&p, g_X);    float* pX    = (float*)p;
    cudaGetSymbolAddress(&p, g_Xn);   float* pXn   = (float*)p;
    cudaGetSymbolAddress(&p, g_Y);    float* pY    = (float*)p;
    cudaGetSymbolAddress(&p, g_Yg);   float* pYg   = (float*)p;
    cudaGetSymbolAddress(&p, g_Att);  float* pAtt  = (float*)p;
    cudaGetSymbolAddress(&p, g_Hf);   float* pH    = (float*)p;
    cudaGetSymbolAddress(&p, g_Wbig); float* pWbig = (float*)p;
    cudaGetSymbolAddress(&p, g_QKVG); float* pQKVG = (float*)p;

    cudaFuncSetAttribute(attn_k, cudaFuncAttributeMaxDynamicSharedMemorySize, ATTN_SMEM);
    cudaFuncSetAttribute(tgemm_k<0>, cudaFuncAttributeMaxDynamicSharedMemorySize, SMEM_GEMM);
    cudaFuncSetAttribute(tgemm_k<1>, cudaFuncAttributeMaxDynamicSharedMemorySize, SMEM_GEMM);
    cudaFuncSetAttribute(tgemm_k<2>, cudaFuncAttributeMaxDynamicSharedMemorySize, SMEM_GEMM);
    cudaFuncSetAttribute(tgemm_k<3>, cudaFuncAttributeMaxDynamicSharedMemorySize, SMEM_GEMM);

    copy_k<<<(BL * DIM / 4 + 255) / 256, 256>>>(X, pX, BL * DIM / 4);

    dim3 gProj(PSTR / 128, BL / 128);   // 32 x 32
    dim3 gDim (DIM  / 128, BL / 128);   // 8 x 32
    dim3 gFfn (FFN  / 128, BL / 128);   // 32 x 32

    for (int i = 0; i < NLAYERS; i++) {
        size_t wofs = (size_t)i * HEADS * DIM * HD;
        pack_qkvg_k<<<(DIM * DIM + 255) / 256, 256>>>(Wq + wofs, Wk + wofs, Wv + wofs,
                                                      W_G + (size_t)i * DIM * VD, pWbig);
        layernorm_k<<<BL, 256>>>(pX, pXn, ln1w + i * DIM, ln1b + i * DIM);

        tgemm_k<0><<<gProj, 128, SMEM_GEMM>>>(pXn, pWbig, pQKVG, nullptr, nullptr,
                                              BL, PSTR, DIM);

        xpos_k<<<(BATCH * SEQ * HEADS * 64 + 255) / 256, 256>>>(pQKVG);

        attn_k<<<dim3(SEQ / 64, BATCH * HEADS), 256, ATTN_SMEM>>>(pQKVG, pY);

        gn_gate_k<<<(BATCH * HEADS * SEQ) / 8, 256>>>(pY, pQKVG, gnw + i * VD,
                                                      gnb + i * VD, pYg);

        tgemm_k<1><<<gDim, 128, SMEM_GEMM>>>(pYg, W_O + (size_t)i * VD * DIM, pAtt,
                                             nullptr, pX, BL, DIM, DIM);

        layernorm_k<<<BL, 256>>>(pAtt, pXn, ln2w + i * DIM, ln2b + i * DIM);

        tgemm_k<2><<<gFfn, 128, SMEM_GEMM>>>(pXn, fw1 + (size_t)i * DIM * FFN, pH,
                                             fb1 + i * FFN, nullptr, BL, FFN, DIM);

        float* dst = (i == NLAYERS - 1) ? out : pX;
        tgemm_k<3><<<gDim, 128, SMEM_GEMM>>>(pH, fw2 + (size_t)i * FFN * DIM, dst,
                                             fb2 + i * DIM, pAtt, BL, DIM, FFN);
    }
}

// round 11
// speedup vs baseline: 5.0080x; 1.0487x over previous
#include <cuda_runtime.h>
#include <math.h>

#define BATCH 2
#define SEQ   2048
#define DIM   1024
#define FFN   4096
#define HEADS 8
#define HD    128
#define HV    128
#define VD    1024
#define NLAYERS 2
#define BL    (BATCH*SEQ)          // 4096
#define EPSV  1e-5f
#define PSTR  (4*DIM)              // packed QKVG row stride

// ---------------- scratch (static device globals; no allocations) ----------
__device__ float g_X   [BL*DIM];
__device__ float g_Xn  [BL*DIM];
__device__ float g_Y   [BL*DIM];
__device__ float g_Yg  [BL*DIM];
__device__ float g_Att [BL*DIM];
__device__ float g_Hf  [BL*FFN];
__device__ float g_Wbig[DIM*PSTR];
__device__ float g_QKVG[(size_t)BL*PSTR];
__device__ float g_Wo  [DIM*DIM];
__device__ float g_Wf1 [DIM*FFN];
__device__ float g_Wf2 [FFN*DIM];

// ---------------- small helpers -------------------------------------------
__device__ __forceinline__ float gelu_f(float x) {
    return 0.5f * x * (1.0f + erff(x * 0.70710678118654752f));
}

__device__ __forceinline__ unsigned f2tf32(float x) {
    unsigned r;
    asm("cvt.rna.tf32.f32 %0, %1;" : "=r"(r) : "f"(x));
    return r;
}

__device__ __forceinline__ void stcvt4(float* dst, float4 a) {
    dst[0] = __uint_as_float(f2tf32(a.x));
    dst[1] = __uint_as_float(f2tf32(a.y));
    dst[2] = __uint_as_float(f2tf32(a.z));
    dst[3] = __uint_as_float(f2tf32(a.w));
}

__device__ __forceinline__ void mma_tf32(float* c, unsigned a0, unsigned a1,
                                         unsigned a2, unsigned a3,
                                         unsigned b0, unsigned b1) {
    asm volatile(
        "mma.sync.aligned.m16n8k8.row.col.f32.tf32.tf32.f32 "
        "{%0,%1,%2,%3}, {%4,%5,%6,%7}, {%8,%9}, {%0,%1,%2,%3};"
        : "+f"(c[0]), "+f"(c[1]), "+f"(c[2]), "+f"(c[3])
        : "r"(a0), "r"(a1), "r"(a2), "r"(a3), "r"(b0), "r"(b1));
}

__device__ __forceinline__ void cpa16(void* smem, const void* g) {
    unsigned s = (unsigned)__cvta_generic_to_shared(smem);
    asm volatile("cp.async.cg.shared.global [%0], [%1], 16;" :: "r"(s), "l"(g));
}
__device__ __forceinline__ void cp_commit() {
    asm volatile("cp.async.commit_group;");
}
template<int N> __device__ __forceinline__ void cp_wait() {
    asm volatile("cp.async.wait_group %0;" :: "n"(N));
}

// ---------------- copy X -> scratch ---------------------------------------
__global__ void copy_k(const float* __restrict__ src, float* __restrict__ dst, int n4) {
    int i = blockIdx.x * blockDim.x + threadIdx.x;
    if (i < n4) ((float4*)dst)[i] = ((const float4*)src)[i];
}

// ---------------- cvt-copy: fp32 -> tf32-rounded fp32 bits -----------------
__global__ void cvtcopy_k(const float* __restrict__ src, float* __restrict__ dst, int n4) {
    int i = blockIdx.x * blockDim.x + threadIdx.x;
    if (i >= n4) return;
    float4 v = ((const float4*)src)[i];
    float4 o;
    o.x = __uint_as_float(f2tf32(v.x));
    o.y = __uint_as_float(f2tf32(v.y));
    o.z = __uint_as_float(f2tf32(v.z));
    o.w = __uint_as_float(f2tf32(v.w));
    ((float4*)dst)[i] = o;
}

// ---------------- pack Wq|Wk|Wv|WG -> [d][4096] (tf32-rounded) -------------
__global__ void pack_qkvg_k(const float* __restrict__ Wq, const float* __restrict__ Wk,
                            const float* __restrict__ Wv, const float* __restrict__ WG,
                            float* __restrict__ P) {
    int idx = blockIdx.x * blockDim.x + threadIdx.x;       // over DIM*DIM (d, j)
    if (idx >= DIM * DIM) return;
    int d = idx >> 10;
    int j = idx & 1023;
    int h = j >> 7, e = j & 127;
    int src = (h * DIM + d) * HD + e;                      // W[h][d][e]
    float* row = P + (size_t)d * PSTR;
    row[j]        = __uint_as_float(f2tf32(Wq[src]));
    row[1024 + j] = __uint_as_float(f2tf32(Wk[src]));
    row[2048 + j] = __uint_as_float(f2tf32(Wv[src]));
    row[3072 + j] = __uint_as_float(f2tf32(WG[d * VD + j]));
}

// ---------------- layernorm over 1024 (tf32-rounded output) ----------------
__global__ void __launch_bounds__(256) layernorm_k(const float* __restrict__ in,
        float* __restrict__ out, const float* __restrict__ w, const float* __restrict__ bb) {
    int row = blockIdx.x, tid = threadIdx.x;
    const float4 xv = *(const float4*)(in + (size_t)row * DIM + tid * 4);
    float s  = xv.x + xv.y + xv.z + xv.w;
    float ss = xv.x*xv.x + xv.y*xv.y + xv.z*xv.z + xv.w*xv.w;
    #pragma unroll
    for (int o = 16; o; o >>= 1) {
        s  += __shfl_xor_sync(0xffffffffu, s,  o);
        ss += __shfl_xor_sync(0xffffffffu, ss, o);
    }
    __shared__ float sw[8], ssw[8], stat[2];
    int wid = tid >> 5, lane = tid & 31;
    if (!lane) { sw[wid] = s; ssw[wid] = ss; }
    __syncthreads();
    if (tid == 0) {
        float S = 0.f, SS = 0.f;
        #pragma unroll
        for (int i = 0; i < 8; i++) { S += sw[i]; SS += ssw[i]; }
        float mean = S * (1.f / DIM);
        float var  = SS * (1.f / DIM) - mean * mean;
        stat[0] = mean;
        stat[1] = rsqrtf(var + EPSV);
    }
    __syncthreads();
    float mean = stat[0], rstd = stat[1];
    const float4 wv = *(const float4*)(w  + tid * 4);
    const float4 bv = *(const float4*)(bb + tid * 4);
    float4 o;
    o.x = (xv.x - mean) * rstd * wv.x + bv.x;
    o.y = (xv.y - mean) * rstd * wv.y + bv.y;
    o.z = (xv.z - mean) * rstd * wv.z + bv.z;
    o.w = (xv.w - mean) * rstd * wv.w + bv.w;
    stcvt4(out + (size_t)row * DIM + tid * 4, o);
}

// ---------------- TF32 tensor-core GEMM, cp.async 3-stage ------------------
// C[M,N] = A[M,K] @ B[K,N]; operands PRE-ROUNDED to tf32 values in gmem.
// 4 warps, warp tile 64x64, CTA 128x128, k-step 16.
// EPI: 0 none | 1 +R | 2 +bias,gelu,cvt-out | 3 +bias,+R
#define LDA 20
#define LDB 136
#define GSTAGE 3
#define SMEM_GEMM (GSTAGE*(128*LDA + 16*LDB)*4)

template<int EPI>
__global__ void __launch_bounds__(128) tgemm_k(const float* __restrict__ A,
        const float* __restrict__ Bw, float* __restrict__ C,
        const float* __restrict__ bias, const float* __restrict__ R,
        int M, int N, int K) {
    extern __shared__ float smg[];
    float* AsBase = smg;                         // [GSTAGE][128*LDA]
    float* BsBase = smg + GSTAGE * 128 * LDA;    // [GSTAGE][16*LDB]

    const int tid  = threadIdx.x;
    const int lane = tid & 31;
    const int warp = tid >> 5;
    const int wm = warp >> 1, wn = warp & 1;
    const int row0 = blockIdx.y * 128, col0 = blockIdx.x * 128;
    const int qr = lane >> 2, qc = lane & 3;

    const int aRow = tid >> 2,  aCol = (tid & 3) * 4;
    const int bRow = tid >> 5,  bCol = (tid & 31) * 4;

    float acc[4][8][4];
    #pragma unroll
    for (int i = 0; i < 4; i++)
        #pragma unroll
        for (int j = 0; j < 8; j++)
            #pragma unroll
            for (int q = 0; q < 4; q++) acc[i][j][q] = 0.f;

    auto load_stage = [&](int st, int k0) {
        float* as = AsBase + st * 128 * LDA;
        #pragma unroll
        for (int i = 0; i < 4; i++) {
            int r = aRow + 32 * i;
            cpa16(&as[r * LDA + aCol], &A[(size_t)(row0 + r) * K + k0 + aCol]);
        }
        float* bs = BsBase + st * 16 * LDB;
        #pragma unroll
        for (int i = 0; i < 4; i++) {
            int k = bRow + 4 * i;
            cpa16(&bs[k * LDB + bCol], &Bw[(size_t)(k0 + k) * N + col0 + bCol]);
        }
        cp_commit();
    };

    load_stage(0, 0);
    load_stage(1, 16);

    const int nk = K >> 4;
    for (int s = 0; s < nk; s++) {
        if (s + 1 < nk) cp_wait<1>(); else cp_wait<0>();
        __syncthreads();
        const float* as = AsBase + (s % 3) * 128 * LDA;
        const float* bs = BsBase + (s % 3) * 16 * LDB;
        #pragma unroll
        for (int kk = 0; kk < 16; kk += 8) {
            unsigned av[4][4], bv[8][2];
            #pragma unroll
            for (int mi = 0; mi < 4; mi++) {
                int r = wm * 64 + mi * 16 + qr;
                int c = kk + qc;
                av[mi][0] = __float_as_uint(as[r * LDA + c]);
                av[mi][1] = __float_as_uint(as[(r + 8) * LDA + c]);
                av[mi][2] = __float_as_uint(as[r * LDA + c + 4]);
                av[mi][3] = __float_as_uint(as[(r + 8) * LDA + c + 4]);
            }
            #pragma unroll
            for (int nj = 0; nj < 8; nj++) {
                int n  = wn * 64 + nj * 8 + qr;
                int kb = kk + qc;
                bv[nj][0] = __float_as_uint(bs[kb * LDB + n]);
                bv[nj][1] = __float_as_uint(bs[(kb + 4) * LDB + n]);
            }
            #pragma unroll
            for (int mi = 0; mi < 4; mi++)
                #pragma unroll
                for (int nj = 0; nj < 8; nj++)
                    mma_tf32(acc[mi][nj], av[mi][0], av[mi][1], av[mi][2], av[mi][3],
                             bv[nj][0], bv[nj][1]);
        }
        // NOTE: no barrier needed here — next iteration's top barrier protects
        // buffer reuse; load_stage below writes the buffer consumed 2 iters ago.
        if (s + 2 < nk) load_stage((s + 2) % 3, (s + 2) * 16);
    }

    // epilogue
    #pragma unroll
    for (int mi = 0; mi < 4; mi++) {
        const int r = row0 + wm * 64 + mi * 16 + qr;
        #pragma unroll
        for (int nj = 0; nj < 8; nj++) {
            const int cidx = col0 + wn * 64 + nj * 8 + 2 * qc;
            float v0 = acc[mi][nj][0], v1 = acc[mi][nj][1];
            float v2 = acc[mi][nj][2], v3 = acc[mi][nj][3];
            if (EPI == 2 || EPI == 3) {
                float b0 = bias[cidx], b1 = bias[cidx + 1];
                v0 += b0; v1 += b1; v2 += b0; v3 += b1;
            }
            if (EPI == 2) {
                // FFN1 output feeds FFN2's A operand: round to tf32 at store.
                v0 = __uint_as_float(f2tf32(gelu_f(v0)));
                v1 = __uint_as_float(f2tf32(gelu_f(v1)));
                v2 = __uint_as_float(f2tf32(gelu_f(v2)));
                v3 = __uint_as_float(f2tf32(gelu_f(v3)));
            }
            const size_t o0 = (size_t)r * N + cidx;
            const size_t o1 = (size_t)(r + 8) * N + cidx;
            if (EPI == 1 || EPI == 3) {
                const float2 r0 = *(const float2*)&R[o0];
                const float2 r1 = *(const float2*)&R[o1];
                v0 += r0.x; v1 += r0.y; v2 += r1.x; v3 += r1.y;
            }
            *(float2*)&C[o0] = make_float2(v0, v1);
            *(float2*)&C[o1] = make_float2(v2, v3);
        }
    }
}

// ---------------- xPos rotary (in-place on packed QKVG) --------------------
__global__ void xpos_k(float* __restrict__ QKVG) {
    int idx = blockIdx.x * blockDim.x + threadIdx.x;  // over B*L*H*64 pairs
    if (idx >= BATCH * SEQ * HEADS * 64) return;
    int p = idx & 63;
    int h = (idx >> 6) & 7;
    int l = (idx >> 9) & (SEQ - 1);
    int b = idx >> (9 + 11);
    size_t base = ((size_t)(b * SEQ + l)) * PSTR + h * HD + 2 * p;
    float pos = (float)l;
    float bs  = (2.f * p + 0.4f * HD) / (1.4f * HD);
    float sc  = powf(bs, pos * (1.f / 512.f));
    float invf = expf(-(float)p * (logf(10000.f) / 64.f));
    float ang = pos * invf;
    float sn, cs;
    sincosf(ang, &sn, &cs);
    float* Q = QKVG;
    float* K = QKVG + 1024;
    float q0 = Q[base], q1 = Q[base + 1];
    Q[base]     = q0 * cs * sc - q1 * sn * sc;
    Q[base + 1] = q1 * cs * sc + q0 * sn * sc;
    float isc = 1.f / sc;
    float k0 = K[base], k1 = K[base + 1];
    K[base]     = k0 * cs * isc - k1 * sn * isc;
    K[base + 1] = k1 * cs * isc + k0 * sn * isc;
}

// ---------------- fused retention attention (tf32 tensor-core) -------------
// Reads Q/K/V from packed QKVG (row stride PSTR, col offsets 0/1024/2048).
#define AT_LDQ 132
#define AT_LDV 68
#define AT_LDS 68
#define ATTN_SMEM ((64*AT_LDQ*2 + 128*AT_LDV + 64*AT_LDS)*4)

__global__ void __launch_bounds__(256) attn_k(const float* __restrict__ QKVG,
                                              float* __restrict__ Y) {
    extern __shared__ float sm[];
    float* Qs = sm;                        // [64][132] tf32
    float* Ks = Qs + 64 * AT_LDQ;          // [64][132] tf32
    float* Vt = Ks + 64 * AT_LDQ;          // [128][68] tf32 (transposed: [v][m])
    float* Ss = Vt + 128 * AT_LDV;         // [64][68]  tf32
    const int tid  = threadIdx.x;
    const int lane = tid & 31;
    const int warp = tid >> 5;
    const int wm = warp >> 1;              // 0..3
    const int wn = warp & 1;               // 0..1
    const int q0 = blockIdx.x * 64;
    const int bh = blockIdx.y;
    const int b = bh >> 3, h = bh & 7;
    const float gamma = 1.f - expf(-3.4657359028f + (float)h * -0.3960840962f);
    const float lg = logf(gamma);

    const float* Qg = QKVG;
    const float* Kg = QKVG + 1024;
    const float* Vg = QKVG + 2048;

    // load Q tile (cvt to tf32)
    for (int i = tid; i < 64 * 32; i += 256) {
        int r = i >> 5, c = (i & 31) << 2;
        float4 v = *(const float4*)&Qg[((size_t)(b * SEQ + q0 + r)) * PSTR + h * HD + c];
        stcvt4(&Qs[r * AT_LDQ + c], v);
    }

    float acc2[8][4];
    #pragma unroll
    for (int j = 0; j < 8; j++) { acc2[j][0]=acc2[j][1]=acc2[j][2]=acc2[j][3]=0.f; }

    const int qr = (lane >> 2);
    const int qc = (lane & 3);

    const int nmt = (q0 >> 6) + 1;
    for (int mt = 0; mt < nmt; mt++) {
        const int m0 = mt << 6;
        __syncthreads();
        for (int i = tid; i < 64 * 32; i += 256) {
            int r = i >> 5, c = (i & 31) << 2;
            float4 v = *(const float4*)&Kg[((size_t)(b * SEQ + m0 + r)) * PSTR + h * HD + c];
            stcvt4(&Ks[r * AT_LDQ + c], v);
        }
        {
            const int mo = lane & 7;
            const int v0 = (lane >> 3) << 2;
            const int mrow = warp * 8 + mo;
            const float* vsrc = &Vg[((size_t)(b * SEQ + m0 + mrow)) * PSTR + h * HD];
            #pragma unroll
            for (int vb = 0; vb < 128; vb += 16) {
                float4 vv = *(const float4*)&vsrc[vb + v0];
                Vt[(vb + v0 + 0) * AT_LDV + mrow] = __uint_as_float(f2tf32(vv.x));
                Vt[(vb + v0 + 1) * AT_LDV + mrow] = __uint_as_float(f2tf32(vv.y));
                Vt[(vb + v0 + 2) * AT_LDV + mrow] = __uint_as_float(f2tf32(vv.z));
                Vt[(vb + v0 + 3) * AT_LDV + mrow] = __uint_as_float(f2tf32(vv.w));
            }
        }
        __syncthreads();

        // ---- S = Q K^T : warp tile 16x32, k=128 ----
        float sacc[4][4];
        #pragma unroll
        for (int nj = 0; nj < 4; nj++) { sacc[nj][0]=sacc[nj][1]=sacc[nj][2]=sacc[nj][3]=0.f; }
        #pragma unroll
        for (int k0 = 0; k0 < 128; k0 += 8) {
            const int r = wm * 16 + qr;
            const int c = k0 + qc;
            unsigned a0 = __float_as_uint(Qs[r * AT_LDQ + c]);
            unsigned a1 = __float_as_uint(Qs[(r + 8) * AT_LDQ + c]);
            unsigned a2 = __float_as_uint(Qs[r * AT_LDQ + c + 4]);
            unsigned a3 = __float_as_uint(Qs[(r + 8) * AT_LDQ + c + 4]);
            #pragma unroll
            for (int nj = 0; nj < 4; nj++) {
                const int n = wn * 32 + nj * 8 + qr;
                unsigned b0 = __float_as_uint(Ks[n * AT_LDQ + c]);
                unsigned b1 = __float_as_uint(Ks[n * AT_LDQ + c + 4]);
                mma_tf32(sacc[nj], a0, a1, a2, a3, b0, b1);
            }
        }
        {
            const int lr = wm * 16 + qr;
            const int li  = q0 + lr;
            const int li8 = li + 8;
            #pragma unroll
            for (int nj = 0; nj < 4; nj++) {
                const int lc = wn * 32 + nj * 8 + 2 * qc;
                const int mj = m0 + lc;
                float d00 = (li  >= mj    ) ? __expf(lg * (float)(li  - mj    )) : 0.f;
                float d01 = (li  >= mj + 1) ? __expf(lg * (float)(li  - mj - 1)) : 0.f;
                float d10 = (li8 >= mj    ) ? __expf(lg * (float)(li8 - mj    )) : 0.f;
                float d11 = (li8 >= mj + 1) ? __expf(lg * (float)(li8 - mj - 1)) : 0.f;
                Ss[lr * AT_LDS + lc]           = __uint_as_float(f2tf32(sacc[nj][0] * d00));
                Ss[lr * AT_LDS + lc + 1]       = __uint_as_float(f2tf32(sacc[nj][1] * d01));
                Ss[(lr + 8) * AT_LDS + lc]     = __uint_as_float(f2tf32(sacc[nj][2] * d10));
                Ss[(lr + 8) * AT_LDS + lc + 1] = __uint_as_float(f2tf32(sacc[nj][3] * d11));
            }
        }
        __syncthreads();

        // ---- Y += S @ V : warp tile 16x64, k=64 ----
        #pragma unroll
        for (int k0 = 0; k0 < 64; k0 += 8) {
            const int r = wm * 16 + qr;
            const int c = k0 + qc;
            unsigned a0 = __float_as_uint(Ss[r * AT_LDS + c]);
            unsigned a1 = __float_as_uint(Ss[(r + 8) * AT_LDS + c]);
            unsigned a2 = __float_as_uint(Ss[r * AT_LDS + c + 4]);
            unsigned a3 = __float_as_uint(Ss[(r + 8) * AT_LDS + c + 4]);
            #pragma unroll
            for (int nj = 0; nj < 8; nj++) {
                const int n = wn * 64 + nj * 8 + qr;
                unsigned b0 = __float_as_uint(Vt[n * AT_LDV + c]);
                unsigned b1 = __float_as_uint(Vt[n * AT_LDV + c + 4]);
                mma_tf32(acc2[nj], a0, a1, a2, a3, b0, b1);
            }
        }
    }

    {
        const int lr = wm * 16 + qr;
        const size_t rowbase = (size_t)((b * 8 + h) * SEQ) + q0 + lr;
        #pragma unroll
        for (int nj = 0; nj < 8; nj++) {
            const int c = wn * 64 + nj * 8 + 2 * qc;
            *(float2*)&Y[rowbase * HV + c]       = make_float2(acc2[nj][0], acc2[nj][1]);
            *(float2*)&Y[(rowbase + 8) * HV + c] = make_float2(acc2[nj][2], acc2[nj][3]);
        }
    }
}

// ---------------- per-head groupnorm + SiLU gate (tf32-rounded out) --------
__global__ void __launch_bounds__(256) gn_gate_k(const float* __restrict__ Y,
        const float* __restrict__ QKVG, const float* __restrict__ gnw,
        const float* __restrict__ gnb, float* __restrict__ out) {
    int gwarp = (blockIdx.x * blockDim.x + threadIdx.x) >> 5;   // row over B*H*L
    int lane = threadIdx.x & 31;
    if (gwarp >= BATCH * HEADS * SEQ) return;
    int b = gwarp / (HEADS * SEQ);
    int h = (gwarp / SEQ) & 7;
    int l = gwarp & (SEQ - 1);
    const float* y = Y + (size_t)gwarp * HV;
    float v0 = y[lane], v1 = y[lane + 32], v2 = y[lane + 64], v3 = y[lane + 96];
    float s  = v0 + v1 + v2 + v3;
    float ss = v0*v0 + v1*v1 + v2*v2 + v3*v3;
    #pragma unroll
    for (int o = 16; o; o >>= 1) {
        s  += __shfl_xor_sync(0xffffffffu, s,  o);
        ss += __shfl_xor_sync(0xffffffffu, ss, o);
    }
    float mean = s * (1.f / HV);
    float var  = ss * (1.f / HV) - mean * mean;
    float rstd = rsqrtf(var + EPSV);
    size_t row = (size_t)(b * SEQ + l);
    const float* Gp = QKVG + row * PSTR + 3072 + h * HV;
    size_t ob = row * VD + h * HV;
    float vv[4] = {v0, v1, v2, v3};
    #pragma unroll
    for (int i = 0; i < 4; i++) {
        int c = lane + i * 32;
        float g = Gp[c];
        float gate = g / (1.f + expf(-g));
        float r = ((vv[i] - mean) * rstd * gnw[h * HV + c] + gnb[h * HV + c]) * gate;
        out[ob + c] = __uint_as_float(f2tf32(r));   // feeds W_O GEMM A operand
    }
}

// ---------------- host launcher --------------------------------------------
extern "C" void kernel_launch(void* const* d_in, const int* in_sizes, int n_in,
                              void* d_out, int out_size) {
    const float* X    = (const float*)d_in[0];
    const float* Wq   = (const float*)d_in[1];
    const float* Wk   = (const float*)d_in[2];
    const float* Wv   = (const float*)d_in[3];
    const float* W_G  = (const float*)d_in[4];
    const float* W_O  = (const float*)d_in[5];
    const float* gnw  = (const float*)d_in[6];
    const float* gnb  = (const float*)d_in[7];
    const float* ln1w = (const float*)d_in[8];
    const float* ln1b = (const float*)d_in[9];
    const float* ln2w = (const float*)d_in[10];
    const float* ln2b = (const float*)d_in[11];
    const float* fw1  = (const float*)d_in[12];
    const float* fb1  = (const float*)d_in[13];
    const float* fw2  = (const float*)d_in[14];
    const float* fb2  = (const float*)d_in[15];
    float* out = (float*)d_out;

    void* p;
    cudaGetSymbolAddress(&p, g_X);    float* pX    = (float*)p;
    cudaGetSymbolAddress(&p, g_Xn);   float* pXn   = (float*)p;
    cudaGetSymbolAddress(&p, g_Y);    float* pY    = (float*)p;
    cudaGetSymbolAddress(&p, g_Yg);   float* pYg   = (float*)p;
    cudaGetSymbolAddress(&p, g_Att);  float* pAtt  = (float*)p;
    cudaGetSymbolAddress(&p, g_Hf);   float* pH    = (float*)p;
    cudaGetSymbolAddress(&p, g_Wbig); float* pWbig = (float*)p;
    cudaGetSymbolAddress(&p, g_QKVG); float* pQKVG = (float*)p;
    cudaGetSymbolAddress(&p, g_Wo);   float* pWo   = (float*)p;
    cudaGetSymbolAddress(&p, g_Wf1);  float* pWf1  = (float*)p;
    cudaGetSymbolAddress(&p, g_Wf2);  float* pWf2  = (float*)p;

    cudaFuncSetAttribute(attn_k, cudaFuncAttributeMaxDynamicSharedMemorySize, ATTN_SMEM);
    cudaFuncSetAttribute(tgemm_k<0>, cudaFuncAttributeMaxDynamicSharedMemorySize, SMEM_GEMM);
    cudaFuncSetAttribute(tgemm_k<1>, cudaFuncAttributeMaxDynamicSharedMemorySize, SMEM_GEMM);
    cudaFuncSetAttribute(tgemm_k<2>, cudaFuncAttributeMaxDynamicSharedMemorySize, SMEM_GEMM);
    cudaFuncSetAttribute(tgemm_k<3>, cudaFuncAttributeMaxDynamicSharedMemorySize, SMEM_GEMM);

    copy_k<<<(BL * DIM / 4 + 255) / 256, 256>>>(X, pX, BL * DIM / 4);

    dim3 gProj(PSTR / 128, BL / 128);   // 32 x 32
    dim3 gDim (DIM  / 128, BL / 128);   // 8 x 32
    dim3 gFfn (FFN  / 128, BL / 128);   // 32 x 32

    for (int i = 0; i < NLAYERS; i++) {
        size_t wofs = (size_t)i * HEADS * DIM * HD;
        pack_qkvg_k<<<(DIM * DIM + 255) / 256, 256>>>(Wq + wofs, Wk + wofs, Wv + wofs,
                                                      W_G + (size_t)i * DIM * VD, pWbig);
        cvtcopy_k<<<(DIM * DIM / 4 + 255) / 256, 256>>>(W_O + (size_t)i * VD * DIM,
                                                        pWo, DIM * DIM / 4);
        cvtcopy_k<<<(DIM * FFN / 4 + 255) / 256, 256>>>(fw1 + (size_t)i * DIM * FFN,
                                                        pWf1, DIM * FFN / 4);
        cvtcopy_k<<<(FFN * DIM / 4 + 255) / 256, 256>>>(fw2 + (size_t)i * FFN * DIM,
                                                        pWf2, FFN * DIM / 4);

        layernorm_k<<<BL, 256>>>(pX, pXn, ln1w + i * DIM, ln1b + i * DIM);

        tgemm_k<0><<<gProj, 128, SMEM_GEMM>>>(pXn, pWbig, pQKVG, nullptr, nullptr,
                                              BL, PSTR, DIM);

        xpos_k<<<(BATCH * SEQ * HEADS * 64 + 255) / 256, 256>>>(pQKVG);

        attn_k<<<dim3(SEQ / 64, BATCH * HEADS), 256, ATTN_SMEM>>>(pQKVG, pY);

        gn_gate_k<<<(BATCH * HEADS * SEQ) / 8, 256>>>(pY, pQKVG, gnw + i * VD,
                                                      gnb + i * VD, pYg);

        tgemm_k<1><<<gDim, 128, SMEM_GEMM>>>(pYg, pWo, pAtt, nullptr, pX, BL, DIM, DIM);

        layernorm_k<<<BL, 256>>>(pAtt, pXn, ln2w + i * DIM, ln2b + i * DIM);

        tgemm_k<2><<<gFfn, 128, SMEM_GEMM>>>(pXn, pWf1, pH, fb1 + i * FFN, nullptr,
                                             BL, FFN, DIM);

        float* dst = (i == NLAYERS - 1) ? out : pX;
        tgemm_k<3><<<gDim, 128, SMEM_GEMM>>>(pH, pWf2, dst, fb2 + i * DIM, pAtt,
                                             BL, DIM, FFN);
    }
}

// round 12
// speedup vs baseline: 5.9234x; 1.1828x over previous
#include <cuda_runtime.h>
#include <cuda_fp16.h>
#include <math.h>

#define BATCH 2
#define SEQ   2048
#define DIM   1024
#define FFN   4096
#define HEADS 8
#define HD    128
#define HV    128
#define VD    1024
#define NLAYERS 2
#define BL    (BATCH*SEQ)          // 4096
#define EPSV  1e-5f
#define PSTR  (4*DIM)              // packed QKVG row stride

// ---------------- scratch (static device globals; no allocations) ----------
__device__ float  g_X   [BL*DIM];
__device__ float  g_Y   [BL*DIM];
__device__ float  g_Att [BL*DIM];
__device__ float  g_QKVG[(size_t)BL*PSTR];
__device__ __half g_Xn  [BL*DIM];
__device__ __half g_Yg  [BL*DIM];
__device__ __half g_Hf  [(size_t)BL*FFN];
__device__ __half g_WbigT[(size_t)PSTR*DIM];   // [n=4096][k=1024]
__device__ __half g_WoT [DIM*DIM];             // [n=1024][k=1024]
__device__ __half g_Wf1T[(size_t)FFN*DIM];     // [n=4096][k=1024]
__device__ __half g_Wf2T[(size_t)DIM*FFN];     // [n=1024][k=4096]

// ---------------- small helpers -------------------------------------------
__device__ __forceinline__ float gelu_f(float x) {
    return 0.5f * x * (1.0f + erff(x * 0.70710678118654752f));
}

__device__ __forceinline__ unsigned f2tf32(float x) {
    unsigned r;
    asm("cvt.rna.tf32.f32 %0, %1;" : "=r"(r) : "f"(x));
    return r;
}

__device__ __forceinline__ void stcvt4(float* dst, float4 a) {
    dst[0] = __uint_as_float(f2tf32(a.x));
    dst[1] = __uint_as_float(f2tf32(a.y));
    dst[2] = __uint_as_float(f2tf32(a.z));
    dst[3] = __uint_as_float(f2tf32(a.w));
}

__device__ __forceinline__ void mma_tf32(float* c, unsigned a0, unsigned a1,
                                         unsigned a2, unsigned a3,
                                         unsigned b0, unsigned b1) {
    asm volatile(
        "mma.sync.aligned.m16n8k8.row.col.f32.tf32.tf32.f32 "
        "{%0,%1,%2,%3}, {%4,%5,%6,%7}, {%8,%9}, {%0,%1,%2,%3};"
        : "+f"(c[0]), "+f"(c[1]), "+f"(c[2]), "+f"(c[3])
        : "r"(a0), "r"(a1), "r"(a2), "r"(a3), "r"(b0), "r"(b1));
}

__device__ __forceinline__ void mma_f16(float* c, unsigned a0, unsigned a1,
                                        unsigned a2, unsigned a3,
                                        unsigned b0, unsigned b1) {
    asm volatile(
        "mma.sync.aligned.m16n8k16.row.col.f32.f16.f16.f32 "
        "{%0,%1,%2,%3}, {%4,%5,%6,%7}, {%8,%9}, {%0,%1,%2,%3};"
        : "+f"(c[0]), "+f"(c[1]), "+f"(c[2]), "+f"(c[3])
        : "r"(a0), "r"(a1), "r"(a2), "r"(a3), "r"(b0), "r"(b1));
}

__device__ __forceinline__ void cpa16(void* smem, const void* g) {
    unsigned s = (unsigned)__cvta_generic_to_shared(smem);
    asm volatile("cp.async.cg.shared.global [%0], [%1], 16;" :: "r"(s), "l"(g));
}
__device__ __forceinline__ void cp_commit() {
    asm volatile("cp.async.commit_group;");
}
template<int N> __device__ __forceinline__ void cp_wait() {
    asm volatile("cp.async.wait_group %0;" :: "n"(N));
}

// ---------------- copy X -> scratch ---------------------------------------
__global__ void copy_k(const float* __restrict__ src, float* __restrict__ dst, int n4) {
    int i = blockIdx.x * blockDim.x + threadIdx.x;
    if (i < n4) ((float4*)dst)[i] = ((const float4*)src)[i];
}

// ---------------- tiled transpose fp32 -> fp16 -----------------------------
// dst[c][r] = (half)src[r][c]; grid (C/32, R/32), block (32, 8)
__global__ void transpose_h_k(const float* __restrict__ src, __half* __restrict__ dst,
                              int sstride, int dstride) {
    __shared__ float t[32][33];
    int c0 = blockIdx.x * 32, r0 = blockIdx.y * 32;
    int tx = threadIdx.x, ty = threadIdx.y;
    #pragma unroll
    for (int i = 0; i < 32; i += 8)
        t[ty + i][tx] = src[(size_t)(r0 + ty + i) * sstride + c0 + tx];
    __syncthreads();
    #pragma unroll
    for (int i = 0; i < 32; i += 8)
        dst[(size_t)(c0 + ty + i) * dstride + r0 + tx] = __float2half_rn(t[tx][ty + i]);
}

// batched Wq/Wk/Wv head transpose -> WbigT rows [m*1024 + h*128 + e][d]
__global__ void pack_qkv_t_k(const float* __restrict__ Wq, const float* __restrict__ Wk,
                             const float* __restrict__ Wv, __half* __restrict__ dstBase) {
    __shared__ float t[32][33];
    int z = blockIdx.z;
    int m = z >> 3, h = z & 7;
    const float* src = (m == 0 ? Wq : (m == 1 ? Wk : Wv)) + (size_t)h * DIM * HD;
    __half* dst = dstBase + (size_t)(m * 1024 + h * 128) * DIM;
    int c0 = blockIdx.x * 32, r0 = blockIdx.y * 32;   // c over e(128), r over d(1024)
    int tx = threadIdx.x, ty = threadIdx.y;
    #pragma unroll
    for (int i = 0; i < 32; i += 8)
        t[ty + i][tx] = src[(size_t)(r0 + ty + i) * HD + c0 + tx];
    __syncthreads();
    #pragma unroll
    for (int i = 0; i < 32; i += 8)
        dst[(size_t)(c0 + ty + i) * DIM + r0 + tx] = __float2half_rn(t[tx][ty + i]);
}

// ---------------- layernorm over 1024 -> fp16 out --------------------------
__global__ void __launch_bounds__(256) layernorm_k(const float* __restrict__ in,
        __half* __restrict__ out, const float* __restrict__ w, const float* __restrict__ bb) {
    int row = blockIdx.x, tid = threadIdx.x;
    const float4 xv = *(const float4*)(in + (size_t)row * DIM + tid * 4);
    float s  = xv.x + xv.y + xv.z + xv.w;
    float ss = xv.x*xv.x + xv.y*xv.y + xv.z*xv.z + xv.w*xv.w;
    #pragma unroll
    for (int o = 16; o; o >>= 1) {
        s  += __shfl_xor_sync(0xffffffffu, s,  o);
        ss += __shfl_xor_sync(0xffffffffu, ss, o);
    }
    __shared__ float sw[8], ssw[8], stat[2];
    int wid = tid >> 5, lane = tid & 31;
    if (!lane) { sw[wid] = s; ssw[wid] = ss; }
    __syncthreads();
    if (tid == 0) {
        float S = 0.f, SS = 0.f;
        #pragma unroll
        for (int i = 0; i < 8; i++) { S += sw[i]; SS += ssw[i]; }
        float mean = S * (1.f / DIM);
        float var  = SS * (1.f / DIM) - mean * mean;
        stat[0] = mean;
        stat[1] = rsqrtf(var + EPSV);
    }
    __syncthreads();
    float mean = stat[0], rstd = stat[1];
    const float4 wv = *(const float4*)(w  + tid * 4);
    const float4 bv = *(const float4*)(bb + tid * 4);
    __half2 h01 = __floats2half2_rn((xv.x - mean) * rstd * wv.x + bv.x,
                                    (xv.y - mean) * rstd * wv.y + bv.y);
    __half2 h23 = __floats2half2_rn((xv.z - mean) * rstd * wv.z + bv.z,
                                    (xv.w - mean) * rstd * wv.w + bv.w);
    __half2* o = (__half2*)(out + (size_t)row * DIM + tid * 4);
    o[0] = h01;
    o[1] = h23;
}

// ---------------- FP16 tensor-core GEMM, cp.async 3-stage ------------------
// C[M,N] = A[M,K] @ Bt[N,K]^T ; A row-major fp16, Bt row-major fp16 (= B^T).
// 4 warps, warp tile 64x64, CTA 128x128, k-step 32 (2x mma.k16 per stage).
// EPI: 0 none | 1 +R | 2 +bias,gelu -> half Ch | 3 +bias,+R
#define LDH 40   // halves per 32-k row (80 B)
#define GSTAGE 3
#define SMEM_GEMM (GSTAGE * 2 * 128 * LDH * 2)   // A+B tiles, halves->bytes

template<int EPI>
__global__ void __launch_bounds__(128) tgemm_k(const __half* __restrict__ A,
        const __half* __restrict__ Bt, float* __restrict__ C, __half* __restrict__ Ch,
        const float* __restrict__ bias, const float* __restrict__ R,
        int M, int N, int K) {
    extern __shared__ __half smh[];
    __half* AsBase = smh;                          // [GSTAGE][128*LDH]
    __half* BsBase = smh + GSTAGE * 128 * LDH;     // [GSTAGE][128*LDH]

    const int tid  = threadIdx.x;
    const int lane = tid & 31;
    const int warp = tid >> 5;
    const int wm = warp >> 1, wn = warp & 1;
    const int row0 = blockIdx.y * 128, col0 = blockIdx.x * 128;
    const int qr = lane >> 2, qc = lane & 3;

    float acc[4][8][4];
    #pragma unroll
    for (int i = 0; i < 4; i++)
        #pragma unroll
        for (int j = 0; j < 8; j++)
            #pragma unroll
            for (int q = 0; q < 4; q++) acc[i][j][q] = 0.f;

    // thread t loads A row (row0+t) and Bt row (col0+t), 4 x 16B chunks each
    auto load_stage = [&](int st, int k0) {
        __half* as = AsBase + st * 128 * LDH;
        const __half* ag = &A[(size_t)(row0 + tid) * K + k0];
        #pragma unroll
        for (int c = 0; c < 4; c++)
            cpa16(&as[tid * LDH + c * 8], ag + c * 8);
        __half* bs = BsBase + st * 128 * LDH;
        const __half* bg = &Bt[(size_t)(col0 + tid) * K + k0];
        #pragma unroll
        for (int c = 0; c < 4; c++)
            cpa16(&bs[tid * LDH + c * 8], bg + c * 8);
        cp_commit();
    };

    load_stage(0, 0);
    load_stage(1, 32);

    const int nk = K >> 5;
    for (int s = 0; s < nk; s++) {
        if (s + 1 < nk) cp_wait<1>(); else cp_wait<0>();
        __syncthreads();
        const __half* as = AsBase + (s % 3) * 128 * LDH;
        const __half* bs = BsBase + (s % 3) * 128 * LDH;
        #pragma unroll
        for (int kk = 0; kk < 32; kk += 16) {
            unsigned av[4][4], bv[8][2];
            #pragma unroll
            for (int mi = 0; mi < 4; mi++) {
                int r = wm * 64 + mi * 16 + qr;
                av[mi][0] = *(const unsigned*)(as + r * LDH + kk + 2 * qc);
                av[mi][1] = *(const unsigned*)(as + (r + 8) * LDH + kk + 2 * qc);
                av[mi][2] = *(const unsigned*)(as + r * LDH + kk + 2 * qc + 8);
                av[mi][3] = *(const unsigned*)(as + (r + 8) * LDH + kk + 2 * qc + 8);
            }
            #pragma unroll
            for (int nj = 0; nj < 8; nj++) {
                int n = wn * 64 + nj * 8 + qr;
                bv[nj][0] = *(const unsigned*)(bs + n * LDH + kk + 2 * qc);
                bv[nj][1] = *(const unsigned*)(bs + n * LDH + kk + 2 * qc + 8);
            }
            #pragma unroll
            for (int mi = 0; mi < 4; mi++)
                #pragma unroll
                for (int nj = 0; nj < 8; nj++)
                    mma_f16(acc[mi][nj], av[mi][0], av[mi][1], av[mi][2], av[mi][3],
                            bv[nj][0], bv[nj][1]);
        }
        if (s + 2 < nk) load_stage((s + 2) % 3, (s + 2) * 32);
    }

    // epilogue
    #pragma unroll
    for (int mi = 0; mi < 4; mi++) {
        const int r = row0 + wm * 64 + mi * 16 + qr;
        #pragma unroll
        for (int nj = 0; nj < 8; nj++) {
            const int cidx = col0 + wn * 64 + nj * 8 + 2 * qc;
            float v0 = acc[mi][nj][0], v1 = acc[mi][nj][1];
            float v2 = acc[mi][nj][2], v3 = acc[mi][nj][3];
            if (EPI == 2 || EPI == 3) {
                float b0 = bias[cidx], b1 = bias[cidx + 1];
                v0 += b0; v1 += b1; v2 += b0; v3 += b1;
            }
            const size_t o0 = (size_t)r * N + cidx;
            const size_t o1 = (size_t)(r + 8) * N + cidx;
            if (EPI == 2) {
                // FFN1: gelu, store half (feeds FFN2 A operand)
                *(__half2*)&Ch[o0] = __floats2half2_rn(gelu_f(v0), gelu_f(v1));
                *(__half2*)&Ch[o1] = __floats2half2_rn(gelu_f(v2), gelu_f(v3));
            } else {
                if (EPI == 1 || EPI == 3) {
                    const float2 r0 = *(const float2*)&R[o0];
                    const float2 r1 = *(const float2*)&R[o1];
                    v0 += r0.x; v1 += r0.y; v2 += r1.x; v3 += r1.y;
                }
                *(float2*)&C[o0] = make_float2(v0, v1);
                *(float2*)&C[o1] = make_float2(v2, v3);
            }
        }
    }
}

// ---------------- xPos rotary (in-place on packed QKVG) --------------------
__global__ void xpos_k(float* __restrict__ QKVG) {
    int idx = blockIdx.x * blockDim.x + threadIdx.x;  // over B*L*H*64 pairs
    if (idx >= BATCH * SEQ * HEADS * 64) return;
    int p = idx & 63;
    int h = (idx >> 6) & 7;
    int l = (idx >> 9) & (SEQ - 1);
    int b = idx >> (9 + 11);
    size_t base = ((size_t)(b * SEQ + l)) * PSTR + h * HD + 2 * p;
    float pos = (float)l;
    float bs  = (2.f * p + 0.4f * HD) / (1.4f * HD);
    float sc  = powf(bs, pos * (1.f / 512.f));
    float invf = expf(-(float)p * (logf(10000.f) / 64.f));
    float ang = pos * invf;
    float sn, cs;
    sincosf(ang, &sn, &cs);
    float* Q = QKVG;
    float* K = QKVG + 1024;
    float q0 = Q[base], q1 = Q[base + 1];
    Q[base]     = q0 * cs * sc - q1 * sn * sc;
    Q[base + 1] = q1 * cs * sc + q0 * sn * sc;
    float isc = 1.f / sc;
    float k0 = K[base], k1 = K[base + 1];
    K[base]     = k0 * cs * isc - k1 * sn * isc;
    K[base + 1] = k1 * cs * isc + k0 * sn * isc;
}

// ---------------- fused retention attention (tf32 tensor-core) -------------
// Reads Q/K/V from packed QKVG (row stride PSTR, col offsets 0/1024/2048).
#define AT_LDQ 132
#define AT_LDV 68
#define AT_LDS 68
#define ATTN_SMEM ((64*AT_LDQ*2 + 128*AT_LDV + 64*AT_LDS)*4)

__global__ void __launch_bounds__(256) attn_k(const float* __restrict__ QKVG,
                                              float* __restrict__ Y) {
    extern __shared__ float sm[];
    float* Qs = sm;                        // [64][132] tf32
    float* Ks = Qs + 64 * AT_LDQ;          // [64][132] tf32
    float* Vt = Ks + 64 * AT_LDQ;          // [128][68] tf32 (transposed: [v][m])
    float* Ss = Vt + 128 * AT_LDV;         // [64][68]  tf32
    const int tid  = threadIdx.x;
    const int lane = tid & 31;
    const int warp = tid >> 5;
    const int wm = warp >> 1;              // 0..3
    const int wn = warp & 1;               // 0..1
    const int q0 = blockIdx.x * 64;
    const int bh = blockIdx.y;
    const int b = bh >> 3, h = bh & 7;
    const float gamma = 1.f - expf(-3.4657359028f + (float)h * -0.3960840962f);
    const float lg = logf(gamma);

    const float* Qg = QKVG;
    const float* Kg = QKVG + 1024;
    const float* Vg = QKVG + 2048;

    // load Q tile (cvt to tf32)
    for (int i = tid; i < 64 * 32; i += 256) {
        int r = i >> 5, c = (i & 31) << 2;
        float4 v = *(const float4*)&Qg[((size_t)(b * SEQ + q0 + r)) * PSTR + h * HD + c];
        stcvt4(&Qs[r * AT_LDQ + c], v);
    }

    float acc2[8][4];
    #pragma unroll
    for (int j = 0; j < 8; j++) { acc2[j][0]=acc2[j][1]=acc2[j][2]=acc2[j][3]=0.f; }

    const int qr = (lane >> 2);
    const int qc = (lane & 3);

    const int nmt = (q0 >> 6) + 1;
    for (int mt = 0; mt < nmt; mt++) {
        const int m0 = mt << 6;
        __syncthreads();
        for (int i = tid; i < 64 * 32; i += 256) {
            int r = i >> 5, c = (i & 31) << 2;
            float4 v = *(const float4*)&Kg[((size_t)(b * SEQ + m0 + r)) * PSTR + h * HD + c];
            stcvt4(&Ks[r * AT_LDQ + c], v);
        }
        {
            const int mo = lane & 7;
            const int v0 = (lane >> 3) << 2;
            const int mrow = warp * 8 + mo;
            const float* vsrc = &Vg[((size_t)(b * SEQ + m0 + mrow)) * PSTR + h * HD];
            #pragma unroll
            for (int vb = 0; vb < 128; vb += 16) {
                float4 vv = *(const float4*)&vsrc[vb + v0];
                Vt[(vb + v0 + 0) * AT_LDV + mrow] = __uint_as_float(f2tf32(vv.x));
                Vt[(vb + v0 + 1) * AT_LDV + mrow] = __uint_as_float(f2tf32(vv.y));
                Vt[(vb + v0 + 2) * AT_LDV + mrow] = __uint_as_float(f2tf32(vv.z));
                Vt[(vb + v0 + 3) * AT_LDV + mrow] = __uint_as_float(f2tf32(vv.w));
            }
        }
        __syncthreads();

        // ---- S = Q K^T : warp tile 16x32, k=128 ----
        float sacc[4][4];
        #pragma unroll
        for (int nj = 0; nj < 4; nj++) { sacc[nj][0]=sacc[nj][1]=sacc[nj][2]=sacc[nj][3]=0.f; }
        #pragma unroll
        for (int k0 = 0; k0 < 128; k0 += 8) {
            const int r = wm * 16 + qr;
            const int c = k0 + qc;
            unsigned a0 = __float_as_uint(Qs[r * AT_LDQ + c]);
            unsigned a1 = __float_as_uint(Qs[(r + 8) * AT_LDQ + c]);
            unsigned a2 = __float_as_uint(Qs[r * AT_LDQ + c + 4]);
            unsigned a3 = __float_as_uint(Qs[(r + 8) * AT_LDQ + c + 4]);
            #pragma unroll
            for (int nj = 0; nj < 4; nj++) {
                const int n = wn * 32 + nj * 8 + qr;
                unsigned b0 = __float_as_uint(Ks[n * AT_LDQ + c]);
                unsigned b1 = __float_as_uint(Ks[n * AT_LDQ + c + 4]);
                mma_tf32(sacc[nj], a0, a1, a2, a3, b0, b1);
            }
        }
        {
            const int lr = wm * 16 + qr;
            const int li  = q0 + lr;
            const int li8 = li + 8;
            #pragma unroll
            for (int nj = 0; nj < 4; nj++) {
                const int lc = wn * 32 + nj * 8 + 2 * qc;
                const int mj = m0 + lc;
                float d00 = (li  >= mj    ) ? __expf(lg * (float)(li  - mj    )) : 0.f;
                float d01 = (li  >= mj + 1) ? __expf(lg * (float)(li  - mj - 1)) : 0.f;
                float d10 = (li8 >= mj    ) ? __expf(lg * (float)(li8 - mj    )) : 0.f;
                float d11 = (li8 >= mj + 1) ? __expf(lg * (float)(li8 - mj - 1)) : 0.f;
                Ss[lr * AT_LDS + lc]           = __uint_as_float(f2tf32(sacc[nj][0] * d00));
                Ss[lr * AT_LDS + lc + 1]       = __uint_as_float(f2tf32(sacc[nj][1] * d01));
                Ss[(lr + 8) * AT_LDS + lc]     = __uint_as_float(f2tf32(sacc[nj][2] * d10));
                Ss[(lr + 8) * AT_LDS + lc + 1] = __uint_as_float(f2tf32(sacc[nj][3] * d11));
            }
        }
        __syncthreads();

        // ---- Y += S @ V : warp tile 16x64, k=64 ----
        #pragma unroll
        for (int k0 = 0; k0 < 64; k0 += 8) {
            const int r = wm * 16 + qr;
            const int c = k0 + qc;
            unsigned a0 = __float_as_uint(Ss[r * AT_LDS + c]);
            unsigned a1 = __float_as_uint(Ss[(r + 8) * AT_LDS + c]);
            unsigned a2 = __float_as_uint(Ss[r * AT_LDS + c + 4]);
            unsigned a3 = __float_as_uint(Ss[(r + 8) * AT_LDS + c + 4]);
            #pragma unroll
            for (int nj = 0; nj < 8; nj++) {
                const int n = wn * 64 + nj * 8 + qr;
                unsigned b0 = __float_as_uint(Vt[n * AT_LDV + c]);
                unsigned b1 = __float_as_uint(Vt[n * AT_LDV + c + 4]);
                mma_tf32(acc2[nj], a0, a1, a2, a3, b0, b1);
            }
        }
    }

    {
        const int lr = wm * 16 + qr;
        const size_t rowbase = (size_t)((b * 8 + h) * SEQ) + q0 + lr;
        #pragma unroll
        for (int nj = 0; nj < 8; nj++) {
            const int c = wn * 64 + nj * 8 + 2 * qc;
            *(float2*)&Y[rowbase * HV + c]       = make_float2(acc2[nj][0], acc2[nj][1]);
            *(float2*)&Y[(rowbase + 8) * HV + c] = make_float2(acc2[nj][2], acc2[nj][3]);
        }
    }
}

// ---------------- per-head groupnorm + SiLU gate -> fp16 out ---------------
__global__ void __launch_bounds__(256) gn_gate_k(const float* __restrict__ Y,
        const float* __restrict__ QKVG, const float* __restrict__ gnw,
        const float* __restrict__ gnb, __half* __restrict__ out) {
    int gwarp = (blockIdx.x * blockDim.x + threadIdx.x) >> 5;   // row over B*H*L
    int lane = threadIdx.x & 31;
    if (gwarp >= BATCH * HEADS * SEQ) return;
    int b = gwarp / (HEADS * SEQ);
    int h = (gwarp / SEQ) & 7;
    int l = gwarp & (SEQ - 1);
    const float* y = Y + (size_t)gwarp * HV;
    float v0 = y[lane], v1 = y[lane + 32], v2 = y[lane + 64], v3 = y[lane + 96];
    float s  = v0 + v1 + v2 + v3;
    float ss = v0*v0 + v1*v1 + v2*v2 + v3*v3;
    #pragma unroll
    for (int o = 16; o; o >>= 1) {
        s  += __shfl_xor_sync(0xffffffffu, s,  o);
        ss += __shfl_xor_sync(0xffffffffu, ss, o);
    }
    float mean = s * (1.f / HV);
    float var  = ss * (1.f / HV) - mean * mean;
    float rstd = rsqrtf(var + EPSV);
    size_t row = (size_t)(b * SEQ + l);
    const float* Gp = QKVG + row * PSTR + 3072 + h * HV;
    size_t ob = row * VD + h * HV;
    float vv[4] = {v0, v1, v2, v3};
    #pragma unroll
    for (int i = 0; i < 4; i++) {
        int c = lane + i * 32;
        float g = Gp[c];
        float gate = g / (1.f + expf(-g));
        float r = ((vv[i] - mean) * rstd * gnw[h * HV + c] + gnb[h * HV + c]) * gate;
        out[ob + c] = __float2half_rn(r);
    }
}

// ---------------- host launcher --------------------------------------------
extern "C" void kernel_launch(void* const* d_in, const int* in_sizes, int n_in,
                              void* d_out, int out_size) {
    const float* X    = (const float*)d_in[0];
    const float* Wq   = (const float*)d_in[1];
    const float* Wk   = (const float*)d_in[2];
    const float* Wv   = (const float*)d_in[3];
    const float* W_G  = (const float*)d_in[4];
    const float* W_O  = (const float*)d_in[5];
    const float* gnw  = (const float*)d_in[6];
    const float* gnb  = (const float*)d_in[7];
    const float* ln1w = (const float*)d_in[8];
    const float* ln1b = (const float*)d_in[9];
    const float* ln2w = (const float*)d_in[10];
    const float* ln2b = (const float*)d_in[11];
    const float* fw1  = (const float*)d_in[12];
    const float* fb1  = (const float*)d_in[13];
    const float* fw2  = (const float*)d_in[14];
    const float* fb2  = (const float*)d_in[15];
    float* out = (float*)d_out;

    void* p;
    cudaGetSymbolAddress(&p, g_X);     float*  pX     = (float*)p;
    cudaGetSymbolAddress(&p, g_Y);     float*  pY     = (float*)p;
    cudaGetSymbolAddress(&p, g_Att);   float*  pAtt   = (float*)p;
    cudaGetSymbolAddress(&p, g_QKVG);  float*  pQKVG  = (float*)p;
    cudaGetSymbolAddress(&p, g_Xn);    __half* pXn    = (__half*)p;
    cudaGetSymbolAddress(&p, g_Yg);    __half* pYg    = (__half*)p;
    cudaGetSymbolAddress(&p, g_Hf);    __half* pHf    = (__half*)p;
    cudaGetSymbolAddress(&p, g_WbigT); __half* pWbigT = (__half*)p;
    cudaGetSymbolAddress(&p, g_WoT);   __half* pWoT   = (__half*)p;
    cudaGetSymbolAddress(&p, g_Wf1T);  __half* pWf1T  = (__half*)p;
    cudaGetSymbolAddress(&p, g_Wf2T);  __half* pWf2T  = (__half*)p;

    cudaFuncSetAttribute(attn_k, cudaFuncAttributeMaxDynamicSharedMemorySize, ATTN_SMEM);
    cudaFuncSetAttribute(tgemm_k<0>, cudaFuncAttributeMaxDynamicSharedMemorySize, SMEM_GEMM);
    cudaFuncSetAttribute(tgemm_k<1>, cudaFuncAttributeMaxDynamicSharedMemorySize, SMEM_GEMM);
    cudaFuncSetAttribute(tgemm_k<2>, cudaFuncAttributeMaxDynamicSharedMemorySize, SMEM_GEMM);
    cudaFuncSetAttribute(tgemm_k<3>, cudaFuncAttributeMaxDynamicSharedMemorySize, SMEM_GEMM);

    copy_k<<<(BL * DIM / 4 + 255) / 256, 256>>>(X, pX, BL * DIM / 4);

    dim3 tb(32, 8);
    dim3 gProj(PSTR / 128, BL / 128);   // 32 x 32
    dim3 gDim (DIM  / 128, BL / 128);   // 8 x 32
    dim3 gFfn (FFN  / 128, BL / 128);   // 32 x 32

    for (int i = 0; i < NLAYERS; i++) {
        size_t wofs = (size_t)i * HEADS * DIM * HD;
        // weight packs (transposed, fp16)
        pack_qkv_t_k<<<dim3(4, 32, 24), tb>>>(Wq + wofs, Wk + wofs, Wv + wofs, pWbigT);
        transpose_h_k<<<dim3(32, 32), tb>>>(W_G + (size_t)i * DIM * VD,
                                            pWbigT + (size_t)3072 * DIM, VD, DIM);
        transpose_h_k<<<dim3(32, 32), tb>>>(W_O + (size_t)i * VD * DIM, pWoT, DIM, VD);
        transpose_h_k<<<dim3(128, 32), tb>>>(fw1 + (size_t)i * DIM * FFN, pWf1T, FFN, DIM);
        transpose_h_k<<<dim3(32, 128), tb>>>(fw2 + (size_t)i * FFN * DIM, pWf2T, DIM, FFN);

        layernorm_k<<<BL, 256>>>(pX, pXn, ln1w + i * DIM, ln1b + i * DIM);

        tgemm_k<0><<<gProj, 128, SMEM_GEMM>>>(pXn, pWbigT, pQKVG, nullptr,
                                              nullptr, nullptr, BL, PSTR, DIM);

        xpos_k<<<(BATCH * SEQ * HEADS * 64 + 255) / 256, 256>>>(pQKVG);

        attn_k<<<dim3(SEQ / 64, BATCH * HEADS), 256, ATTN_SMEM>>>(pQKVG, pY);

        gn_gate_k<<<(BATCH * HEADS * SEQ) / 8, 256>>>(pY, pQKVG, gnw + i * VD,
                                                      gnb + i * VD, pYg);

        tgemm_k<1><<<gDim, 128, SMEM_GEMM>>>(pYg, pWoT, pAtt, nullptr,
                                             nullptr, pX, BL, DIM, DIM);

        layernorm_k<<<BL, 256>>>(pAtt, pXn, ln2w + i * DIM, ln2b + i * DIM);

        tgemm_k<2><<<gFfn, 128, SMEM_GEMM>>>(pXn, pWf1T, nullptr, pHf,
                                             fb1 + i * FFN, nullptr, BL, FFN, DIM);

        float* dst = (i == NLAYERS - 1) ? out : pX;
        tgemm_k<3><<<gDim, 128, SMEM_GEMM>>>(pHf, pWf2T, dst, nullptr,
                                             fb2 + i * DIM, pAtt, BL, DIM, FFN);
    }
}

// round 14
// speedup vs baseline: 6.9082x; 1.1663x over previous
#include <cuda_runtime.h>
#include <cuda_fp16.h>
#include <math.h>

#define BATCH 2
#define SEQ   2048
#define DIM   1024
#define FFN   4096
#define HEADS 8
#define HD    128
#define HV    128
#define VD    1024
#define NLAYERS 2
#define BL    (BATCH*SEQ)          // 4096
#define EPSV  1e-5f
#define PSTR  (4*DIM)              // packed QKVG row stride

// ---------------- scratch (static device globals; no allocations) ----------
__device__ float  g_X   [BL*DIM];
__device__ float  g_Y   [BL*DIM];
__device__ float  g_Att [BL*DIM];
__device__ float  g_QKVG[(size_t)BL*PSTR];
__device__ float  g_xt  [SEQ*64*4];            // xpos table: (l,p) -> qc,qs,kc,ks
__device__ __half g_Xn  [BL*DIM];
__device__ __half g_Yg  [BL*DIM];
__device__ __half g_Hf  [(size_t)BL*FFN];
__device__ __half g_WbigT[(size_t)PSTR*DIM];   // [n=4096][k=1024]
__device__ __half g_WoT [DIM*DIM];             // [n=1024][k=1024]
__device__ __half g_Wf1T[(size_t)FFN*DIM];     // [n=4096][k=1024]
__device__ __half g_Wf2T[(size_t)DIM*FFN];     // [n=1024][k=4096]

// ---------------- small helpers -------------------------------------------
__device__ __forceinline__ float gelu_f(float x) {
    return 0.5f * x * (1.0f + erff(x * 0.70710678118654752f));
}

__device__ __forceinline__ void mma_f16(float* c, unsigned a0, unsigned a1,
                                        unsigned a2, unsigned a3,
                                        unsigned b0, unsigned b1) {
    asm volatile(
        "mma.sync.aligned.m16n8k16.row.col.f32.f16.f16.f32 "
        "{%0,%1,%2,%3}, {%4,%5,%6,%7}, {%8,%9}, {%0,%1,%2,%3};"
        : "+f"(c[0]), "+f"(c[1]), "+f"(c[2]), "+f"(c[3])
        : "r"(a0), "r"(a1), "r"(a2), "r"(a3), "r"(b0), "r"(b1));
}

__device__ __forceinline__ void cpa16(void* smem, const void* g) {
    unsigned s = (unsigned)__cvta_generic_to_shared(smem);
    asm volatile("cp.async.cg.shared.global [%0], [%1], 16;" :: "r"(s), "l"(g));
}
__device__ __forceinline__ void cp_commit() {
    asm volatile("cp.async.commit_group;");
}
template<int N> __device__ __forceinline__ void cp_wait() {
    asm volatile("cp.async.wait_group %0;" :: "n"(N));
}

// ---------------- copy X -> scratch ---------------------------------------
__global__ void copy_k(const float* __restrict__ src, float* __restrict__ dst, int n4) {
    int i = blockIdx.x * blockDim.x + threadIdx.x;
    if (i < n4) ((float4*)dst)[i] = ((const float4*)src)[i];
}

// ---------------- xPos table: (l,p) -> {cos*sc, sin*sc, cos/sc, sin/sc} ----
__global__ void xpos_table_k(float* __restrict__ T) {
    int idx = blockIdx.x * blockDim.x + threadIdx.x;   // over SEQ*64
    if (idx >= SEQ * 64) return;
    int l = idx >> 6, p = idx & 63;
    float pos = (float)l;
    float bs  = (2.f * p + 0.4f * HD) / (1.4f * HD);
    float sc  = powf(bs, pos * (1.f / 512.f));
    float invf = expf(-(float)p * (logf(10000.f) / 64.f));
    float sn, cs;
    sincosf(pos * invf, &sn, &cs);
    float4 t = make_float4(cs * sc, sn * sc, cs / sc, sn / sc);
    *(float4*)&T[idx * 4] = t;
}

// ---------------- tiled transpose fp32 -> fp16 -----------------------------
__global__ void transpose_h_k(const float* __restrict__ src, __half* __restrict__ dst,
                              int sstride, int dstride) {
    __shared__ float t[32][33];
    int c0 = blockIdx.x * 32, r0 = blockIdx.y * 32;
    int tx = threadIdx.x, ty = threadIdx.y;
    #pragma unroll
    for (int i = 0; i < 32; i += 8)
        t[ty + i][tx] = src[(size_t)(r0 + ty + i) * sstride + c0 + tx];
    __syncthreads();
    #pragma unroll
    for (int i = 0; i < 32; i += 8)
        dst[(size_t)(c0 + ty + i) * dstride + r0 + tx] = __float2half_rn(t[tx][ty + i]);
}

// batched Wq/Wk/Wv head transpose -> WbigT rows [m*1024 + h*128 + e][d]
__global__ void pack_qkv_t_k(const float* __restrict__ Wq, const float* __restrict__ Wk,
                             const float* __restrict__ Wv, __half* __restrict__ dstBase) {
    __shared__ float t[32][33];
    int z = blockIdx.z;
    int m = z >> 3, h = z & 7;
    const float* src = (m == 0 ? Wq : (m == 1 ? Wk : Wv)) + (size_t)h * DIM * HD;
    __half* dst = dstBase + (size_t)(m * 1024 + h * 128) * DIM;
    int c0 = blockIdx.x * 32, r0 = blockIdx.y * 32;   // c over e(128), r over d(1024)
    int tx = threadIdx.x, ty = threadIdx.y;
    #pragma unroll
    for (int i = 0; i < 32; i += 8)
        t[ty + i][tx] = src[(size_t)(r0 + ty + i) * HD + c0 + tx];
    __syncthreads();
    #pragma unroll
    for (int i = 0; i < 32; i += 8)
        dst[(size_t)(c0 + ty + i) * DIM + r0 + tx] = __float2half_rn(t[tx][ty + i]);
}

// ---------------- layernorm over 1024 -> fp16 out --------------------------
__global__ void __launch_bounds__(256) layernorm_k(const float* __restrict__ in,
        __half* __restrict__ out, const float* __restrict__ w, const float* __restrict__ bb) {
    int row = blockIdx.x, tid = threadIdx.x;
    const float4 xv = *(const float4*)(in + (size_t)row * DIM + tid * 4);
    float s  = xv.x + xv.y + xv.z + xv.w;
    float ss = xv.x*xv.x + xv.y*xv.y + xv.z*xv.z + xv.w*xv.w;
    #pragma unroll
    for (int o = 16; o; o >>= 1) {
        s  += __shfl_xor_sync(0xffffffffu, s,  o);
        ss += __shfl_xor_sync(0xffffffffu, ss, o);
    }
    __shared__ float sw[8], ssw[8], stat[2];
    int wid = tid >> 5, lane = tid & 31;
    if (!lane) { sw[wid] = s; ssw[wid] = ss; }
    __syncthreads();
    if (tid == 0) {
        float S = 0.f, SS = 0.f;
        #pragma unroll
        for (int i = 0; i < 8; i++) { S += sw[i]; SS += ssw[i]; }
        float mean = S * (1.f / DIM);
        float var  = SS * (1.f / DIM) - mean * mean;
        stat[0] = mean;
        stat[1] = rsqrtf(var + EPSV);
    }
    __syncthreads();
    float mean = stat[0], rstd = stat[1];
    const float4 wv = *(const float4*)(w  + tid * 4);
    const float4 bv = *(const float4*)(bb + tid * 4);
    __half2 h01 = __floats2half2_rn((xv.x - mean) * rstd * wv.x + bv.x,
                                    (xv.y - mean) * rstd * wv.y + bv.y);
    __half2 h23 = __floats2half2_rn((xv.z - mean) * rstd * wv.z + bv.z,
                                    (xv.w - mean) * rstd * wv.w + bv.w);
    __half2* o = (__half2*)(out + (size_t)row * DIM + tid * 4);
    o[0] = h01;
    o[1] = h23;
}

// ---------------- FP16 tensor-core GEMM, cp.async 3-stage ------------------
// C[M,N] = A[M,K] @ Bt[N,K]^T ; 4 warps, warp tile 64x64, CTA 128x128, k-step 32.
// EPI: 0 none | 1 +R | 2 +bias,gelu -> half Ch | 3 +bias,+R
#define LDH 40   // halves per 32-k row (80 B)
#define GSTAGE 3
#define SMEM_GEMM (GSTAGE * 2 * 128 * LDH * 2)

template<int EPI>
__global__ void __launch_bounds__(128) tgemm_k(const __half* __restrict__ A,
        const __half* __restrict__ Bt, float* __restrict__ C, __half* __restrict__ Ch,
        const float* __restrict__ bias, const float* __restrict__ R,
        int M, int N, int K) {
    extern __shared__ __half smh[];
    __half* AsBase = smh;
    __half* BsBase = smh + GSTAGE * 128 * LDH;

    const int tid  = threadIdx.x;
    const int lane = tid & 31;
    const int warp = tid >> 5;
    const int wm = warp >> 1, wn = warp & 1;
    const int row0 = blockIdx.y * 128, col0 = blockIdx.x * 128;
    const int qr = lane >> 2, qc = lane & 3;

    float acc[4][8][4];
    #pragma unroll
    for (int i = 0; i < 4; i++)
        #pragma unroll
        for (int j = 0; j < 8; j++)
            #pragma unroll
            for (int q = 0; q < 4; q++) acc[i][j][q] = 0.f;

    auto load_stage = [&](int st, int k0) {
        __half* as = AsBase + st * 128 * LDH;
        const __half* ag = &A[(size_t)(row0 + tid) * K + k0];
        #pragma unroll
        for (int c = 0; c < 4; c++)
            cpa16(&as[tid * LDH + c * 8], ag + c * 8);
        __half* bs = BsBase + st * 128 * LDH;
        const __half* bg = &Bt[(size_t)(col0 + tid) * K + k0];
        #pragma unroll
        for (int c = 0; c < 4; c++)
            cpa16(&bs[tid * LDH + c * 8], bg + c * 8);
        cp_commit();
    };

    load_stage(0, 0);
    load_stage(1, 32);

    const int nk = K >> 5;
    for (int s = 0; s < nk; s++) {
        if (s + 1 < nk) cp_wait<1>(); else cp_wait<0>();
        __syncthreads();
        const __half* as = AsBase + (s % 3) * 128 * LDH;
        const __half* bs = BsBase + (s % 3) * 128 * LDH;
        #pragma unroll
        for (int kk = 0; kk < 32; kk += 16) {
            unsigned av[4][4], bv[8][2];
            #pragma unroll
            for (int mi = 0; mi < 4; mi++) {
                int r = wm * 64 + mi * 16 + qr;
                av[mi][0] = *(const unsigned*)(as + r * LDH + kk + 2 * qc);
                av[mi][1] = *(const unsigned*)(as + (r + 8) * LDH + kk + 2 * qc);
                av[mi][2] = *(const unsigned*)(as + r * LDH + kk + 2 * qc + 8);
                av[mi][3] = *(const unsigned*)(as + (r + 8) * LDH + kk + 2 * qc + 8);
            }
            #pragma unroll
            for (int nj = 0; nj < 8; nj++) {
                int n = wn * 64 + nj * 8 + qr;
                bv[nj][0] = *(const unsigned*)(bs + n * LDH + kk + 2 * qc);
                bv[nj][1] = *(const unsigned*)(bs + n * LDH + kk + 2 * qc + 8);
            }
            #pragma unroll
            for (int mi = 0; mi < 4; mi++)
                #pragma unroll
                for (int nj = 0; nj < 8; nj++)
                    mma_f16(acc[mi][nj], av[mi][0], av[mi][1], av[mi][2], av[mi][3],
                            bv[nj][0], bv[nj][1]);
        }
        if (s + 2 < nk) load_stage((s + 2) % 3, (s + 2) * 32);
    }

    #pragma unroll
    for (int mi = 0; mi < 4; mi++) {
        const int r = row0 + wm * 64 + mi * 16 + qr;
        #pragma unroll
        for (int nj = 0; nj < 8; nj++) {
            const int cidx = col0 + wn * 64 + nj * 8 + 2 * qc;
            float v0 = acc[mi][nj][0], v1 = acc[mi][nj][1];
            float v2 = acc[mi][nj][2], v3 = acc[mi][nj][3];
            if (EPI == 2 || EPI == 3) {
                float b0 = bias[cidx], b1 = bias[cidx + 1];
                v0 += b0; v1 += b1; v2 += b0; v3 += b1;
            }
            const size_t o0 = (size_t)r * N + cidx;
            const size_t o1 = (size_t)(r + 8) * N + cidx;
            if (EPI == 2) {
                *(__half2*)&Ch[o0] = __floats2half2_rn(gelu_f(v0), gelu_f(v1));
                *(__half2*)&Ch[o1] = __floats2half2_rn(gelu_f(v2), gelu_f(v3));
            } else {
                if (EPI == 1 || EPI == 3) {
                    const float2 r0 = *(const float2*)&R[o0];
                    const float2 r1 = *(const float2*)&R[o1];
                    v0 += r0.x; v1 += r0.y; v2 += r1.x; v3 += r1.y;
                }
                *(float2*)&C[o0] = make_float2(v0, v1);
                *(float2*)&C[o1] = make_float2(v2, v3);
            }
        }
    }
}

// ---------------- xPos rotary (table-driven, in-place on packed QKVG) ------
__global__ void xpos_k(float* __restrict__ QKVG, const float* __restrict__ T) {
    int idx = blockIdx.x * blockDim.x + threadIdx.x;  // over B*L*H*64 pairs
    if (idx >= BATCH * SEQ * HEADS * 64) return;
    int p = idx & 63;
    int h = (idx >> 6) & 7;
    int l = (idx >> 9) & (SEQ - 1);
    int b = idx >> (9 + 11);
    size_t base = ((size_t)(b * SEQ + l)) * PSTR + h * HD + 2 * p;
    float4 t = *(const float4*)&T[(l * 64 + p) * 4];
    float* Q = QKVG;
    float* K = QKVG + 1024;
    float q0 = Q[base], q1 = Q[base + 1];
    Q[base]     = q0 * t.x - q1 * t.y;
    Q[base + 1] = q1 * t.x + q0 * t.y;
    float k0 = K[base], k1 = K[base + 1];
    K[base]     = k0 * t.z - k1 * t.w;
    K[base + 1] = k1 * t.z + k0 * t.w;
}

// ---------------- fused retention attention (FP16 tensor-core) -------------
// Reads Q/K/V from packed QKVG (row stride PSTR, col offsets 0/1024/2048).
// 8 warps: wm = warp>>1 (16 q-rows), wn = warp&1.
#define AT_LDQH 136   // halves per Q/K row (k=128 + 8 pad); word stride 68 == 4 mod 32
#define AT_LDVH 72    // halves per Vt row (m=64 + 8 pad); word stride 36 == 4 mod 32
#define AT_LDSH 72    // halves per Ss row
#define ATTN_SMEM ((64*AT_LDQH*2 + 128*AT_LDVH + 64*AT_LDSH) * 2)

__global__ void __launch_bounds__(256) attn_k(const float* __restrict__ QKVG,
                                              float* __restrict__ Y) {
    extern __shared__ __half sma[];
    __half* Qs = sma;                        // [64][136]
    __half* Ks = Qs + 64 * AT_LDQH;          // [64][136]
    __half* Vt = Ks + 64 * AT_LDQH;          // [128][72] transposed [v][m]
    __half* Ss = Vt + 128 * AT_LDVH;         // [64][72]
    const int tid  = threadIdx.x;
    const int lane = tid & 31;
    const int warp = tid >> 5;
    const int wm = warp >> 1;                // 0..3
    const int wn = warp & 1;                 // 0..1
    const int q0 = blockIdx.x * 64;
    const int bh = blockIdx.y;
    const int b = bh >> 3, h = bh & 7;
    const float gamma = 1.f - expf(-3.4657359028f + (float)h * -0.3960840962f);
    const float lg = logf(gamma);

    const float* Qg = QKVG;
    const float* Kg = QKVG + 1024;
    const float* Vg = QKVG + 2048;

    // load Q tile -> fp16
    for (int i = tid; i < 64 * 32; i += 256) {
        int r = i >> 5, c = (i & 31) << 2;
        float4 v = *(const float4*)&Qg[((size_t)(b * SEQ + q0 + r)) * PSTR + h * HD + c];
        __half2* d = (__half2*)&Qs[r * AT_LDQH + c];
        d[0] = __floats2half2_rn(v.x, v.y);
        d[1] = __floats2half2_rn(v.z, v.w);
    }

    float acc2[8][4];
    #pragma unroll
    for (int j = 0; j < 8; j++) { acc2[j][0]=acc2[j][1]=acc2[j][2]=acc2[j][3]=0.f; }

    const int qr = (lane >> 2);
    const int qc = (lane & 3);

    const int nmt = (q0 >> 6) + 1;
    for (int mt = 0; mt < nmt; mt++) {
        const int m0 = mt << 6;
        __syncthreads();
        // K tile -> fp16
        for (int i = tid; i < 64 * 32; i += 256) {
            int r = i >> 5, c = (i & 31) << 2;
            float4 v = *(const float4*)&Kg[((size_t)(b * SEQ + m0 + r)) * PSTR + h * HD + c];
            __half2* d = (__half2*)&Ks[r * AT_LDQH + c];
            d[0] = __floats2half2_rn(v.x, v.y);
            d[1] = __floats2half2_rn(v.z, v.w);
        }
        // V tile transposed -> fp16: Vt[v][m]
        {
            const int mo = lane & 7;
            const int v0 = (lane >> 3) << 2;
            const int mrow = warp * 8 + mo;
            const float* vsrc = &Vg[((size_t)(b * SEQ + m0 + mrow)) * PSTR + h * HD];
            #pragma unroll
            for (int vb = 0; vb < 128; vb += 16) {
                float4 vv = *(const float4*)&vsrc[vb + v0];
                Vt[(vb + v0 + 0) * AT_LDVH + mrow] = __float2half_rn(vv.x);
                Vt[(vb + v0 + 1) * AT_LDVH + mrow] = __float2half_rn(vv.y);
                Vt[(vb + v0 + 2) * AT_LDVH + mrow] = __float2half_rn(vv.z);
                Vt[(vb + v0 + 3) * AT_LDVH + mrow] = __float2half_rn(vv.w);
            }
        }
        __syncthreads();

        // ---- S = Q K^T : warp tile 16x32, k=128, mma.k16 ----
        float sacc[4][4];
        #pragma unroll
        for (int nj = 0; nj < 4; nj++) { sacc[nj][0]=sacc[nj][1]=sacc[nj][2]=sacc[nj][3]=0.f; }
        #pragma unroll
        for (int k0 = 0; k0 < 128; k0 += 16) {
            const int r = wm * 16 + qr;
            const __half* qrow = Qs + r * AT_LDQH + k0 + 2 * qc;
            unsigned a0 = *(const unsigned*)(qrow);
            unsigned a1 = *(const unsigned*)(qrow + 8 * AT_LDQH);
            unsigned a2 = *(const unsigned*)(qrow + 8);
            unsigned a3 = *(const unsigned*)(qrow + 8 * AT_LDQH + 8);
            #pragma unroll
            for (int nj = 0; nj < 4; nj++) {
                const int n = wn * 32 + nj * 8 + qr;
                const __half* krow = Ks + n * AT_LDQH + k0 + 2 * qc;
                unsigned b0 = *(const unsigned*)(krow);
                unsigned b1 = *(const unsigned*)(krow + 8);
                mma_f16(sacc[nj], a0, a1, a2, a3, b0, b1);
            }
        }
        // decay + causal mask on fragments -> Ss (fp16)
        {
            const int lr = wm * 16 + qr;
            const int li  = q0 + lr;
            const int li8 = li + 8;
            #pragma unroll
            for (int nj = 0; nj < 4; nj++) {
                const int lc = wn * 32 + nj * 8 + 2 * qc;
                const int mj = m0 + lc;
                float d00 = (li  >= mj    ) ? __expf(lg * (float)(li  - mj    )) : 0.f;
                float d01 = (li  >= mj + 1) ? __expf(lg * (float)(li  - mj - 1)) : 0.f;
                float d10 = (li8 >= mj    ) ? __expf(lg * (float)(li8 - mj    )) : 0.f;
                float d11 = (li8 >= mj + 1) ? __expf(lg * (float)(li8 - mj - 1)) : 0.f;
                *(__half2*)&Ss[lr * AT_LDSH + lc] =
                    __floats2half2_rn(sacc[nj][0] * d00, sacc[nj][1] * d01);
                *(__half2*)&Ss[(lr + 8) * AT_LDSH + lc] =
                    __floats2half2_rn(sacc[nj][2] * d10, sacc[nj][3] * d11);
            }
        }
        __syncthreads();

        // ---- Y += S @ V : warp tile 16x64, k=64, mma.k16 ----
        #pragma unroll
        for (int k0 = 0; k0 < 64; k0 += 16) {
            const int r = wm * 16 + qr;
            const __half* srow = Ss + r * AT_LDSH + k0 + 2 * qc;
            unsigned a0 = *(const unsigned*)(srow);
            unsigned a1 = *(const unsigned*)(srow + 8 * AT_LDSH);
            unsigned a2 = *(const unsigned*)(srow + 8);
            unsigned a3 = *(const unsigned*)(srow + 8 * AT_LDSH + 8);
            #pragma unroll
            for (int nj = 0; nj < 8; nj++) {
                const int n = wn * 64 + nj * 8 + qr;
                const __half* vrow = Vt + n * AT_LDVH + k0 + 2 * qc;
                unsigned b0 = *(const unsigned*)(vrow);
                unsigned b1 = *(const unsigned*)(vrow + 8);
                mma_f16(acc2[nj], a0, a1, a2, a3, b0, b1);
            }
        }
    }

    {
        const int lr = wm * 16 + qr;
        const size_t rowbase = (size_t)((b * 8 + h) * SEQ) + q0 + lr;
        #pragma unroll
        for (int nj = 0; nj < 8; nj++) {
            const int c = wn * 64 + nj * 8 + 2 * qc;
            *(float2*)&Y[rowbase * HV + c]       = make_float2(acc2[nj][0], acc2[nj][1]);
            *(float2*)&Y[(rowbase + 8) * HV + c] = make_float2(acc2[nj][2], acc2[nj][3]);
        }
    }
}

// ---------------- per-head groupnorm + SiLU gate -> fp16 out ---------------
__global__ void __launch_bounds__(256) gn_gate_k(const float* __restrict__ Y,
        const float* __restrict__ QKVG, const float* __restrict__ gnw,
        const float* __restrict__ gnb, __half* __restrict__ out) {
    int gwarp = (blockIdx.x * blockDim.x + threadIdx.x) >> 5;   // row over B*H*L
    int lane = threadIdx.x & 31;
    if (gwarp >= BATCH * HEADS * SEQ) return;
    int b = gwarp / (HEADS * SEQ);
    int h = (gwarp / SEQ) & 7;
    int l = gwarp & (SEQ - 1);
    const float* y = Y + (size_t)gwarp * HV;
    float v0 = y[lane], v1 = y[lane + 32], v2 = y[lane + 64], v3 = y[lane + 96];
    float s  = v0 + v1 + v2 + v3;
    float ss = v0*v0 + v1*v1 + v2*v2 + v3*v3;
    #pragma unroll
    for (int o = 16; o; o >>= 1) {
        s  += __shfl_xor_sync(0xffffffffu, s,  o);
        ss += __shfl_xor_sync(0xffffffffu, ss, o);
    }
    float mean = s * (1.f / HV);
    float var  = ss * (1.f / HV) - mean * mean;
    float rstd = rsqrtf(var + EPSV);
    size_t row = (size_t)(b * SEQ + l);
    const float* Gp = QKVG + row * PSTR + 3072 + h * HV;
    size_t ob = row * VD + h * HV;
    float vv[4] = {v0, v1, v2, v3};
    #pragma unroll
    for (int i = 0; i < 4; i++) {
        int c = lane + i * 32;
        float g = Gp[c];
        float gate = g / (1.f + expf(-g));
        float r = ((vv[i] - mean) * rstd * gnw[h * HV + c] + gnb[h * HV + c]) * gate;
        out[ob + c] = __float2half_rn(r);
    }
}

// ---------------- host launcher --------------------------------------------
extern "C" void kernel_launch(void* const* d_in, const int* in_sizes, int n_in,
                              void* d_out, int out_size) {
    const float* X    = (const float*)d_in[0];
    const float* Wq   = (const float*)d_in[1];
    const float* Wk   = (const float*)d_in[2];
    const float* Wv   = (const float*)d_in[3];
    const float* W_G  = (const float*)d_in[4];
    const float* W_O  = (const float*)d_in[5];
    const float* gnw  = (const float*)d_in[6];
    const float* gnb  = (const float*)d_in[7];
    const float* ln1w = (const float*)d_in[8];
    const float* ln1b = (const float*)d_in[9];
    const float* ln2w = (const float*)d_in[10];
    const float* ln2b = (const float*)d_in[11];
    const float* fw1  = (const float*)d_in[12];
    const float* fb1  = (const float*)d_in[13];
    const float* fw2  = (const float*)d_in[14];
    const float* fb2  = (const float*)d_in[15];
    float* out = (float*)d_out;

    void* p;
    cudaGetSymbolAddress(&p, g_X);     float*  pX     = (float*)p;
    cudaGetSymbolAddress(&p, g_Y);     float*  pY     = (float*)p;
    cudaGetSymbolAddress(&p, g_Att);   float*  pAtt   = (float*)p;
    cudaGetSymbolAddress(&p, g_QKVG);  float*  pQKVG  = (float*)p;
    cudaGetSymbolAddress(&p, g_xt);    float*  pXT    = (float*)p;
    cudaGetSymbolAddress(&p, g_Xn);    __half* pXn    = (__half*)p;
    cudaGetSymbolAddress(&p, g_Yg);    __half* pYg    = (__half*)p;
    cudaGetSymbolAddress(&p, g_Hf);    __half* pHf    = (__half*)p;
    cudaGetSymbolAddress(&p, g_WbigT); __half* pWbigT = (__half*)p;
    cudaGetSymbolAddress(&p, g_WoT);   __half* pWoT   = (__half*)p;
    cudaGetSymbolAddress(&p, g_Wf1T);  __half* pWf1T  = (__half*)p;
    cudaGetSymbolAddress(&p, g_Wf2T);  __half* pWf2T  = (__half*)p;

    cudaFuncSetAttribute(attn_k, cudaFuncAttributeMaxDynamicSharedMemorySize, ATTN_SMEM);
    cudaFuncSetAttribute(tgemm_k<0>, cudaFuncAttributeMaxDynamicSharedMemorySize, SMEM_GEMM);
    cudaFuncSetAttribute(tgemm_k<1>, cudaFuncAttributeMaxDynamicSharedMemorySize, SMEM_GEMM);
    cudaFuncSetAttribute(tgemm_k<2>, cudaFuncAttributeMaxDynamicSharedMemorySize, SMEM_GEMM);
    cudaFuncSetAttribute(tgemm_k<3>, cudaFuncAttributeMaxDynamicSharedMemorySize, SMEM_GEMM);

    copy_k<<<(BL * DIM / 4 + 255) / 256, 256>>>(X, pX, BL * DIM / 4);
    xpos_table_k<<<(SEQ * 64 + 255) / 256, 256>>>(pXT);

    dim3 tb(32, 8);
    dim3 gProj(PSTR / 128, BL / 128);   // 32 x 32
    dim3 gDim (DIM  / 128, BL / 128);   // 8 x 32
    dim3 gFfn (FFN  / 128, BL / 128);   // 32 x 32

    for (int i = 0; i < NLAYERS; i++) {
        size_t wofs = (size_t)i * HEADS * DIM * HD;
        pack_qkv_t_k<<<dim3(4, 32, 24), tb>>>(Wq + wofs, Wk + wofs, Wv + wofs, pWbigT);
        transpose_h_k<<<dim3(32, 32), tb>>>(W_G + (size_t)i * DIM * VD,
                                            pWbigT + (size_t)3072 * DIM, VD, DIM);
        transpose_h_k<<<dim3(32, 32), tb>>>(W_O + (size_t)i * VD * DIM, pWoT, DIM, VD);
        transpose_h_k<<<dim3(128, 32), tb>>>(fw1 + (size_t)i * DIM * FFN, pWf1T, FFN, DIM);
        transpose_h_k<<<dim3(32, 128), tb>>>(fw2 + (size_t)i * FFN * DIM, pWf2T, DIM, FFN);

        layernorm_k<<<BL, 256>>>(pX, pXn, ln1w + i * DIM, ln1b + i * DIM);

        tgemm_k<0><<<gProj, 128, SMEM_GEMM>>>(pXn, pWbigT, pQKVG, nullptr,
                                              nullptr, nullptr, BL, PSTR, DIM);

        xpos_k<<<(BATCH * SEQ * HEADS * 64 + 255) / 256, 256>>>(pQKVG, pXT);

        attn_k<<<dim3(SEQ / 64, BATCH * HEADS), 256, ATTN_SMEM>>>(pQKVG, pY);

        gn_gate_k<<<(BATCH * HEADS * SEQ) / 8, 256>>>(pY, pQKVG, gnw + i * VD,
                                                      gnb + i * VD, pYg);

        tgemm_k<1><<<gDim, 128, SMEM_GEMM>>>(pYg, pWoT, pAtt, nullptr,
                                             nullptr, pX, BL, DIM, DIM);

        layernorm_k<<<BL, 256>>>(pAtt, pXn, ln2w + i * DIM, ln2b + i * DIM);

        tgemm_k<2><<<gFfn, 128, SMEM_GEMM>>>(pXn, pWf1T, nullptr, pHf,
                                             fb1 + i * FFN, nullptr, BL, FFN, DIM);

        float* dst = (i == NLAYERS - 1) ? out : pX;
        tgemm_k<3><<<gDim, 128, SMEM_GEMM>>>(pHf, pWf2T, dst, nullptr,
                                             fb2 + i * DIM, pAtt, BL, DIM, FFN);
    }
}

// round 15
// speedup vs baseline: 7.0591x; 1.0218x over previous
#include <cuda_runtime.h>
#include <cuda_fp16.h>
#include <math.h>

#define BATCH 2
#define SEQ   2048
#define DIM   1024
#define FFN   4096
#define HEADS 8
#define HD    128
#define HV    128
#define VD    1024
#define NLAYERS 2
#define BL    (BATCH*SEQ)          // 4096
#define EPSV  1e-5f
#define PSTR  (4*DIM)              // packed QKVG row stride

// ---------------- scratch (static device globals; no allocations) ----------
__device__ float  g_X   [BL*DIM];
__device__ float  g_Y   [BL*DIM];
__device__ float  g_Att [BL*DIM];
__device__ float  g_QKVG[(size_t)BL*PSTR];
__device__ float  g_xt  [SEQ*64*4];            // xpos table: (l,p) -> qc,qs,kc,ks
__device__ __half g_Xn  [BL*DIM];
__device__ __half g_Yg  [BL*DIM];
__device__ __half g_Hf  [(size_t)BL*FFN];
__device__ __half g_WbigT[(size_t)PSTR*DIM];   // [n=4096][k=1024]
__device__ __half g_WoT [DIM*DIM];             // [n=1024][k=1024]
__device__ __half g_Wf1T[(size_t)FFN*DIM];     // [n=4096][k=1024]
__device__ __half g_Wf2T[(size_t)DIM*FFN];     // [n=1024][k=4096]

// ---------------- small helpers -------------------------------------------
__device__ __forceinline__ float gelu_f(float x) {
    return 0.5f * x * (1.0f + erff(x * 0.70710678118654752f));
}

__device__ __forceinline__ void mma_f16(float* c, unsigned a0, unsigned a1,
                                        unsigned a2, unsigned a3,
                                        unsigned b0, unsigned b1) {
    asm volatile(
        "mma.sync.aligned.m16n8k16.row.col.f32.f16.f16.f32 "
        "{%0,%1,%2,%3}, {%4,%5,%6,%7}, {%8,%9}, {%0,%1,%2,%3};"
        : "+f"(c[0]), "+f"(c[1]), "+f"(c[2]), "+f"(c[3])
        : "r"(a0), "r"(a1), "r"(a2), "r"(a3), "r"(b0), "r"(b1));
}

__device__ __forceinline__ void ldsm_x4(unsigned& r0, unsigned& r1,
                                        unsigned& r2, unsigned& r3, unsigned addr) {
    asm volatile("ldmatrix.sync.aligned.m8n8.x4.shared.b16 {%0,%1,%2,%3}, [%4];"
        : "=r"(r0), "=r"(r1), "=r"(r2), "=r"(r3) : "r"(addr));
}

__device__ __forceinline__ void cpa16(void* smem, const void* g) {
    unsigned s = (unsigned)__cvta_generic_to_shared(smem);
    asm volatile("cp.async.cg.shared.global [%0], [%1], 16;" :: "r"(s), "l"(g));
}
__device__ __forceinline__ void cp_commit() {
    asm volatile("cp.async.commit_group;");
}
template<int N> __device__ __forceinline__ void cp_wait() {
    asm volatile("cp.async.wait_group %0;" :: "n"(N));
}

// ---------------- copy X -> scratch ---------------------------------------
__global__ void copy_k(const float* __restrict__ src, float* __restrict__ dst, int n4) {
    int i = blockIdx.x * blockDim.x + threadIdx.x;
    if (i < n4) ((float4*)dst)[i] = ((const float4*)src)[i];
}

// ---------------- xPos table: (l,p) -> {cos*sc, sin*sc, cos/sc, sin/sc} ----
__global__ void xpos_table_k(float* __restrict__ T) {
    int idx = blockIdx.x * blockDim.x + threadIdx.x;   // over SEQ*64
    if (idx >= SEQ * 64) return;
    int l = idx >> 6, p = idx & 63;
    float pos = (float)l;
    float bs  = (2.f * p + 0.4f * HD) / (1.4f * HD);
    float sc  = powf(bs, pos * (1.f / 512.f));
    float invf = expf(-(float)p * (logf(10000.f) / 64.f));
    float sn, cs;
    sincosf(pos * invf, &sn, &cs);
    float4 t = make_float4(cs * sc, sn * sc, cs / sc, sn / sc);
    *(float4*)&T[idx * 4] = t;
}

// ---------------- tiled transpose fp32 -> fp16 -----------------------------
__global__ void transpose_h_k(const float* __restrict__ src, __half* __restrict__ dst,
                              int sstride, int dstride) {
    __shared__ float t[32][33];
    int c0 = blockIdx.x * 32, r0 = blockIdx.y * 32;
    int tx = threadIdx.x, ty = threadIdx.y;
    #pragma unroll
    for (int i = 0; i < 32; i += 8)
        t[ty + i][tx] = src[(size_t)(r0 + ty + i) * sstride + c0 + tx];
    __syncthreads();
    #pragma unroll
    for (int i = 0; i < 32; i += 8)
        dst[(size_t)(c0 + ty + i) * dstride + r0 + tx] = __float2half_rn(t[tx][ty + i]);
}

// batched Wq/Wk/Wv head transpose -> WbigT rows [m*1024 + h*128 + e][d]
__global__ void pack_qkv_t_k(const float* __restrict__ Wq, const float* __restrict__ Wk,
                             const float* __restrict__ Wv, __half* __restrict__ dstBase) {
    __shared__ float t[32][33];
    int z = blockIdx.z;
    int m = z >> 3, h = z & 7;
    const float* src = (m == 0 ? Wq : (m == 1 ? Wk : Wv)) + (size_t)h * DIM * HD;
    __half* dst = dstBase + (size_t)(m * 1024 + h * 128) * DIM;
    int c0 = blockIdx.x * 32, r0 = blockIdx.y * 32;   // c over e(128), r over d(1024)
    int tx = threadIdx.x, ty = threadIdx.y;
    #pragma unroll
    for (int i = 0; i < 32; i += 8)
        t[ty + i][tx] = src[(size_t)(r0 + ty + i) * HD + c0 + tx];
    __syncthreads();
    #pragma unroll
    for (int i = 0; i < 32; i += 8)
        dst[(size_t)(c0 + ty + i) * DIM + r0 + tx] = __float2half_rn(t[tx][ty + i]);
}

// ---------------- layernorm over 1024 -> fp16 out --------------------------
__global__ void __launch_bounds__(256) layernorm_k(const float* __restrict__ in,
        __half* __restrict__ out, const float* __restrict__ w, const float* __restrict__ bb) {
    int row = blockIdx.x, tid = threadIdx.x;
    const float4 xv = *(const float4*)(in + (size_t)row * DIM + tid * 4);
    float s  = xv.x + xv.y + xv.z + xv.w;
    float ss = xv.x*xv.x + xv.y*xv.y + xv.z*xv.z + xv.w*xv.w;
    #pragma unroll
    for (int o = 16; o; o >>= 1) {
        s  += __shfl_xor_sync(0xffffffffu, s,  o);
        ss += __shfl_xor_sync(0xffffffffu, ss, o);
    }
    __shared__ float sw[8], ssw[8], stat[2];
    int wid = tid >> 5, lane = tid & 31;
    if (!lane) { sw[wid] = s; ssw[wid] = ss; }
    __syncthreads();
    if (tid == 0) {
        float S = 0.f, SS = 0.f;
        #pragma unroll
        for (int i = 0; i < 8; i++) { S += sw[i]; SS += ssw[i]; }
        float mean = S * (1.f / DIM);
        float var  = SS * (1.f / DIM) - mean * mean;
        stat[0] = mean;
        stat[1] = rsqrtf(var + EPSV);
    }
    __syncthreads();
    float mean = stat[0], rstd = stat[1];
    const float4 wv = *(const float4*)(w  + tid * 4);
    const float4 bv = *(const float4*)(bb + tid * 4);
    __half2 h01 = __floats2half2_rn((xv.x - mean) * rstd * wv.x + bv.x,
                                    (xv.y - mean) * rstd * wv.y + bv.y);
    __half2 h23 = __floats2half2_rn((xv.z - mean) * rstd * wv.z + bv.z,
                                    (xv.w - mean) * rstd * wv.w + bv.w);
    __half2* o = (__half2*)(out + (size_t)row * DIM + tid * 4);
    o[0] = h01;
    o[1] = h23;
}

// ---------------- FP16 tensor-core GEMM, cp.async 3-stage + ldmatrix -------
// C[M,N] = A[M,K] @ Bt[N,K]^T ; 4 warps, warp tile 64x64, CTA 128x128, k-step 32.
// EPI: 0 none | 1 +R | 2 +bias,gelu -> half Ch | 3 +bias,+R
#define LDH 40   // halves per 32-k row (80 B); 8-row ldmatrix groups cover all 32 banks
#define GSTAGE 3
#define SMEM_GEMM (GSTAGE * 2 * 128 * LDH * 2)

template<int EPI>
__global__ void __launch_bounds__(128) tgemm_k(const __half* __restrict__ A,
        const __half* __restrict__ Bt, float* __restrict__ C, __half* __restrict__ Ch,
        const float* __restrict__ bias, const float* __restrict__ R,
        int M, int N, int K) {
    extern __shared__ __half smh[];

    const int tid  = threadIdx.x;
    const int lane = tid & 31;
    const int warp = tid >> 5;
    const int wm = warp >> 1, wn = warp & 1;
    const int row0 = blockIdx.y * 128, col0 = blockIdx.x * 128;
    const int qr = lane >> 2, qc = lane & 3;

    const unsigned smbase = (unsigned)__cvta_generic_to_shared(smh);
    // ldmatrix lane->address mapping (x4 = 4 8x8 tiles; lanes 8t..8t+7 give tile t rows)
    const int l8  = lane & 7;
    const int t01 = (lane >> 3) & 1;
    const int t23 = (lane >> 4) & 1;
    // A tiles: t0 (r,k) t1 (r+8,k) t2 (r,k+8) t3 (r+8,k+8)
    const unsigned aoff = ((wm * 64 + t01 * 8 + l8) * LDH + t23 * 8) * 2;
    // B tiles: t0 (n,k) t1 (n,k+8) t2 (n+8,k) t3 (n+8,k+8)
    const unsigned boff = ((wn * 64 + t23 * 8 + l8) * LDH + t01 * 8) * 2;

    float acc[4][8][4];
    #pragma unroll
    for (int i = 0; i < 4; i++)
        #pragma unroll
        for (int j = 0; j < 8; j++)
            #pragma unroll
            for (int q = 0; q < 4; q++) acc[i][j][q] = 0.f;

    __half* AsBase = smh;
    __half* BsBase = smh + GSTAGE * 128 * LDH;

    auto load_stage = [&](int st, int k0) {
        __half* as = AsBase + st * 128 * LDH;
        const __half* ag = &A[(size_t)(row0 + tid) * K + k0];
        #pragma unroll
        for (int c = 0; c < 4; c++)
            cpa16(&as[tid * LDH + c * 8], ag + c * 8);
        __half* bs = BsBase + st * 128 * LDH;
        const __half* bg = &Bt[(size_t)(col0 + tid) * K + k0];
        #pragma unroll
        for (int c = 0; c < 4; c++)
            cpa16(&bs[tid * LDH + c * 8], bg + c * 8);
        cp_commit();
    };

    load_stage(0, 0);
    load_stage(1, 32);

    const int nk = K >> 5;
    for (int s = 0; s < nk; s++) {
        if (s + 1 < nk) cp_wait<1>(); else cp_wait<0>();
        __syncthreads();
        const unsigned asb = smbase + (unsigned)((s % 3) * 128 * LDH * 2) + aoff;
        const unsigned bsb = smbase + (unsigned)((GSTAGE + (s % 3)) * 128 * LDH * 2) + boff;
        #pragma unroll
        for (int kk = 0; kk < 32; kk += 16) {
            unsigned av[4][4], bv[8][2];
            #pragma unroll
            for (int mi = 0; mi < 4; mi++)
                ldsm_x4(av[mi][0], av[mi][1], av[mi][2], av[mi][3],
                        asb + (unsigned)((mi * 16 * LDH + kk) * 2));
            #pragma unroll
            for (int njp = 0; njp < 4; njp++)
                ldsm_x4(bv[2 * njp][0], bv[2 * njp][1],
                        bv[2 * njp + 1][0], bv[2 * njp + 1][1],
                        bsb + (unsigned)((njp * 16 * LDH + kk) * 2));
            #pragma unroll
            for (int mi = 0; mi < 4; mi++)
                #pragma unroll
                for (int nj = 0; nj < 8; nj++)
                    mma_f16(acc[mi][nj], av[mi][0], av[mi][1], av[mi][2], av[mi][3],
                            bv[nj][0], bv[nj][1]);
        }
        if (s + 2 < nk) load_stage((s + 2) % 3, (s + 2) * 32);
    }

    #pragma unroll
    for (int mi = 0; mi < 4; mi++) {
        const int r = row0 + wm * 64 + mi * 16 + qr;
        #pragma unroll
        for (int nj = 0; nj < 8; nj++) {
            const int cidx = col0 + wn * 64 + nj * 8 + 2 * qc;
            float v0 = acc[mi][nj][0], v1 = acc[mi][nj][1];
            float v2 = acc[mi][nj][2], v3 = acc[mi][nj][3];
            if (EPI == 2 || EPI == 3) {
                float b0 = bias[cidx], b1 = bias[cidx + 1];
                v0 += b0; v1 += b1; v2 += b0; v3 += b1;
            }
            const size_t o0 = (size_t)r * N + cidx;
            const size_t o1 = (size_t)(r + 8) * N + cidx;
            if (EPI == 2) {
                *(__half2*)&Ch[o0] = __floats2half2_rn(gelu_f(v0), gelu_f(v1));
                *(__half2*)&Ch[o1] = __floats2half2_rn(gelu_f(v2), gelu_f(v3));
            } else {
                if (EPI == 1 || EPI == 3) {
                    const float2 r0 = *(const float2*)&R[o0];
                    const float2 r1 = *(const float2*)&R[o1];
                    v0 += r0.x; v1 += r0.y; v2 += r1.x; v3 += r1.y;
                }
                *(float2*)&C[o0] = make_float2(v0, v1);
                *(float2*)&C[o1] = make_float2(v2, v3);
            }
        }
    }
}

// ---------------- xPos rotary (table-driven, in-place on packed QKVG) ------
__global__ void xpos_k(float* __restrict__ QKVG, const float* __restrict__ T) {
    int idx = blockIdx.x * blockDim.x + threadIdx.x;  // over B*L*H*64 pairs
    if (idx >= BATCH * SEQ * HEADS * 64) return;
    int p = idx & 63;
    int h = (idx >> 6) & 7;
    int l = (idx >> 9) & (SEQ - 1);
    int b = idx >> (9 + 11);
    size_t base = ((size_t)(b * SEQ + l)) * PSTR + h * HD + 2 * p;
    float4 t = *(const float4*)&T[(l * 64 + p) * 4];
    float* Q = QKVG;
    float* K = QKVG + 1024;
    float q0 = Q[base], q1 = Q[base + 1];
    Q[base]     = q0 * t.x - q1 * t.y;
    Q[base + 1] = q1 * t.x + q0 * t.y;
    float k0 = K[base], k1 = K[base + 1];
    K[base]     = k0 * t.z - k1 * t.w;
    K[base + 1] = k1 * t.z + k0 * t.w;
}

// ---------------- fused retention attention (FP16 tensor-core) -------------
// Reads Q/K/V from packed QKVG (row stride PSTR, col offsets 0/1024/2048).
// 8 warps: wm = warp>>1 (16 q-rows), wn = warp&1.
#define AT_LDQH 136   // halves per Q/K row (k=128 + 8 pad)
#define AT_LDVH 72    // halves per Vt row (m=64 + 8 pad)
#define AT_LDSH 72    // halves per Ss row
#define ATTN_SMEM ((64*AT_LDQH*2 + 128*AT_LDVH + 64*AT_LDSH) * 2)

__global__ void __launch_bounds__(256) attn_k(const float* __restrict__ QKVG,
                                              float* __restrict__ Y) {
    extern __shared__ __half sma[];
    __half* Qs = sma;                        // [64][136]
    __half* Ks = Qs + 64 * AT_LDQH;          // [64][136]
    __half* Vt = Ks + 64 * AT_LDQH;          // [128][72] transposed [v][m]
    __half* Ss = Vt + 128 * AT_LDVH;         // [64][72]
    const int tid  = threadIdx.x;
    const int lane = tid & 31;
    const int warp = tid >> 5;
    const int wm = warp >> 1;                // 0..3
    const int wn = warp & 1;                 // 0..1
    const int q0 = blockIdx.x * 64;
    const int bh = blockIdx.y;
    const int b = bh >> 3, h = bh & 7;
    const float gamma = 1.f - expf(-3.4657359028f + (float)h * -0.3960840962f);
    const float lg = logf(gamma);

    const float* Qg = QKVG;
    const float* Kg = QKVG + 1024;
    const float* Vg = QKVG + 2048;

    // load Q tile -> fp16
    for (int i = tid; i < 64 * 32; i += 256) {
        int r = i >> 5, c = (i & 31) << 2;
        float4 v = *(const float4*)&Qg[((size_t)(b * SEQ + q0 + r)) * PSTR + h * HD + c];
        __half2* d = (__half2*)&Qs[r * AT_LDQH + c];
        d[0] = __floats2half2_rn(v.x, v.y);
        d[1] = __floats2half2_rn(v.z, v.w);
    }

    float acc2[8][4];
    #pragma unroll
    for (int j = 0; j < 8; j++) { acc2[j][0]=acc2[j][1]=acc2[j][2]=acc2[j][3]=0.f; }

    const int qr = (lane >> 2);
    const int qc = (lane & 3);

    const int nmt = (q0 >> 6) + 1;
    for (int mt = 0; mt < nmt; mt++) {
        const int m0 = mt << 6;
        __syncthreads();
        // K tile -> fp16
        for (int i = tid; i < 64 * 32; i += 256) {
            int r = i >> 5, c = (i & 31) << 2;
            float4 v = *(const float4*)&Kg[((size_t)(b * SEQ + m0 + r)) * PSTR + h * HD + c];
            __half2* d = (__half2*)&Ks[r * AT_LDQH + c];
            d[0] = __floats2half2_rn(v.x, v.y);
            d[1] = __floats2half2_rn(v.z, v.w);
        }
        // V tile transposed -> fp16: Vt[v][m]
        {
            const int mo = lane & 7;
            const int v0 = (lane >> 3) << 2;
            const int mrow = warp * 8 + mo;
            const float* vsrc = &Vg[((size_t)(b * SEQ + m0 + mrow)) * PSTR + h * HD];
            #pragma unroll
            for (int vb = 0; vb < 128; vb += 16) {
                float4 vv = *(const float4*)&vsrc[vb + v0];
                Vt[(vb + v0 + 0) * AT_LDVH + mrow] = __float2half_rn(vv.x);
                Vt[(vb + v0 + 1) * AT_LDVH + mrow] = __float2half_rn(vv.y);
                Vt[(vb + v0 + 2) * AT_LDVH + mrow] = __float2half_rn(vv.z);
                Vt[(vb + v0 + 3) * AT_LDVH + mrow] = __float2half_rn(vv.w);
            }
        }
        __syncthreads();

        // ---- S = Q K^T : warp tile 16x32, k=128, mma.k16 ----
        float sacc[4][4];
        #pragma unroll
        for (int nj = 0; nj < 4; nj++) { sacc[nj][0]=sacc[nj][1]=sacc[nj][2]=sacc[nj][3]=0.f; }
        #pragma unroll
        for (int k0 = 0; k0 < 128; k0 += 16) {
            const int r = wm * 16 + qr;
            const __half* qrow = Qs + r * AT_LDQH + k0 + 2 * qc;
            unsigned a0 = *(const unsigned*)(qrow);
            unsigned a1 = *(const unsigned*)(qrow + 8 * AT_LDQH);
            unsigned a2 = *(const unsigned*)(qrow + 8);
            unsigned a3 = *(const unsigned*)(qrow + 8 * AT_LDQH + 8);
            #pragma unroll
            for (int nj = 0; nj < 4; nj++) {
                const int n = wn * 32 + nj * 8 + qr;
                const __half* krow = Ks + n * AT_LDQH + k0 + 2 * qc;
                unsigned b0 = *(const unsigned*)(krow);
                unsigned b1 = *(const unsigned*)(krow + 8);
                mma_f16(sacc[nj], a0, a1, a2, a3, b0, b1);
            }
        }
        // decay + causal mask on fragments -> Ss (fp16)
        {
            const int lr = wm * 16 + qr;
            const int li  = q0 + lr;
            const int li8 = li + 8;
            #pragma unroll
            for (int nj = 0; nj < 4; nj++) {
                const int lc = wn * 32 + nj * 8 + 2 * qc;
                const int mj = m0 + lc;
                float d00 = (li  >= mj    ) ? __expf(lg * (float)(li  - mj    )) : 0.f;
                float d01 = (li  >= mj + 1) ? __expf(lg * (float)(li  - mj - 1)) : 0.f;
                float d10 = (li8 >= mj    ) ? __expf(lg * (float)(li8 - mj    )) : 0.f;
                float d11 = (li8 >= mj + 1) ? __expf(lg * (float)(li8 - mj - 1)) : 0.f;
                *(__half2*)&Ss[lr * AT_LDSH + lc] =
                    __floats2half2_rn(sacc[nj][0] * d00, sacc[nj][1] * d01);
                *(__half2*)&Ss[(lr + 8) * AT_LDSH + lc] =
                    __floats2half2_rn(sacc[nj][2] * d10, sacc[nj][3] * d11);
            }
        }
        __syncthreads();

        // ---- Y += S @ V : warp tile 16x64, k=64, mma.k16 ----
        #pragma unroll
        for (int k0 = 0; k0 < 64; k0 += 16) {
            const int r = wm * 16 + qr;
            const __half* srow = Ss + r * AT_LDSH + k0 + 2 * qc;
            unsigned a0 = *(const unsigned*)(srow);
            unsigned a1 = *(const unsigned*)(srow + 8 * AT_LDSH);
            unsigned a2 = *(const unsigned*)(srow + 8);
            unsigned a3 = *(const unsigned*)(srow + 8 * AT_LDSH + 8);
            #pragma unroll
            for (int nj = 0; nj < 8; nj++) {
                const int n = wn * 64 + nj * 8 + qr;
                const __half* vrow = Vt + n * AT_LDVH + k0 + 2 * qc;
                unsigned b0 = *(const unsigned*)(vrow);
                unsigned b1 = *(const unsigned*)(vrow + 8);
                mma_f16(acc2[nj], a0, a1, a2, a3, b0, b1);
            }
        }
    }

    {
        const int lr = wm * 16 + qr;
        const size_t rowbase = (size_t)((b * 8 + h) * SEQ) + q0 + lr;
        #pragma unroll
        for (int nj = 0; nj < 8; nj++) {
            const int c = wn * 64 + nj * 8 + 2 * qc;
            *(float2*)&Y[rowbase * HV + c]       = make_float2(acc2[nj][0], acc2[nj][1]);
            *(float2*)&Y[(rowbase + 8) * HV + c] = make_float2(acc2[nj][2], acc2[nj][3]);
        }
    }
}

// ---------------- per-head groupnorm + SiLU gate -> fp16 out ---------------
__global__ void __launch_bounds__(256) gn_gate_k(const float* __restrict__ Y,
        const float* __restrict__ QKVG, const float* __restrict__ gnw,
        const float* __restrict__ gnb, __half* __restrict__ out) {
    int gwarp = (blockIdx.x * blockDim.x + threadIdx.x) >> 5;   // row over B*H*L
    int lane = threadIdx.x & 31;
    if (gwarp >= BATCH * HEADS * SEQ) return;
    int b = gwarp / (HEADS * SEQ);
    int h = (gwarp / SEQ) & 7;
    int l = gwarp & (SEQ - 1);
    const float* y = Y + (size_t)gwarp * HV;
    float v0 = y[lane], v1 = y[lane + 32], v2 = y[lane + 64], v3 = y[lane + 96];
    float s  = v0 + v1 + v2 + v3;
    float ss = v0*v0 + v1*v1 + v2*v2 + v3*v3;
    #pragma unroll
    for (int o = 16; o; o >>= 1) {
        s  += __shfl_xor_sync(0xffffffffu, s,  o);
        ss += __shfl_xor_sync(0xffffffffu, ss, o);
    }
    float mean = s * (1.f / HV);
    float var  = ss * (1.f / HV) - mean * mean;
    float rstd = rsqrtf(var + EPSV);
    size_t row = (size_t)(b * SEQ + l);
    const float* Gp = QKVG + row * PSTR + 3072 + h * HV;
    size_t ob = row * VD + h * HV;
    float vv[4] = {v0, v1, v2, v3};
    #pragma unroll
    for (int i = 0; i < 4; i++) {
        int c = lane + i * 32;
        float g = Gp[c];
        float gate = g / (1.f + expf(-g));
        float r = ((vv[i] - mean) * rstd * gnw[h * HV + c] + gnb[h * HV + c]) * gate;
        out[ob + c] = __float2half_rn(r);
    }
}

// ---------------- host launcher --------------------------------------------
extern "C" void kernel_launch(void* const* d_in, const int* in_sizes, int n_in,
                              void* d_out, int out_size) {
    const float* X    = (const float*)d_in[0];
    const float* Wq   = (const float*)d_in[1];
    const float* Wk   = (const float*)d_in[2];
    const float* Wv   = (const float*)d_in[3];
    const float* W_G  = (const float*)d_in[4];
    const float* W_O  = (const float*)d_in[5];
    const float* gnw  = (const float*)d_in[6];
    const float* gnb  = (const float*)d_in[7];
    const float* ln1w = (const float*)d_in[8];
    const float* ln1b = (const float*)d_in[9];
    const float* ln2w = (const float*)d_in[10];
    const float* ln2b = (const float*)d_in[11];
    const float* fw1  = (const float*)d_in[12];
    const float* fb1  = (const float*)d_in[13];
    const float* fw2  = (const float*)d_in[14];
    const float* fb2  = (const float*)d_in[15];
    float* out = (float*)d_out;

    void* p;
    cudaGetSymbolAddress(&p, g_X);     float*  pX     = (float*)p;
    cudaGetSymbolAddress(&p, g_Y);     float*  pY     = (float*)p;
    cudaGetSymbolAddress(&p, g_Att);   float*  pAtt   = (float*)p;
    cudaGetSymbolAddress(&p, g_QKVG);  float*  pQKVG  = (float*)p;
    cudaGetSymbolAddress(&p, g_xt);    float*  pXT    = (float*)p;
    cudaGetSymbolAddress(&p, g_Xn);    __half* pXn    = (__half*)p;
    cudaGetSymbolAddress(&p, g_Yg);    __half* pYg    = (__half*)p;
    cudaGetSymbolAddress(&p, g_Hf);    __half* pHf    = (__half*)p;
    cudaGetSymbolAddress(&p, g_WbigT); __half* pWbigT = (__half*)p;
    cudaGetSymbolAddress(&p, g_WoT);   __half* pWoT   = (__half*)p;
    cudaGetSymbolAddress(&p, g_Wf1T);  __half* pWf1T  = (__half*)p;
    cudaGetSymbolAddress(&p, g_Wf2T);  __half* pWf2T  = (__half*)p;

    cudaFuncSetAttribute(attn_k, cudaFuncAttributeMaxDynamicSharedMemorySize, ATTN_SMEM);
    cudaFuncSetAttribute(tgemm_k<0>, cudaFuncAttributeMaxDynamicSharedMemorySize, SMEM_GEMM);
    cudaFuncSetAttribute(tgemm_k<1>, cudaFuncAttributeMaxDynamicSharedMemorySize, SMEM_GEMM);
    cudaFuncSetAttribute(tgemm_k<2>, cudaFuncAttributeMaxDynamicSharedMemorySize, SMEM_GEMM);
    cudaFuncSetAttribute(tgemm_k<3>, cudaFuncAttributeMaxDynamicSharedMemorySize, SMEM_GEMM);

    copy_k<<<(BL * DIM / 4 + 255) / 256, 256>>>(X, pX, BL * DIM / 4);
    xpos_table_k<<<(SEQ * 64 + 255) / 256, 256>>>(pXT);

    dim3 tb(32, 8);
    dim3 gProj(PSTR / 128, BL / 128);   // 32 x 32
    dim3 gDim (DIM  / 128, BL / 128);   // 8 x 32
    dim3 gFfn (FFN  / 128, BL / 128);   // 32 x 32

    for (int i = 0; i < NLAYERS; i++) {
        size_t wofs = (size_t)i * HEADS * DIM * HD;
        pack_qkv_t_k<<<dim3(4, 32, 24), tb>>>(Wq + wofs, Wk + wofs, Wv + wofs, pWbigT);
        transpose_h_k<<<dim3(32, 32), tb>>>(W_G + (size_t)i * DIM * VD,
                                            pWbigT + (size_t)3072 * DIM, VD, DIM);
        transpose_h_k<<<dim3(32, 32), tb>>>(W_O + (size_t)i * VD * DIM, pWoT, DIM, VD);
        transpose_h_k<<<dim3(128, 32), tb>>>(fw1 + (size_t)i * DIM * FFN, pWf1T, FFN, DIM);
        transpose_h_k<<<dim3(32, 128), tb>>>(fw2 + (size_t)i * FFN * DIM, pWf2T, DIM, FFN);

        layernorm_k<<<BL, 256>>>(pX, pXn, ln1w + i * DIM, ln1b + i * DIM);

        tgemm_k<0><<<gProj, 128, SMEM_GEMM>>>(pXn, pWbigT, pQKVG, nullptr,
                                              nullptr, nullptr, BL, PSTR, DIM);

        xpos_k<<<(BATCH * SEQ * HEADS * 64 + 255) / 256, 256>>>(pQKVG, pXT);

        attn_k<<<dim3(SEQ / 64, BATCH * HEADS), 256, ATTN_SMEM>>>(pQKVG, pY);

        gn_gate_k<<<(BATCH * HEADS * SEQ) / 8, 256>>>(pY, pQKVG, gnw + i * VD,
                                                      gnb + i * VD, pYg);

        tgemm_k<1><<<gDim, 128, SMEM_GEMM>>>(pYg, pWoT, pAtt, nullptr,
                                             nullptr, pX, BL, DIM, DIM);

        layernorm_k<<<BL, 256>>>(pAtt, pXn, ln2w + i * DIM, ln2b + i * DIM);

        tgemm_k<2><<<gFfn, 128, SMEM_GEMM>>>(pXn, pWf1T, nullptr, pHf,
                                             fb1 + i * FFN, nullptr, BL, FFN, DIM);

        float* dst = (i == NLAYERS - 1) ? out : pX;
        tgemm_k<3><<<gDim, 128, SMEM_GEMM>>>(pHf, pWf2T, dst, nullptr,
                                             fb2 + i * DIM, pAtt, BL, DIM, FFN);
    }
}

// round 16
// speedup vs baseline: 7.3103x; 1.0356x over previous
#include <cuda_runtime.h>
#include <cuda_fp16.h>
#include <math.h>

#define BATCH 2
#define SEQ   2048
#define DIM   1024
#define FFN   4096
#define HEADS 8
#define HD    128
#define HV    128
#define VD    1024
#define NLAYERS 2
#define BL    (BATCH*SEQ)          // 4096
#define EPSV  1e-5f
#define QKVSTR 3072                // packed fp16 Q|K|V row stride

// ---------------- scratch (static device globals; no allocations) ----------
__device__ float  g_X   [BL*DIM];
__device__ float  g_Att [BL*DIM];
__device__ float  g_Gf  [(size_t)BL*DIM];      // gate pre-activations (fp32)
__device__ float  g_xt  [SEQ*64*4];            // xpos table: (l,p) -> qc,qs,kc,ks
__device__ __half g_QKVh[(size_t)BL*QKVSTR];   // rotated Q | K | V (fp16)
__device__ __half g_Xn  [BL*DIM];
__device__ __half g_Yg  [BL*DIM];
__device__ __half g_Hf  [(size_t)BL*FFN];
__device__ __half g_WbigT[(size_t)4*DIM*DIM];  // [n=4096][k=1024]
__device__ __half g_WoT [DIM*DIM];             // [n=1024][k=1024]
__device__ __half g_Wf1T[(size_t)FFN*DIM];     // [n=4096][k=1024]
__device__ __half g_Wf2T[(size_t)DIM*FFN];     // [n=1024][k=4096]

// ---------------- small helpers -------------------------------------------
__device__ __forceinline__ float gelu_f(float x) {
    return 0.5f * x * (1.0f + erff(x * 0.70710678118654752f));
}

__device__ __forceinline__ void mma_f16(float* c, unsigned a0, unsigned a1,
                                        unsigned a2, unsigned a3,
                                        unsigned b0, unsigned b1) {
    asm volatile(
        "mma.sync.aligned.m16n8k16.row.col.f32.f16.f16.f32 "
        "{%0,%1,%2,%3}, {%4,%5,%6,%7}, {%8,%9}, {%0,%1,%2,%3};"
        : "+f"(c[0]), "+f"(c[1]), "+f"(c[2]), "+f"(c[3])
        : "r"(a0), "r"(a1), "r"(a2), "r"(a3), "r"(b0), "r"(b1));
}

__device__ __forceinline__ void ldsm_x4(unsigned& r0, unsigned& r1,
                                        unsigned& r2, unsigned& r3, unsigned addr) {
    asm volatile("ldmatrix.sync.aligned.m8n8.x4.shared.b16 {%0,%1,%2,%3}, [%4];"
        : "=r"(r0), "=r"(r1), "=r"(r2), "=r"(r3) : "r"(addr));
}

__device__ __forceinline__ void cpa16(void* smem, const void* g) {
    unsigned s = (unsigned)__cvta_generic_to_shared(smem);
    asm volatile("cp.async.cg.shared.global [%0], [%1], 16;" :: "r"(s), "l"(g));
}
__device__ __forceinline__ void cp_commit() {
    asm volatile("cp.async.commit_group;");
}
template<int N> __device__ __forceinline__ void cp_wait() {
    asm volatile("cp.async.wait_group %0;" :: "n"(N));
}

// ---------------- xPos table: (l,p) -> {cos*sc, sin*sc, cos/sc, sin/sc} ----
__global__ void xpos_table_k(float* __restrict__ T) {
    int idx = blockIdx.x * blockDim.x + threadIdx.x;   // over SEQ*64
    if (idx >= SEQ * 64) return;
    int l = idx >> 6, p = idx & 63;
    float pos = (float)l;
    float bs  = (2.f * p + 0.4f * HD) / (1.4f * HD);
    float sc  = powf(bs, pos * (1.f / 512.f));
    float invf = expf(-(float)p * (logf(10000.f) / 64.f));
    float sn, cs;
    sincosf(pos * invf, &sn, &cs);
    float4 t = make_float4(cs * sc, sn * sc, cs / sc, sn / sc);
    *(float4*)&T[idx * 4] = t;
}

// ---------------- tiled transpose fp32 -> fp16 -----------------------------
__global__ void transpose_h_k(const float* __restrict__ src, __half* __restrict__ dst,
                              int sstride, int dstride) {
    __shared__ float t[32][33];
    int c0 = blockIdx.x * 32, r0 = blockIdx.y * 32;
    int tx = threadIdx.x, ty = threadIdx.y;
    #pragma unroll
    for (int i = 0; i < 32; i += 8)
        t[ty + i][tx] = src[(size_t)(r0 + ty + i) * sstride + c0 + tx];
    __syncthreads();
    #pragma unroll
    for (int i = 0; i < 32; i += 8)
        dst[(size_t)(c0 + ty + i) * dstride + r0 + tx] = __float2half_rn(t[tx][ty + i]);
}

// batched Wq/Wk/Wv head transpose -> WbigT rows [m*1024 + h*128 + e][d]
__global__ void pack_qkv_t_k(const float* __restrict__ Wq, const float* __restrict__ Wk,
                             const float* __restrict__ Wv, __half* __restrict__ dstBase) {
    __shared__ float t[32][33];
    int z = blockIdx.z;
    int m = z >> 3, h = z & 7;
    const float* src = (m == 0 ? Wq : (m == 1 ? Wk : Wv)) + (size_t)h * DIM * HD;
    __half* dst = dstBase + (size_t)(m * 1024 + h * 128) * DIM;
    int c0 = blockIdx.x * 32, r0 = blockIdx.y * 32;   // c over e(128), r over d(1024)
    int tx = threadIdx.x, ty = threadIdx.y;
    #pragma unroll
    for (int i = 0; i < 32; i += 8)
        t[ty + i][tx] = src[(size_t)(r0 + ty + i) * HD + c0 + tx];
    __syncthreads();
    #pragma unroll
    for (int i = 0; i < 32; i += 8)
        dst[(size_t)(c0 + ty + i) * DIM + r0 + tx] = __float2half_rn(t[tx][ty + i]);
}

// ---------------- layernorm over 1024 -> fp16 out --------------------------
__global__ void __launch_bounds__(256) layernorm_k(const float* __restrict__ in,
        __half* __restrict__ out, const float* __restrict__ w, const float* __restrict__ bb) {
    int row = blockIdx.x, tid = threadIdx.x;
    const float4 xv = *(const float4*)(in + (size_t)row * DIM + tid * 4);
    float s  = xv.x + xv.y + xv.z + xv.w;
    float ss = xv.x*xv.x + xv.y*xv.y + xv.z*xv.z + xv.w*xv.w;
    #pragma unroll
    for (int o = 16; o; o >>= 1) {
        s  += __shfl_xor_sync(0xffffffffu, s,  o);
        ss += __shfl_xor_sync(0xffffffffu, ss, o);
    }
    __shared__ float sw[8], ssw[8], stat[2];
    int wid = tid >> 5, lane = tid & 31;
    if (!lane) { sw[wid] = s; ssw[wid] = ss; }
    __syncthreads();
    if (tid == 0) {
        float S = 0.f, SS = 0.f;
        #pragma unroll
        for (int i = 0; i < 8; i++) { S += sw[i]; SS += ssw[i]; }
        float mean = S * (1.f / DIM);
        float var  = SS * (1.f / DIM) - mean * mean;
        stat[0] = mean;
        stat[1] = rsqrtf(var + EPSV);
    }
    __syncthreads();
    float mean = stat[0], rstd = stat[1];
    const float4 wv = *(const float4*)(w  + tid * 4);
    const float4 bv = *(const float4*)(bb + tid * 4);
    __half2 h01 = __floats2half2_rn((xv.x - mean) * rstd * wv.x + bv.x,
                                    (xv.y - mean) * rstd * wv.y + bv.y);
    __half2 h23 = __floats2half2_rn((xv.z - mean) * rstd * wv.z + bv.z,
                                    (xv.w - mean) * rstd * wv.w + bv.w);
    __half2* o = (__half2*)(out + (size_t)row * DIM + tid * 4);
    o[0] = h01;
    o[1] = h23;
}

// ---------------- FP16 tensor-core GEMM, cp.async 3-stage + ldmatrix -------
// C[M,N] = A[M,K] @ Bt[N,K]^T ; 4 warps, warp tile 64x64, CTA 128x128, k-step 32.
// EPI: 1 +R | 2 +bias,gelu -> half Ch | 3 +bias,+R | 4 proj: xpos-rotate Q/K,
//      write QKV fp16 to Oh (stride 3072), G fp32 to Gf.
#define LDH 40
#define GSTAGE 3
#define SMEM_GEMM (GSTAGE * 2 * 128 * LDH * 2)

template<int EPI>
__global__ void __launch_bounds__(128) tgemm_k(const __half* __restrict__ A,
        const __half* __restrict__ Bt, float* __restrict__ C, __half* __restrict__ Ch,
        const float* __restrict__ bias, const float* __restrict__ R,
        float* __restrict__ Gf, const float* __restrict__ Tbl,
        int M, int N, int K) {
    extern __shared__ __half smh[];

    const int tid  = threadIdx.x;
    const int lane = tid & 31;
    const int warp = tid >> 5;
    const int wm = warp >> 1, wn = warp & 1;
    const int row0 = blockIdx.y * 128, col0 = blockIdx.x * 128;
    const int qr = lane >> 2, qc = lane & 3;

    const unsigned smbase = (unsigned)__cvta_generic_to_shared(smh);
    const int l8  = lane & 7;
    const int t01 = (lane >> 3) & 1;
    const int t23 = (lane >> 4) & 1;
    const unsigned aoff = ((wm * 64 + t01 * 8 + l8) * LDH + t23 * 8) * 2;
    const unsigned boff = ((wn * 64 + t23 * 8 + l8) * LDH + t01 * 8) * 2;

    float acc[4][8][4];
    #pragma unroll
    for (int i = 0; i < 4; i++)
        #pragma unroll
        for (int j = 0; j < 8; j++)
            #pragma unroll
            for (int q = 0; q < 4; q++) acc[i][j][q] = 0.f;

    __half* AsBase = smh;
    __half* BsBase = smh + GSTAGE * 128 * LDH;

    auto load_stage = [&](int st, int k0) {
        __half* as = AsBase + st * 128 * LDH;
        const __half* ag = &A[(size_t)(row0 + tid) * K + k0];
        #pragma unroll
        for (int c = 0; c < 4; c++)
            cpa16(&as[tid * LDH + c * 8], ag + c * 8);
        __half* bs = BsBase + st * 128 * LDH;
        const __half* bg = &Bt[(size_t)(col0 + tid) * K + k0];
        #pragma unroll
        for (int c = 0; c < 4; c++)
            cpa16(&bs[tid * LDH + c * 8], bg + c * 8);
        cp_commit();
    };

    load_stage(0, 0);
    load_stage(1, 32);

    const int nk = K >> 5;
    for (int s = 0; s < nk; s++) {
        if (s + 1 < nk) cp_wait<1>(); else cp_wait<0>();
        __syncthreads();
        const unsigned asb = smbase + (unsigned)((s % 3) * 128 * LDH * 2) + aoff;
        const unsigned bsb = smbase + (unsigned)((GSTAGE + (s % 3)) * 128 * LDH * 2) + boff;
        #pragma unroll
        for (int kk = 0; kk < 32; kk += 16) {
            unsigned av[4][4], bv[8][2];
            #pragma unroll
            for (int mi = 0; mi < 4; mi++)
                ldsm_x4(av[mi][0], av[mi][1], av[mi][2], av[mi][3],
                        asb + (unsigned)((mi * 16 * LDH + kk) * 2));
            #pragma unroll
            for (int njp = 0; njp < 4; njp++)
                ldsm_x4(bv[2 * njp][0], bv[2 * njp][1],
                        bv[2 * njp + 1][0], bv[2 * njp + 1][1],
                        bsb + (unsigned)((njp * 16 * LDH + kk) * 2));
            #pragma unroll
            for (int mi = 0; mi < 4; mi++)
                #pragma unroll
                for (int nj = 0; nj < 8; nj++)
                    mma_f16(acc[mi][nj], av[mi][0], av[mi][1], av[mi][2], av[mi][3],
                            bv[nj][0], bv[nj][1]);
        }
        if (s + 2 < nk) load_stage((s + 2) % 3, (s + 2) * 32);
    }

    if (EPI == 4) {
        // projection epilogue: region 0=Q,1=K (rotate, fp16), 2=V (fp16), 3=G (fp32)
        const int region = col0 >> 10;
        #pragma unroll
        for (int mi = 0; mi < 4; mi++) {
            const int r = row0 + wm * 64 + mi * 16 + qr;
            const int l = r & (SEQ - 1);
            #pragma unroll
            for (int nj = 0; nj < 8; nj++) {
                const int cidx = col0 + wn * 64 + nj * 8 + 2 * qc;
                float v0 = acc[mi][nj][0], v1 = acc[mi][nj][1];
                float v2 = acc[mi][nj][2], v3 = acc[mi][nj][3];
                if (region <= 1) {
                    const int p = (cidx & 127) >> 1;
                    const float4 t  = *(const float4*)&Tbl[((size_t)l * 64 + p) * 4];
                    const float4 t8 = *(const float4*)&Tbl[((size_t)(l + 8) * 64 + p) * 4];
                    const float tc  = (region == 0) ? t.x  : t.z;
                    const float ts  = (region == 0) ? t.y  : t.w;
                    const float tc8 = (region == 0) ? t8.x : t8.z;
                    const float ts8 = (region == 0) ? t8.y : t8.w;
                    *(__half2*)&Ch[(size_t)r * QKVSTR + cidx] =
                        __floats2half2_rn(v0 * tc - v1 * ts, v1 * tc + v0 * ts);
                    *(__half2*)&Ch[(size_t)(r + 8) * QKVSTR + cidx] =
                        __floats2half2_rn(v2 * tc8 - v3 * ts8, v3 * tc8 + v2 * ts8);
                } else if (region == 2) {
                    *(__half2*)&Ch[(size_t)r * QKVSTR + cidx] = __floats2half2_rn(v0, v1);
                    *(__half2*)&Ch[(size_t)(r + 8) * QKVSTR + cidx] = __floats2half2_rn(v2, v3);
                } else {
                    const int j = cidx - 3072;
                    *(float2*)&Gf[(size_t)r * DIM + j]       = make_float2(v0, v1);
                    *(float2*)&Gf[(size_t)(r + 8) * DIM + j] = make_float2(v2, v3);
                }
            }
        }
        return;
    }

    #pragma unroll
    for (int mi = 0; mi < 4; mi++) {
        const int r = row0 + wm * 64 + mi * 16 + qr;
        #pragma unroll
        for (int nj = 0; nj < 8; nj++) {
            const int cidx = col0 + wn * 64 + nj * 8 + 2 * qc;
            float v0 = acc[mi][nj][0], v1 = acc[mi][nj][1];
            float v2 = acc[mi][nj][2], v3 = acc[mi][nj][3];
            if (EPI == 2 || EPI == 3) {
                float b0 = bias[cidx], b1 = bias[cidx + 1];
                v0 += b0; v1 += b1; v2 += b0; v3 += b1;
            }
            const size_t o0 = (size_t)r * N + cidx;
            const size_t o1 = (size_t)(r + 8) * N + cidx;
            if (EPI == 2) {
                *(__half2*)&Ch[o0] = __floats2half2_rn(gelu_f(v0), gelu_f(v1));
                *(__half2*)&Ch[o1] = __floats2half2_rn(gelu_f(v2), gelu_f(v3));
            } else {
                if (EPI == 1 || EPI == 3) {
                    const float2 r0 = *(const float2*)&R[o0];
                    const float2 r1 = *(const float2*)&R[o1];
                    v0 += r0.x; v1 += r0.y; v2 += r1.x; v3 += r1.y;
                }
                *(float2*)&C[o0] = make_float2(v0, v1);
                *(float2*)&C[o1] = make_float2(v2, v3);
            }
        }
    }
}

// ---------------- fused retention attention + GroupNorm + gate -------------
// Reads fp16 Q/K/V from QKVh (stride 3072), G fp32 from Gf.
// Writes gated/normed fp16 Yg [b*SEQ+l][h*128+c].
#define AT_LDQH 136
#define AT_LDVH 72
#define AT_LDSH 72
#define ATTN_SMEM ((64*AT_LDQH*2 + 128*AT_LDVH + 64*AT_LDSH) * 2)

__global__ void __launch_bounds__(256) attn_k(const __half* __restrict__ QKVh,
        const float* __restrict__ Gf, const float* __restrict__ gnw,
        const float* __restrict__ gnb, __half* __restrict__ Yg) {
    extern __shared__ __half sma[];
    __half* Qs = sma;                        // [64][136]
    __half* Ks = Qs + 64 * AT_LDQH;          // [64][136]
    __half* Vt = Ks + 64 * AT_LDQH;          // [128][72] transposed [v][m]
    __half* Ss = Vt + 128 * AT_LDVH;         // [64][72]
    const int tid  = threadIdx.x;
    const int lane = tid & 31;
    const int warp = tid >> 5;
    const int wm = warp >> 1;
    const int wn = warp & 1;
    const int q0 = blockIdx.x * 64;
    const int bh = blockIdx.y;
    const int b = bh >> 3, h = bh & 7;
    const float gamma = 1.f - expf(-3.4657359028f + (float)h * -0.3960840962f);
    const float lg = logf(gamma);

    const __half* Qg = QKVh + h * HD;
    const __half* Kg = QKVh + 1024 + h * HD;
    const __half* Vg = QKVh + 2048 + h * HD;

    // load Q tile (fp16, 16B chunks)
    for (int i = tid; i < 64 * 16; i += 256) {
        int r = i >> 4, c = (i & 15) << 3;
        *(uint4*)&Qs[r * AT_LDQH + c] =
            *(const uint4*)&Qg[((size_t)(b * SEQ + q0 + r)) * QKVSTR + c];
    }

    float acc2[8][4];
    #pragma unroll
    for (int j = 0; j < 8; j++) { acc2[j][0]=acc2[j][1]=acc2[j][2]=acc2[j][3]=0.f; }

    const int qr = (lane >> 2);
    const int qc = (lane & 3);

    const int nmt = (q0 >> 6) + 1;
    for (int mt = 0; mt < nmt; mt++) {
        const int m0 = mt << 6;
        __syncthreads();
        for (int i = tid; i < 64 * 16; i += 256) {
            int r = i >> 4, c = (i & 15) << 3;
            *(uint4*)&Ks[r * AT_LDQH + c] =
                *(const uint4*)&Kg[((size_t)(b * SEQ + m0 + r)) * QKVSTR + c];
        }
        // V tile transposed: Vt[v][m]
        {
            const int mo = lane & 7;
            const int v0 = (lane >> 3) << 2;
            const int mrow = warp * 8 + mo;
            const __half* vsrc = &Vg[((size_t)(b * SEQ + m0 + mrow)) * QKVSTR];
            #pragma unroll
            for (int vb = 0; vb < 128; vb += 16) {
                __half hv[4];
                *(uint2*)hv = *(const uint2*)&vsrc[vb + v0];
                Vt[(vb + v0 + 0) * AT_LDVH + mrow] = hv[0];
                Vt[(vb + v0 + 1) * AT_LDVH + mrow] = hv[1];
                Vt[(vb + v0 + 2) * AT_LDVH + mrow] = hv[2];
                Vt[(vb + v0 + 3) * AT_LDVH + mrow] = hv[3];
            }
        }
        __syncthreads();

        // ---- S = Q K^T ----
        float sacc[4][4];
        #pragma unroll
        for (int nj = 0; nj < 4; nj++) { sacc[nj][0]=sacc[nj][1]=sacc[nj][2]=sacc[nj][3]=0.f; }
        #pragma unroll
        for (int k0 = 0; k0 < 128; k0 += 16) {
            const int r = wm * 16 + qr;
            const __half* qrow = Qs + r * AT_LDQH + k0 + 2 * qc;
            unsigned a0 = *(const unsigned*)(qrow);
            unsigned a1 = *(const unsigned*)(qrow + 8 * AT_LDQH);
            unsigned a2 = *(const unsigned*)(qrow + 8);
            unsigned a3 = *(const unsigned*)(qrow + 8 * AT_LDQH + 8);
            #pragma unroll
            for (int nj = 0; nj < 4; nj++) {
                const int n = wn * 32 + nj * 8 + qr;
                const __half* krow = Ks + n * AT_LDQH + k0 + 2 * qc;
                unsigned b0 = *(const unsigned*)(krow);
                unsigned b1 = *(const unsigned*)(krow + 8);
                mma_f16(sacc[nj], a0, a1, a2, a3, b0, b1);
            }
        }
        // decay + causal mask -> Ss (fp16)
        {
            const int lr = wm * 16 + qr;
            const int li  = q0 + lr;
            const int li8 = li + 8;
            #pragma unroll
            for (int nj = 0; nj < 4; nj++) {
                const int lc = wn * 32 + nj * 8 + 2 * qc;
                const int mj = m0 + lc;
                float d00 = (li  >= mj    ) ? __expf(lg * (float)(li  - mj    )) : 0.f;
                float d01 = (li  >= mj + 1) ? __expf(lg * (float)(li  - mj - 1)) : 0.f;
                float d10 = (li8 >= mj    ) ? __expf(lg * (float)(li8 - mj    )) : 0.f;
                float d11 = (li8 >= mj + 1) ? __expf(lg * (float)(li8 - mj - 1)) : 0.f;
                *(__half2*)&Ss[lr * AT_LDSH + lc] =
                    __floats2half2_rn(sacc[nj][0] * d00, sacc[nj][1] * d01);
                *(__half2*)&Ss[(lr + 8) * AT_LDSH + lc] =
                    __floats2half2_rn(sacc[nj][2] * d10, sacc[nj][3] * d11);
            }
        }
        __syncthreads();

        // ---- Y += S @ V ----
        #pragma unroll
        for (int k0 = 0; k0 < 64; k0 += 16) {
            const int r = wm * 16 + qr;
            const __half* srow = Ss + r * AT_LDSH + k0 + 2 * qc;
            unsigned a0 = *(const unsigned*)(srow);
            unsigned a1 = *(const unsigned*)(srow + 8 * AT_LDSH);
            unsigned a2 = *(const unsigned*)(srow + 8);
            unsigned a3 = *(const unsigned*)(srow + 8 * AT_LDSH + 8);
            #pragma unroll
            for (int nj = 0; nj < 8; nj++) {
                const int n = wn * 64 + nj * 8 + qr;
                const __half* vrow = Vt + n * AT_LDVH + k0 + 2 * qc;
                unsigned b0 = *(const unsigned*)(vrow);
                unsigned b1 = *(const unsigned*)(vrow + 8);
                mma_f16(acc2[nj], a0, a1, a2, a3, b0, b1);
            }
        }
    }

    // ---- fused GroupNorm + SiLU gate epilogue ----
    // Stage Y rows in smem (aliases Qs/Ks region: 64*132*4 = 33792 B < 34816 B,
    // does not touch live Vt/Ss). All S-phase reads of Qs/Ks completed before
    // the last SV barrier; Ys writes don't overlap Ss/Vt addresses.
    float* Ys = (float*)sma;      // [64][132]
    {
        const int lr = wm * 16 + qr;
        #pragma unroll
        for (int nj = 0; nj < 8; nj++) {
            const int col = wn * 64 + nj * 8 + 2 * qc;
            Ys[lr * 132 + col]           = acc2[nj][0];
            Ys[lr * 132 + col + 1]       = acc2[nj][1];
            Ys[(lr + 8) * 132 + col]     = acc2[nj][2];
            Ys[(lr + 8) * 132 + col + 1] = acc2[nj][3];
        }
    }
    __syncthreads();
    // one warp per 8 rows
    for (int rr = 0; rr < 8; rr++) {
        const int lrow = warp * 8 + rr;
        float v0 = Ys[lrow * 132 + lane];
        float v1 = Ys[lrow * 132 + lane + 32];
        float v2 = Ys[lrow * 132 + lane + 64];
        float v3 = Ys[lrow * 132 + lane + 96];
        float s  = v0 + v1 + v2 + v3;
        float ss = v0*v0 + v1*v1 + v2*v2 + v3*v3;
        #pragma unroll
        for (int o = 16; o; o >>= 1) {
            s  += __shfl_xor_sync(0xffffffffu, s,  o);
            ss += __shfl_xor_sync(0xffffffffu, ss, o);
        }
        float mean = s * (1.f / HV);
        float var  = ss * (1.f / HV) - mean * mean;
        float rstd = rsqrtf(var + EPSV);
        const size_t grow = (size_t)(b * SEQ + q0 + lrow);
        const float* Gp = Gf + grow * DIM + h * HV;
        float vv[4] = {v0, v1, v2, v3};
        #pragma unroll
        for (int i = 0; i < 4; i++) {
            const int c = lane + i * 32;
            float g = Gp[c];
            float gate = g / (1.f + expf(-g));
            float r = ((vv[i] - mean) * rstd * gnw[h * HV + c] + gnb[h * HV + c]) * gate;
            Yg[grow * VD + h * HV + c] = __float2half_rn(r);
        }
    }
}

// ---------------- host launcher --------------------------------------------
extern "C" void kernel_launch(void* const* d_in, const int* in_sizes, int n_in,
                              void* d_out, int out_size) {
    const float* X    = (const float*)d_in[0];
    const float* Wq   = (const float*)d_in[1];
    const float* Wk   = (const float*)d_in[2];
    const float* Wv   = (const float*)d_in[3];
    const float* W_G  = (const float*)d_in[4];
    const float* W_O  = (const float*)d_in[5];
    const float* gnw  = (const float*)d_in[6];
    const float* gnb  = (const float*)d_in[7];
    const float* ln1w = (const float*)d_in[8];
    const float* ln1b = (const float*)d_in[9];
    const float* ln2w = (const float*)d_in[10];
    const float* ln2b = (const float*)d_in[11];
    const float* fw1  = (const float*)d_in[12];
    const float* fb1  = (const float*)d_in[13];
    const float* fw2  = (const float*)d_in[14];
    const float* fb2  = (const float*)d_in[15];
    float* out = (float*)d_out;

    void* p;
    cudaGetSymbolAddress(&p, g_X);     float*  pX     = (float*)p;
    cudaGetSymbolAddress(&p, g_Att);   float*  pAtt   = (float*)p;
    cudaGetSymbolAddress(&p, g_Gf);    float*  pGf    = (float*)p;
    cudaGetSymbolAddress(&p, g_xt);    float*  pXT    = (float*)p;
    cudaGetSymbolAddress(&p, g_QKVh);  __half* pQKVh  = (__half*)p;
    cudaGetSymbolAddress(&p, g_Xn);    __half* pXn    = (__half*)p;
    cudaGetSymbolAddress(&p, g_Yg);    __half* pYg    = (__half*)p;
    cudaGetSymbolAddress(&p, g_Hf);    __half* pHf    = (__half*)p;
    cudaGetSymbolAddress(&p, g_WbigT); __half* pWbigT = (__half*)p;
    cudaGetSymbolAddress(&p, g_WoT);   __half* pWoT   = (__half*)p;
    cudaGetSymbolAddress(&p, g_Wf1T);  __half* pWf1T  = (__half*)p;
    cudaGetSymbolAddress(&p, g_Wf2T);  __half* pWf2T  = (__half*)p;

    cudaFuncSetAttribute(attn_k, cudaFuncAttributeMaxDynamicSharedMemorySize, ATTN_SMEM);
    cudaFuncSetAttribute(tgemm_k<1>, cudaFuncAttributeMaxDynamicSharedMemorySize, SMEM_GEMM);
    cudaFuncSetAttribute(tgemm_k<2>, cudaFuncAttributeMaxDynamicSharedMemorySize, SMEM_GEMM);
    cudaFuncSetAttribute(tgemm_k<3>, cudaFuncAttributeMaxDynamicSharedMemorySize, SMEM_GEMM);
    cudaFuncSetAttribute(tgemm_k<4>, cudaFuncAttributeMaxDynamicSharedMemorySize, SMEM_GEMM);

    xpos_table_k<<<(SEQ * 64 + 255) / 256, 256>>>(pXT);

    dim3 tb(32, 8);
    dim3 gProj(4 * DIM / 128, BL / 128);   // 32 x 32
    dim3 gDim (DIM  / 128, BL / 128);      // 8 x 32
    dim3 gFfn (FFN  / 128, BL / 128);      // 32 x 32

    for (int i = 0; i < NLAYERS; i++) {
        size_t wofs = (size_t)i * HEADS * DIM * HD;
        pack_qkv_t_k<<<dim3(4, 32, 24), tb>>>(Wq + wofs, Wk + wofs, Wv + wofs, pWbigT);
        transpose_h_k<<<dim3(32, 32), tb>>>(W_G + (size_t)i * DIM * VD,
                                            pWbigT + (size_t)3072 * DIM, VD, DIM);
        transpose_h_k<<<dim3(32, 32), tb>>>(W_O + (size_t)i * VD * DIM, pWoT, DIM, VD);
        transpose_h_k<<<dim3(128, 32), tb>>>(fw1 + (size_t)i * DIM * FFN, pWf1T, FFN, DIM);
        transpose_h_k<<<dim3(32, 128), tb>>>(fw2 + (size_t)i * FFN * DIM, pWf2T, DIM, FFN);

        const float* Xin = (i == 0) ? X : pX;

        layernorm_k<<<BL, 256>>>(Xin, pXn, ln1w + i * DIM, ln1b + i * DIM);

        // projections + fused xpos + fp16 pack (Q|K|V) + G fp32
        tgemm_k<4><<<gProj, 128, SMEM_GEMM>>>(pXn, pWbigT, nullptr, pQKVh,
                                              nullptr, nullptr, pGf, pXT,
                                              BL, 4 * DIM, DIM);

        // retention + fused GroupNorm + SiLU gate
        attn_k<<<dim3(SEQ / 64, BATCH * HEADS), 256, ATTN_SMEM>>>(
            pQKVh, pGf, gnw + i * VD, gnb + i * VD, pYg);

        tgemm_k<1><<<gDim, 128, SMEM_GEMM>>>(pYg, pWoT, pAtt, nullptr,
                                             nullptr, Xin, nullptr, nullptr,
                                             BL, DIM, DIM);

        layernorm_k<<<BL, 256>>>(pAtt, pXn, ln2w + i * DIM, ln2b + i * DIM);

        tgemm_k<2><<<gFfn, 128, SMEM_GEMM>>>(pXn, pWf1T, nullptr, pHf,
                                             fb1 + i * FFN, nullptr, nullptr, nullptr,
                                             BL, FFN, DIM);

        float* dst = (i == NLAYERS - 1) ? out : pX;
        tgemm_k<3><<<gDim, 128, SMEM_GEMM>>>(pHf, pWf2T, dst, nullptr,
                                             fb2 + i * DIM, pAtt, nullptr, nullptr,
                                             BL, DIM, FFN);
    }
}